// round 8
// baseline (speedup 1.0000x reference)
#include <cuda_runtime.h>
#include <cuda_bf16.h>
#include <math.h>
#include <stdint.h>

#define NB    8
#define LQ    1000
#define DM    256
#define NH    8
#define DH    32
#define NLV   4
#define NPT   4
#define LEN_IN 21760
#define DFFN  1024
#define NQ    (NB*LQ)    /* 8000 */
#define NSRC  (NB*LEN_IN) /* 174080 */

// ---------------- fp32 scratch ---------------------------------------------
__device__ float g_proj[NQ*DM];
__device__ float g_tgt2[NQ*DM];
__device__ float g_tgt3[NQ*DM];
__device__ float g_offaw[NQ*384];
__device__ float g_value[(size_t)NSRC*DM];
__device__ float g_cbias[384];

// ---------------- bf16 hi/lo split scratch ---------------------------------
__device__ __nv_bfloat16 g_qk_h[NQ*DM],   g_qk_l[NQ*DM];
__device__ __nv_bfloat16 g_tgt_h[NQ*DM],  g_tgt_l[NQ*DM];
__device__ __nv_bfloat16 g_qk2_h[NQ*512], g_qk2_l[NQ*512];
__device__ __nv_bfloat16 g_v2_h[NQ*DM],   g_v2_l[NQ*DM];
__device__ __nv_bfloat16 g_att_h[NQ*DM],  g_att_l[NQ*DM];
__device__ __nv_bfloat16 g_query_h[NQ*DM],g_query_l[NQ*DM];
__device__ __nv_bfloat16 g_tgt3_h[NQ*DM], g_tgt3_l[NQ*DM];
__device__ __nv_bfloat16 g_ca_h[NQ*DM],   g_ca_l[NQ*DM];
__device__ __nv_bfloat16 g_ffn_h[NQ*DFFN],g_ffn_l[NQ*DFFN];
__device__ __nv_bfloat16 g_src_h[(size_t)NSRC*DM], g_src_l[(size_t)NSRC*DM];

#define WTOT 1015808
#define OFF_SAIN  0
#define OFF_SAOUT 196608
#define OFF_OFFW  262144
#define OFF_VALW  360448
#define OFF_OUTPW 425984
#define OFF_FFN1  491520
#define OFF_FFN2  753664
__device__ __nv_bfloat16 g_wh[WTOT], g_wl[WTOT];

// =================== helpers ===============================================
__device__ __forceinline__ uint32_t smem_u32(const void* p) {
    uint32_t a;
    asm("{ .reg .u64 t; cvta.to.shared.u64 t, %1; cvt.u32.u64 %0, t; }" : "=r"(a) : "l"(p));
    return a;
}
__device__ __forceinline__ void ldmx4(uint32_t addr, uint32_t* r) {
    asm volatile("ldmatrix.sync.aligned.m8n8.x4.shared.b16 {%0,%1,%2,%3}, [%4];"
                 : "=r"(r[0]), "=r"(r[1]), "=r"(r[2]), "=r"(r[3]) : "r"(addr));
}
__device__ __forceinline__ void ldmx4t(uint32_t addr, uint32_t* r) {
    asm volatile("ldmatrix.sync.aligned.m8n8.x4.trans.shared.b16 {%0,%1,%2,%3}, [%4];"
                 : "=r"(r[0]), "=r"(r[1]), "=r"(r[2]), "=r"(r[3]) : "r"(addr));
}
__device__ __forceinline__ void mma16816(float* d, const uint32_t* a, uint32_t b0, uint32_t b1) {
    asm volatile("mma.sync.aligned.m16n8k16.row.col.f32.bf16.bf16.f32 "
                 "{%0,%1,%2,%3}, {%4,%5,%6,%7}, {%8,%9}, {%0,%1,%2,%3};"
                 : "+f"(d[0]), "+f"(d[1]), "+f"(d[2]), "+f"(d[3])
                 : "r"(a[0]), "r"(a[1]), "r"(a[2]), "r"(a[3]), "r"(b0), "r"(b1));
}
__device__ __forceinline__ void cp16z(uint32_t dst, const void* src, bool v) {
    asm volatile("cp.async.cg.shared.global [%0], [%1], 16, %2;"
                 :: "r"(dst), "l"(src), "r"(v ? 16 : 0));
}
__device__ __forceinline__ void split2(float v, __nv_bfloat16& h, __nv_bfloat16& l) {
    h = __float2bfloat16(v);
    l = __float2bfloat16(v - __bfloat162float(h));
}
__device__ __forceinline__ float ex2f(float x) {
    float r; asm("ex2.approx.ftz.f32 %0, %1;" : "=f"(r) : "f"(x)); return r;
}

#define TCSTR 40

// =================== narrow GEMM (128x128) — used for N=384 only ===========
#define TILE_AH 0
#define TILE_AL 10240
#define TILE_BH 20480
#define TILE_BL 30720
#define STAGE_TOTAL 40960
#define TCG_SMEM (2*STAGE_TOTAL)

__device__ __forceinline__ void stage_load(
    uint32_t sb, const __nv_bfloat16* Ah, const __nv_bfloat16* Al,
    const __nv_bfloat16* Bh, const __nv_bfloat16* Bl,
    int M, int N, int K, int rowBase, int colBase, int k0, int ldR, int ldC) {
    int gr = rowBase + ldR; bool av = gr < M; if (!av) gr = 0;
    const char* pa  = (const char*)(Ah + (size_t)gr * K + k0) + ldC;
    const char* pal = (const char*)(Al + (size_t)gr * K + k0) + ldC;
    uint32_t da  = sb + TILE_AH + ldR * 80 + ldC;
    uint32_t dal = sb + TILE_AL + ldR * 80 + ldC;
    cp16z(da, pa, av);        cp16z(da + 16, pa + 16, av);
    cp16z(dal, pal, av);      cp16z(dal + 16, pal + 16, av);
    int gc = colBase + ldR; bool bv = gc < N; if (!bv) gc = 0;
    const char* pb  = (const char*)(Bh + (size_t)gc * K + k0) + ldC;
    const char* pbl = (const char*)(Bl + (size_t)gc * K + k0) + ldC;
    uint32_t db  = sb + TILE_BH + ldR * 80 + ldC;
    uint32_t dbl = sb + TILE_BL + ldR * 80 + ldC;
    cp16z(db, pb, bv);        cp16z(db + 16, pb + 16, bv);
    cp16z(dbl, pbl, bv);      cp16z(dbl + 16, pbl + 16, bv);
    asm volatile("cp.async.commit_group;" ::: "memory");
}

__global__ __launch_bounds__(256)
void tc_gemm_bf(const __nv_bfloat16* __restrict__ Ah, const __nv_bfloat16* __restrict__ Al,
                const __nv_bfloat16* __restrict__ Bh, const __nv_bfloat16* __restrict__ Bl,
                const float* __restrict__ bias, float* __restrict__ Cf,
                int M, int N, int K) {
    extern __shared__ char smem[];
    const uint32_t sbase = smem_u32(smem);
    const int tid  = threadIdx.x;
    const int lane = tid & 31;
    const int wid  = tid >> 5;
    const int warpM = wid & 3;
    const int warpN = wid >> 2;
    const int rowBase = blockIdx.y * 128;
    const int colBase = blockIdx.x * 128;
    const int ldR = tid >> 1;
    const int ldC = (tid & 1) * 32;

    const int aRow = (lane & 15);
    const int aColOff = (lane >> 4) * 8;
    const int bRow = (lane & 7) + ((lane >> 4) & 1) * 8;
    const int bColOff = ((lane >> 3) & 1) * 8;

    float acc[2][8][4];
    #pragma unroll
    for (int mt = 0; mt < 2; mt++)
        #pragma unroll
        for (int nt = 0; nt < 8; nt++)
            #pragma unroll
            for (int i = 0; i < 4; i++) acc[mt][nt][i] = 0.f;

    const int KC = K >> 5;
    stage_load(sbase, Ah, Al, Bh, Bl, M, N, K, rowBase, colBase, 0, ldR, ldC);

    for (int c = 0; c < KC; c++) {
        asm volatile("cp.async.wait_group 0;" ::: "memory");
        __syncthreads();
        if (c + 1 < KC)
            stage_load(sbase + ((c + 1) & 1) * STAGE_TOTAL, Ah, Al, Bh, Bl,
                       M, N, K, rowBase, colBase, (c + 1) << 5, ldR, ldC);

        const uint32_t sb = sbase + (c & 1) * STAGE_TOTAL;
        #pragma unroll
        for (int ks = 0; ks < 32; ks += 16) {
            uint32_t ah[2][4], al[2][4];
            #pragma unroll
            for (int mt = 0; mt < 2; mt++) {
                const int r0 = warpM * 32 + mt * 16;
                uint32_t off = (uint32_t)((r0 + aRow) * TCSTR + ks + aColOff) * 2;
                ldmx4(sb + TILE_AH + off, ah[mt]);
                ldmx4(sb + TILE_AL + off, al[mt]);
            }
            uint32_t bh[4][4], bl[4][4];
            #pragma unroll
            for (int nb = 0; nb < 4; nb++) {
                const int n0 = warpN * 64 + nb * 16;
                uint32_t off = (uint32_t)((n0 + bRow) * TCSTR + ks + bColOff) * 2;
                ldmx4(sb + TILE_BH + off, bh[nb]);
                ldmx4(sb + TILE_BL + off, bl[nb]);
            }
            #pragma unroll
            for (int mt = 0; mt < 2; mt++) {
                #pragma unroll
                for (int nt = 0; nt < 8; nt++) {
                    const int nb = nt >> 1, hi = (nt & 1) * 2;
                    mma16816(acc[mt][nt], ah[mt], bh[nb][hi], bh[nb][hi+1]);
                    mma16816(acc[mt][nt], ah[mt], bl[nb][hi], bl[nb][hi+1]);
                    mma16816(acc[mt][nt], al[mt], bh[nb][hi], bh[nb][hi+1]);
                }
            }
        }
    }

    #pragma unroll
    for (int mt = 0; mt < 2; mt++) {
        #pragma unroll
        for (int half = 0; half < 2; half++) {
            const int row = rowBase + warpM * 32 + mt * 16 + (lane >> 2) + half * 8;
            if (row < M) {
                #pragma unroll
                for (int nt = 0; nt < 8; nt++) {
                    const int col = colBase + warpN * 64 + nt * 8 + (lane & 3) * 2;
                    float ox = acc[mt][nt][half*2+0] + bias[col];
                    float oy = acc[mt][nt][half*2+1] + bias[col+1];
                    *(float2*)(Cf + (size_t)row * N + col) = make_float2(ox, oy);
                }
            }
        }
    }
}

// =================== wide GEMM (128x256, warp tile 64x64) ==================
// 8 warps: warpM in {0,1} (64 rows), warpN in {0..3} (64 cols). BK=32,
// 2-stage cp.async. N must be a multiple of 256.
#define WT_AH 0
#define WT_AL 10240
#define WT_BH 20480
#define WT_BL 40960
#define WSTAGE 61440
#define TCGW_SMEM (2*WSTAGE)

__device__ __forceinline__ void stage_load_w(
    uint32_t sb, const __nv_bfloat16* Ah, const __nv_bfloat16* Al,
    const __nv_bfloat16* Bh, const __nv_bfloat16* Bl,
    int M, int K, int rowBase, int colBase, int k0, int tid) {
    // A: 128 rows x 64B (hi+lo); thread -> row tid>>1, 32B half
    {
        const int r = tid >> 1, cb = (tid & 1) * 32;
        int gr = rowBase + r; bool av = gr < M; if (!av) gr = 0;
        const char* pa  = (const char*)(Ah + (size_t)gr * K + k0) + cb;
        const char* pal = (const char*)(Al + (size_t)gr * K + k0) + cb;
        uint32_t da  = sb + WT_AH + r * 80 + cb;
        uint32_t dal = sb + WT_AL + r * 80 + cb;
        cp16z(da, pa, av);       cp16z(da + 16, pa + 16, av);
        cp16z(dal, pal, av);     cp16z(dal + 16, pal + 16, av);
    }
    // B: 256 rows x 64B (hi+lo); thread -> full row tid
    {
        const int r = tid;
        const int gc = colBase + r;          // N multiple of 256: always valid
        const char* pb  = (const char*)(Bh + (size_t)gc * K + k0);
        const char* pbl = (const char*)(Bl + (size_t)gc * K + k0);
        uint32_t db  = sb + WT_BH + r * 80;
        uint32_t dbl = sb + WT_BL + r * 80;
        #pragma unroll
        for (int j = 0; j < 4; j++) {
            cp16z(db + j * 16, pb + j * 16, true);
            cp16z(dbl + j * 16, pbl + j * 16, true);
        }
    }
    asm volatile("cp.async.commit_group;" ::: "memory");
}

template<bool RELU, bool SPLITOUT>
__global__ __launch_bounds__(256, 1)
void tc_gemm_w(const __nv_bfloat16* __restrict__ Ah, const __nv_bfloat16* __restrict__ Al,
               const __nv_bfloat16* __restrict__ Bh, const __nv_bfloat16* __restrict__ Bl,
               const float* __restrict__ bias, float* __restrict__ Cf,
               __nv_bfloat16* __restrict__ Chi, __nv_bfloat16* __restrict__ Clo,
               int M, int N, int K) {
    extern __shared__ char smem[];
    const uint32_t sbase = smem_u32(smem);
    const int tid  = threadIdx.x;
    const int lane = tid & 31;
    const int wid  = tid >> 5;
    const int warpM = wid & 1;           // 64-row slice
    const int warpN = wid >> 1;          // 64-col slice
    const int rowBase = blockIdx.y * 128;
    const int colBase = blockIdx.x * 256;

    const int aRow = (lane & 15);
    const int aColOff = (lane >> 4) * 8;
    const int bRow = (lane & 7) + ((lane >> 4) & 1) * 8;
    const int bColOff = ((lane >> 3) & 1) * 8;

    float acc[4][8][4];
    #pragma unroll
    for (int mt = 0; mt < 4; mt++)
        #pragma unroll
        for (int nt = 0; nt < 8; nt++)
            #pragma unroll
            for (int i = 0; i < 4; i++) acc[mt][nt][i] = 0.f;

    const int KC = K >> 5;
    stage_load_w(sbase, Ah, Al, Bh, Bl, M, K, rowBase, colBase, 0, tid);

    for (int c = 0; c < KC; c++) {
        asm volatile("cp.async.wait_group 0;" ::: "memory");
        __syncthreads();
        if (c + 1 < KC)
            stage_load_w(sbase + ((c + 1) & 1) * WSTAGE, Ah, Al, Bh, Bl,
                         M, K, rowBase, colBase, (c + 1) << 5, tid);

        const uint32_t sb = sbase + (c & 1) * WSTAGE;
        #pragma unroll
        for (int ks = 0; ks < 32; ks += 16) {
            uint32_t ah[4][4], al[4][4];
            #pragma unroll
            for (int mt = 0; mt < 4; mt++) {
                const int r0 = warpM * 64 + mt * 16;
                uint32_t off = (uint32_t)((r0 + aRow) * TCSTR + ks + aColOff) * 2;
                ldmx4(sb + WT_AH + off, ah[mt]);
                ldmx4(sb + WT_AL + off, al[mt]);
            }
            #pragma unroll
            for (int nb = 0; nb < 4; nb++) {
                const int n0 = warpN * 64 + nb * 16;
                uint32_t off = (uint32_t)((n0 + bRow) * TCSTR + ks + bColOff) * 2;
                uint32_t bh[4], bl[4];
                ldmx4(sb + WT_BH + off, bh);
                ldmx4(sb + WT_BL + off, bl);
                #pragma unroll
                for (int mt = 0; mt < 4; mt++) {
                    #pragma unroll
                    for (int sub = 0; sub < 2; sub++) {
                        const int nt = nb * 2 + sub;
                        mma16816(acc[mt][nt], ah[mt], bh[sub*2], bh[sub*2+1]);
                        mma16816(acc[mt][nt], ah[mt], bl[sub*2], bl[sub*2+1]);
                        mma16816(acc[mt][nt], al[mt], bh[sub*2], bh[sub*2+1]);
                    }
                }
            }
        }
    }

    #pragma unroll
    for (int mt = 0; mt < 4; mt++) {
        #pragma unroll
        for (int half = 0; half < 2; half++) {
            const int row = rowBase + warpM * 64 + mt * 16 + (lane >> 2) + half * 8;
            if (row < M) {
                #pragma unroll
                for (int nt = 0; nt < 8; nt++) {
                    const int col = colBase + warpN * 64 + nt * 8 + (lane & 3) * 2;
                    float ox = acc[mt][nt][half*2+0] + bias[col];
                    float oy = acc[mt][nt][half*2+1] + bias[col+1];
                    if (RELU) { ox = fmaxf(ox, 0.f); oy = fmaxf(oy, 0.f); }
                    if (SPLITOUT) {
                        __nv_bfloat16 hx, lx, hy, ly;
                        split2(ox, hx, lx); split2(oy, hy, ly);
                        *(__nv_bfloat162*)(Chi + (size_t)row * N + col) = __nv_bfloat162(hx, hy);
                        *(__nv_bfloat162*)(Clo + (size_t)row * N + col) = __nv_bfloat162(lx, ly);
                    } else {
                        *(float2*)(Cf + (size_t)row * N + col) = make_float2(ox, oy);
                    }
                }
            }
        }
    }
}

// =================== tensor-core flash self-attention (unchanged R7) =======
#define ATT_QH 0
#define ATT_QL 10240
#define ATT_KV(st) (20480 + (st)*20480)
#define ATT_KH_O 0
#define ATT_KL_O 5120
#define ATT_VH_O 10240
#define ATT_VL_O 15360
#define ATT_SMEM (20480 + 2*20480)
#define KSCALE 0.25503486f   /* log2(e)/sqrt(32) */

__global__ __launch_bounds__(256)
void attn_mma(const __nv_bfloat16* __restrict__ qkh, const __nv_bfloat16* __restrict__ qkl,
              const __nv_bfloat16* __restrict__ vph, const __nv_bfloat16* __restrict__ vpl,
              __nv_bfloat16* __restrict__ oh, __nv_bfloat16* __restrict__ ol) {
    extern __shared__ char smem[];
    const uint32_t sb = smem_u32(smem);
    const int tid = threadIdx.x;
    const int lane = tid & 31;
    const int w = tid >> 5;
    const int g = lane >> 2, t4 = lane & 3;
    const int qbase = blockIdx.x * 128;
    const int b = blockIdx.y >> 3, h = blockIdx.y & 7;

    {
        const int r = tid >> 1, cb = (tid & 1) * 32;
        const int gr = qbase + r;
        const bool v = gr < LQ;
        const size_t rowo = ((size_t)(b * LQ + (v ? gr : 0)) * 512 + h * 32) * 2;
        cp16z(sb + ATT_QH + r * 80 + cb,      (const char*)qkh + rowo + cb, v);
        cp16z(sb + ATT_QH + r * 80 + cb + 16, (const char*)qkh + rowo + cb + 16, v);
        cp16z(sb + ATT_QL + r * 80 + cb,      (const char*)qkl + rowo + cb, v);
        cp16z(sb + ATT_QL + r * 80 + cb + 16, (const char*)qkl + rowo + cb + 16, v);
    }
    {
        const int r = tid >> 2, j = tid & 3;
        const bool v = r < LQ;
        const size_t ko = ((size_t)(b * LQ + (v ? r : 0)) * 512 + 256 + h * 32) * 2 + j * 16;
        const size_t vo = ((size_t)(b * LQ + (v ? r : 0)) * 256 + h * 32) * 2 + j * 16;
        cp16z(sb + ATT_KV(0) + ATT_KH_O + r * 80 + j * 16, (const char*)qkh + ko, v);
        cp16z(sb + ATT_KV(0) + ATT_KL_O + r * 80 + j * 16, (const char*)qkl + ko, v);
        cp16z(sb + ATT_KV(0) + ATT_VH_O + r * 80 + j * 16, (const char*)vph + vo, v);
        cp16z(sb + ATT_KV(0) + ATT_VL_O + r * 80 + j * 16, (const char*)vpl + vo, v);
    }
    asm volatile("cp.async.commit_group;" ::: "memory");

    float m0 = -1e30f, m1 = -1e30f, l0 = 0.f, l1 = 0.f;
    float o[4][4];
    #pragma unroll
    for (int vt = 0; vt < 4; vt++)
        #pragma unroll
        for (int i = 0; i < 4; i++) o[vt][i] = 0.f;

    uint32_t qh[2][4], ql[2][4];
    const int bRow = (lane & 7) + ((lane >> 4) & 1) * 8;
    const int bColOff = ((lane >> 3) & 1) * 8;
    const int NT = (LQ + 63) / 64;

    for (int ti = 0; ti < NT; ti++) {
        asm volatile("cp.async.wait_group 0;" ::: "memory");
        __syncthreads();
        if (ti == 0) {
            #pragma unroll
            for (int kf = 0; kf < 2; kf++) {
                uint32_t off = (uint32_t)((w * 16 + (lane & 15)) * TCSTR + kf * 16 + (lane >> 4) * 8) * 2;
                ldmx4(sb + ATT_QH + off, qh[kf]);
                ldmx4(sb + ATT_QL + off, ql[kf]);
            }
        }
        if (ti + 1 < NT) {
            const int kt = (ti + 1) * 64;
            const int r = tid >> 2, j = tid & 3;
            const int kr = kt + r;
            const bool v = kr < LQ;
            const size_t ko = ((size_t)(b * LQ + (v ? kr : 0)) * 512 + 256 + h * 32) * 2 + j * 16;
            const size_t vo = ((size_t)(b * LQ + (v ? kr : 0)) * 256 + h * 32) * 2 + j * 16;
            const uint32_t st = sb + ATT_KV((ti + 1) & 1);
            cp16z(st + ATT_KH_O + r * 80 + j * 16, (const char*)qkh + ko, v);
            cp16z(st + ATT_KL_O + r * 80 + j * 16, (const char*)qkl + ko, v);
            cp16z(st + ATT_VH_O + r * 80 + j * 16, (const char*)vph + vo, v);
            cp16z(st + ATT_VL_O + r * 80 + j * 16, (const char*)vpl + vo, v);
            asm volatile("cp.async.commit_group;" ::: "memory");
        }

        const uint32_t stg = sb + ATT_KV(ti & 1);
        const int kt = ti * 64;

        float s[8][4];
        #pragma unroll
        for (int nt = 0; nt < 8; nt++)
            #pragma unroll
            for (int i = 0; i < 4; i++) s[nt][i] = 0.f;
        #pragma unroll
        for (int kf = 0; kf < 2; kf++) {
            #pragma unroll
            for (int nb = 0; nb < 4; nb++) {
                uint32_t off = (uint32_t)((nb * 16 + bRow) * TCSTR + kf * 16 + bColOff) * 2;
                uint32_t kh[4], kl[4];
                ldmx4(stg + ATT_KH_O + off, kh);
                ldmx4(stg + ATT_KL_O + off, kl);
                #pragma unroll
                for (int hf = 0; hf < 2; hf++) {
                    const int nt = nb * 2 + hf;
                    mma16816(s[nt], qh[kf], kh[hf*2], kh[hf*2+1]);
                    mma16816(s[nt], qh[kf], kl[hf*2], kl[hf*2+1]);
                    mma16816(s[nt], ql[kf], kh[hf*2], kh[hf*2+1]);
                }
            }
        }

        const int validTiles = min(8, (LQ - kt) >> 3);
        float tmax0 = -1e30f, tmax1 = -1e30f;
        #pragma unroll
        for (int nt = 0; nt < 8; nt++) {
            if (nt < validTiles) {
                s[nt][0] *= KSCALE; s[nt][1] *= KSCALE;
                s[nt][2] *= KSCALE; s[nt][3] *= KSCALE;
            } else {
                s[nt][0] = s[nt][1] = s[nt][2] = s[nt][3] = -1e30f;
            }
            tmax0 = fmaxf(tmax0, fmaxf(s[nt][0], s[nt][1]));
            tmax1 = fmaxf(tmax1, fmaxf(s[nt][2], s[nt][3]));
        }
        tmax0 = fmaxf(tmax0, __shfl_xor_sync(0xffffffffu, tmax0, 1));
        tmax0 = fmaxf(tmax0, __shfl_xor_sync(0xffffffffu, tmax0, 2));
        tmax1 = fmaxf(tmax1, __shfl_xor_sync(0xffffffffu, tmax1, 1));
        tmax1 = fmaxf(tmax1, __shfl_xor_sync(0xffffffffu, tmax1, 2));
        const float mn0 = fmaxf(m0, tmax0), mn1 = fmaxf(m1, tmax1);
        const float c0 = ex2f(m0 - mn0), c1 = ex2f(m1 - mn1);
        m0 = mn0; m1 = mn1;
        l0 *= c0; l1 *= c1;
        #pragma unroll
        for (int vt = 0; vt < 4; vt++) {
            o[vt][0] *= c0; o[vt][1] *= c0; o[vt][2] *= c1; o[vt][3] *= c1;
        }

        uint32_t ph[4][4], pl[4][4];
        #pragma unroll
        for (int nt = 0; nt < 8; nt++) {
            float p0 = ex2f(s[nt][0] - mn0), p1 = ex2f(s[nt][1] - mn0);
            float p2 = ex2f(s[nt][2] - mn1), p3 = ex2f(s[nt][3] - mn1);
            l0 += p0 + p1; l1 += p2 + p3;
            __nv_bfloat16 h0,lo0,h1,lo1,h2,lo2,h3,lo3;
            split2(p0,h0,lo0); split2(p1,h1,lo1); split2(p2,h2,lo2); split2(p3,h3,lo3);
            const int ks = nt >> 1, base = (nt & 1) * 2;
            __nv_bfloat162 ph01(h0,h1), ph23(h2,h3), pl01(lo0,lo1), pl23(lo2,lo3);
            ph[ks][base+0] = *(uint32_t*)&ph01;
            ph[ks][base+1] = *(uint32_t*)&ph23;
            pl[ks][base+0] = *(uint32_t*)&pl01;
            pl[ks][base+1] = *(uint32_t*)&pl23;
        }

        #pragma unroll
        for (int ks = 0; ks < 4; ks++) {
            const int krow = ks * 16 + (lane & 7) + ((lane >> 3) & 1) * 8;
            #pragma unroll
            for (int nh = 0; nh < 2; nh++) {
                uint32_t off = (uint32_t)(krow * TCSTR + nh * 16 + (lane >> 4) * 8) * 2;
                uint32_t vh[4], vl[4];
                ldmx4t(stg + ATT_VH_O + off, vh);
                ldmx4t(stg + ATT_VL_O + off, vl);
                #pragma unroll
                for (int sub = 0; sub < 2; sub++) {
                    const int vt = nh * 2 + sub;
                    mma16816(o[vt], ph[ks], vh[sub*2], vh[sub*2+1]);
                    mma16816(o[vt], ph[ks], vl[sub*2], vl[sub*2+1]);
                    mma16816(o[vt], pl[ks], vh[sub*2], vh[sub*2+1]);
                }
            }
        }
    }

    l0 += __shfl_xor_sync(0xffffffffu, l0, 1);
    l0 += __shfl_xor_sync(0xffffffffu, l0, 2);
    l1 += __shfl_xor_sync(0xffffffffu, l1, 1);
    l1 += __shfl_xor_sync(0xffffffffu, l1, 2);
    const float inv0 = 1.f / l0, inv1 = 1.f / l1;
    const int r0 = qbase + w * 16 + g;
    const int r1 = r0 + 8;
    #pragma unroll
    for (int half = 0; half < 2; half++) {
        const int row = half ? r1 : r0;
        const float inv = half ? inv1 : inv0;
        if (row < LQ) {
            const size_t base = ((size_t)(b * LQ + row)) * DM + h * DH;
            #pragma unroll
            for (int vt = 0; vt < 4; vt++) {
                float vx = o[vt][half*2+0] * inv;
                float vy = o[vt][half*2+1] * inv;
                __nv_bfloat16 hx,lx,hy,ly;
                split2(vx,hx,lx); split2(vy,hy,ly);
                const size_t idx = base + vt * 8 + t4 * 2;
                *(__nv_bfloat162*)(oh + idx) = __nv_bfloat162(hx,hy);
                *(__nv_bfloat162*)(ol + idx) = __nv_bfloat162(lx,ly);
            }
        }
    }
}

// ---------------- weight splitter + combined bias --------------------------
__global__ void split_weights(const float* __restrict__ w0, const float* __restrict__ w1,
                              const float* __restrict__ w2, const float* __restrict__ w3,
                              const float* __restrict__ w4, const float* __restrict__ w5,
                              const float* __restrict__ w6, const float* __restrict__ w7,
                              const float* __restrict__ off_b, const float* __restrict__ aw_b,
                              __nv_bfloat16* __restrict__ hi, __nv_bfloat16* __restrict__ lo,
                              float* __restrict__ cbias) {
    int i = blockIdx.x * blockDim.x + threadIdx.x;
    if (i < 384) cbias[i] = (i < 256) ? off_b[i] : aw_b[i - 256];
    if (i >= WTOT) return;
    const float* src; int local;
    if      (i < OFF_SAOUT) { src = w0; local = i; }
    else if (i < OFF_OFFW)  { src = w1; local = i - OFF_SAOUT; }
    else if (i < OFF_VALW)  { src = (i < 327680) ? w2 : w3; local = (i < 327680) ? i - OFF_OFFW : i - 327680; }
    else if (i < OFF_OUTPW) { src = w4; local = i - OFF_VALW; }
    else if (i < OFF_FFN1)  { src = w5; local = i - OFF_OUTPW; }
    else if (i < OFF_FFN2)  { src = w6; local = i - OFF_FFN1; }
    else                    { src = w7; local = i - OFF_FFN2; }
    __nv_bfloat16 h, l;
    split2(src[local], h, l);
    hi[i] = h; lo[i] = l;
}

// ---------------- add + split ----------------------------------------------
__global__ void add_split_kernel(const float* __restrict__ a, const float* __restrict__ b,
                                 __nv_bfloat16* __restrict__ qh, __nv_bfloat16* __restrict__ ql,
                                 __nv_bfloat16* __restrict__ th, __nv_bfloat16* __restrict__ tl,
                                 int n4) {
    int i = blockIdx.x * blockDim.x + threadIdx.x;
    if (i >= n4) return;
    float4 x = ((const float4*)a)[i];
    float4 y = ((const float4*)b)[i];
    float q0 = x.x + y.x, q1 = x.y + y.y, q2 = x.z + y.z, q3 = x.w + y.w;
    __nv_bfloat16 h0,l0,h1,l1,h2,l2,h3,l3;
    split2(q0,h0,l0); split2(q1,h1,l1); split2(q2,h2,l2); split2(q3,h3,l3);
    *(__nv_bfloat162*)(qh + i*4)     = __nv_bfloat162(h0,h1);
    *(__nv_bfloat162*)(qh + i*4 + 2) = __nv_bfloat162(h2,h3);
    *(__nv_bfloat162*)(ql + i*4)     = __nv_bfloat162(l0,l1);
    *(__nv_bfloat162*)(ql + i*4 + 2) = __nv_bfloat162(l2,l3);
    split2(x.x,h0,l0); split2(x.y,h1,l1); split2(x.z,h2,l2); split2(x.w,h3,l3);
    *(__nv_bfloat162*)(th + i*4)     = __nv_bfloat162(h0,h1);
    *(__nv_bfloat162*)(th + i*4 + 2) = __nv_bfloat162(h2,h3);
    *(__nv_bfloat162*)(tl + i*4)     = __nv_bfloat162(l0,l1);
    *(__nv_bfloat162*)(tl + i*4 + 2) = __nv_bfloat162(l2,l3);
}

// ---------------- generic fp32 -> hi/lo splitter ---------------------------
__global__ void split_kernel(const float* __restrict__ a,
                             __nv_bfloat16* __restrict__ hi, __nv_bfloat16* __restrict__ lo,
                             int n4) {
    int i = blockIdx.x * blockDim.x + threadIdx.x;
    if (i >= n4) return;
    float4 x = ((const float4*)a)[i];
    __nv_bfloat16 h0,l0,h1,l1,h2,l2,h3,l3;
    split2(x.x,h0,l0); split2(x.y,h1,l1); split2(x.z,h2,l2); split2(x.w,h3,l3);
    *(__nv_bfloat162*)(hi + i*4)     = __nv_bfloat162(h0,h1);
    *(__nv_bfloat162*)(hi + i*4 + 2) = __nv_bfloat162(h2,h3);
    *(__nv_bfloat162*)(lo + i*4)     = __nv_bfloat162(l0,l1);
    *(__nv_bfloat162*)(lo + i*4 + 2) = __nv_bfloat162(l2,l3);
}

// ---------------- LayerNorm(x+res) -----------------------------------------
__global__ __launch_bounds__(256)
void ln_kernel(const float* __restrict__ x, const float* __restrict__ res,
               const float* __restrict__ g, const float* __restrict__ bta,
               float* __restrict__ out,
               const float* __restrict__ pos,
               __nv_bfloat16* __restrict__ hi, __nv_bfloat16* __restrict__ lo) {
    __shared__ float red[8];
    const int row = blockIdx.x, t = threadIdx.x;
    const size_t idx = (size_t)row * DM + t;
    float v = x[idx] + res[idx];

    float s = v;
    #pragma unroll
    for (int o = 16; o; o >>= 1) s += __shfl_xor_sync(0xffffffffu, s, o);
    if ((t & 31) == 0) red[t >> 5] = s;
    __syncthreads();
    float mean = 0.f;
    #pragma unroll
    for (int i = 0; i < 8; i++) mean += red[i];
    mean *= (1.f / DM);
    __syncthreads();

    float d = v - mean;
    float s2 = d * d;
    #pragma unroll
    for (int o = 16; o; o >>= 1) s2 += __shfl_xor_sync(0xffffffffu, s2, o);
    if ((t & 31) == 0) red[t >> 5] = s2;
    __syncthreads();
    float var = 0.f;
    #pragma unroll
    for (int i = 0; i < 8; i++) var += red[i];
    var *= (1.f / DM);

    float o = d * rsqrtf(var + 1e-5f) * g[t] + bta[t];
    out[idx] = o;
    if (hi) {
        float tq = pos ? o + pos[idx] : o;
        __nv_bfloat16 hh, ll;
        split2(tq, hh, ll);
        hi[idx] = hh; lo[idx] = ll;
    }
}

// ---------------- attention-weight softmax ---------------------------------
__global__ void awsm_kernel(float* __restrict__ offaw) {
    int i = blockIdx.x * blockDim.x + threadIdx.x;
    if (i >= NQ * NH) return;
    float* p = offaw + (size_t)(i / NH) * 384 + 256 + (i % NH) * 16;
    float mx = -1e30f;
    #pragma unroll
    for (int j = 0; j < 16; j++) mx = fmaxf(mx, p[j]);
    float sm = 0.f, e[16];
    #pragma unroll
    for (int j = 0; j < 16; j++) { e[j] = __expf(p[j] - mx); sm += e[j]; }
    float inv = 1.f / sm;
    #pragma unroll
    for (int j = 0; j < 16; j++) p[j] = e[j] * inv;
}

// ---------------- MS-deformable sampling -----------------------------------
__global__ __launch_bounds__(256)
void deform_kernel(const float* __restrict__ value, const float* __restrict__ offaw,
                   const float* __restrict__ ref,
                   __nv_bfloat16* __restrict__ oh, __nv_bfloat16* __restrict__ ol) {
    const int qidx = blockIdx.x;
    const int b = qidx / LQ;
    const int h = threadIdx.y, d = threadIdx.x;

    const int starts[4] = {0, 16384, 20480, 21504};
    const int Wi[4]     = {128, 64, 32, 16};

    const float* vb = value + (size_t)b * LEN_IN * DM + h * DH + d;
    const size_t oq = (size_t)qidx;
    const float* offp = offaw + oq * 384;
    float acc = 0.f;

    #pragma unroll
    for (int lvl = 0; lvl < NLV; lvl++) {
        const float W = (float)Wi[lvl];
        const int   Wl = Wi[lvl];
        const int   st = starts[lvl];
        const float rx = ref[(oq * NLV + lvl) * 2 + 0];
        const float ry = ref[(oq * NLV + lvl) * 2 + 1];
        #pragma unroll
        for (int p = 0; p < NPT; p++) {
            const int oidx = ((h * NLV + lvl) * NPT + p) * 2;
            const float ox = offp[oidx + 0];
            const float oy = offp[oidx + 1];
            const float a  = offp[256 + h * 16 + lvl * 4 + p];
            const float x = (rx + ox / W) * W - 0.5f;
            const float y = (ry + oy / W) * W - 0.5f;
            const float x0f = floorf(x), y0f = floorf(y);
            const float lx = x - x0f, ly = y - y0f;
            const int x0 = (int)x0f, y0 = (int)y0f;

            const float w00 = (1.f - ly) * (1.f - lx);
            const float w01 = (1.f - ly) * lx;
            const float w10 = ly * (1.f - lx);
            const float w11 = ly * lx;

            const bool xv0 = (x0 >= 0) & (x0 < Wl);
            const bool xv1 = (x0 + 1 >= 0) & (x0 + 1 < Wl);
            const bool yv0 = (y0 >= 0) & (y0 < Wl);
            const bool yv1 = (y0 + 1 >= 0) & (y0 + 1 < Wl);

            if (yv0 & xv0) acc = fmaf(a * w00, vb[(size_t)(st + y0 * Wl + x0) * DM], acc);
            if (yv0 & xv1) acc = fmaf(a * w01, vb[(size_t)(st + y0 * Wl + x0 + 1) * DM], acc);
            if (yv1 & xv0) acc = fmaf(a * w10, vb[(size_t)(st + (y0 + 1) * Wl + x0) * DM], acc);
            if (yv1 & xv1) acc = fmaf(a * w11, vb[(size_t)(st + (y0 + 1) * Wl + x0 + 1) * DM], acc);
        }
    }
    __nv_bfloat16 hh, ll;
    split2(acc, hh, ll);
    oh[oq * DM + h * DH + d] = hh;
    ol[oq * DM + h * DH + d] = ll;
}

// ---------------- host-side orchestration ----------------------------------
enum GMode { GM_F32, GM_SPLIT, GM_RELU_SPLIT };
static inline void gemm_bf(const __nv_bfloat16* Ah, const __nv_bfloat16* Al,
                           const __nv_bfloat16* Bh, const __nv_bfloat16* Bl,
                           const float* bias, float* Cf,
                           __nv_bfloat16* Chi, __nv_bfloat16* Clo,
                           int M, int N, int K, GMode mode) {
    if (N % 256 == 0) {
        dim3 grid(N / 256, (M + 127) / 128);
        if (mode == GM_RELU_SPLIT)
            tc_gemm_w<true, true><<<grid, 256, TCGW_SMEM>>>(Ah, Al, Bh, Bl, bias, Cf, Chi, Clo, M, N, K);
        else if (mode == GM_SPLIT)
            tc_gemm_w<false, true><<<grid, 256, TCGW_SMEM>>>(Ah, Al, Bh, Bl, bias, Cf, Chi, Clo, M, N, K);
        else
            tc_gemm_w<false, false><<<grid, 256, TCGW_SMEM>>>(Ah, Al, Bh, Bl, bias, Cf, Chi, Clo, M, N, K);
    } else {
        dim3 grid(N / 128, (M + 127) / 128);
        tc_gemm_bf<<<grid, 256, TCG_SMEM>>>(Ah, Al, Bh, Bl, bias, Cf, M, N, K);
    }
}

extern "C" void kernel_launch(void* const* d_in, const int* in_sizes, int n_in,
                              void* d_out, int out_size) {
    (void)in_sizes; (void)n_in; (void)out_size;
    const float* tgt       = (const float*)d_in[0];
    const float* query_pos = (const float*)d_in[1];
    const float* refpts    = (const float*)d_in[2];
    const float* src       = (const float*)d_in[3];
    const float* sa_in_b   = (const float*)d_in[7];
    const float* sa_out_b  = (const float*)d_in[9];
    const float* norm2_g   = (const float*)d_in[10];
    const float* norm2_b   = (const float*)d_in[11];
    const float* off_b     = (const float*)d_in[13];
    const float* aw_b      = (const float*)d_in[15];
    const float* val_b     = (const float*)d_in[17];
    const float* outp_b    = (const float*)d_in[19];
    const float* norm1_g   = (const float*)d_in[20];
    const float* norm1_b   = (const float*)d_in[21];
    const float* ffn_b1    = (const float*)d_in[23];
    const float* ffn_b2    = (const float*)d_in[25];
    const float* norm3_g   = (const float*)d_in[26];
    const float* norm3_b   = (const float*)d_in[27];
    float* out = (float*)d_out;

    cudaFuncSetAttribute(tc_gemm_bf, cudaFuncAttributeMaxDynamicSharedMemorySize, TCG_SMEM);
    cudaFuncSetAttribute(tc_gemm_w<false,false>, cudaFuncAttributeMaxDynamicSharedMemorySize, TCGW_SMEM);
    cudaFuncSetAttribute(tc_gemm_w<false,true>,  cudaFuncAttributeMaxDynamicSharedMemorySize, TCGW_SMEM);
    cudaFuncSetAttribute(tc_gemm_w<true,true>,   cudaFuncAttributeMaxDynamicSharedMemorySize, TCGW_SMEM);
    cudaFuncSetAttribute(attn_mma, cudaFuncAttributeMaxDynamicSharedMemorySize, ATT_SMEM);

    void* p;
    #define SYMF(name) cudaGetSymbolAddress(&p, name); float* name##_p = (float*)p;
    #define SYMB(name) cudaGetSymbolAddress(&p, name); __nv_bfloat16* name##_p = (__nv_bfloat16*)p;
    SYMF(g_proj) SYMF(g_tgt2) SYMF(g_tgt3)
    SYMF(g_offaw) SYMF(g_value) SYMF(g_cbias)
    SYMB(g_qk_h) SYMB(g_qk_l) SYMB(g_tgt_h) SYMB(g_tgt_l)
    SYMB(g_qk2_h) SYMB(g_qk2_l) SYMB(g_v2_h) SYMB(g_v2_l)
    SYMB(g_att_h) SYMB(g_att_l) SYMB(g_query_h) SYMB(g_query_l)
    SYMB(g_tgt3_h) SYMB(g_tgt3_l) SYMB(g_ca_h) SYMB(g_ca_l)
    SYMB(g_ffn_h) SYMB(g_ffn_l) SYMB(g_src_h) SYMB(g_src_l)
    SYMB(g_wh) SYMB(g_wl)
    #undef SYMF
    #undef SYMB

    // 0) weight + input splits
    split_weights<<<(WTOT + 255)/256, 256>>>(
        (const float*)d_in[6], (const float*)d_in[8], (const float*)d_in[12],
        (const float*)d_in[14], (const float*)d_in[16], (const float*)d_in[18],
        (const float*)d_in[22], (const float*)d_in[24],
        off_b, aw_b, g_wh_p, g_wl_p, g_cbias_p);
    const int n4 = NQ * DM / 4;
    add_split_kernel<<<(n4 + 255)/256, 256>>>(tgt, query_pos, g_qk_h_p, g_qk_l_p,
                                              g_tgt_h_p, g_tgt_l_p, n4);
    const int ns4 = (int)((size_t)NSRC * DM / 4);
    split_kernel<<<(ns4 + 255)/256, 256>>>(src, g_src_h_p, g_src_l_p, ns4);

    // 1) self-attn
    gemm_bf(g_qk_h_p, g_qk_l_p, g_wh_p + OFF_SAIN, g_wl_p + OFF_SAIN, sa_in_b,
            0, g_qk2_h_p, g_qk2_l_p, NQ, 512, DM, GM_SPLIT);
    gemm_bf(g_tgt_h_p, g_tgt_l_p, g_wh_p + OFF_SAIN + 131072, g_wl_p + OFF_SAIN + 131072,
            sa_in_b + 2*DM, 0, g_v2_h_p, g_v2_l_p, NQ, DM, DM, GM_SPLIT);
    attn_mma<<<dim3(8, NB * NH), 256, ATT_SMEM>>>(g_qk2_h_p, g_qk2_l_p, g_v2_h_p, g_v2_l_p,
                                                  g_att_h_p, g_att_l_p);
    gemm_bf(g_att_h_p, g_att_l_p, g_wh_p + OFF_SAOUT, g_wl_p + OFF_SAOUT, sa_out_b,
            g_proj_p, 0, 0, NQ, DM, DM, GM_F32);
    ln_kernel<<<NQ, DM>>>(tgt, g_proj_p, norm2_g, norm2_b, g_tgt2_p, query_pos,
                          g_query_h_p, g_query_l_p);

    // 2) cross-attn
    gemm_bf(g_src_h_p, g_src_l_p, g_wh_p + OFF_VALW, g_wl_p + OFF_VALW, val_b,
            g_value_p, 0, 0, NSRC, DM, DM, GM_F32);
    gemm_bf(g_query_h_p, g_query_l_p, g_wh_p + OFF_OFFW, g_wl_p + OFF_OFFW, g_cbias_p,
            g_offaw_p, 0, 0, NQ, 384, DM, GM_F32);
    awsm_kernel<<<(NQ * NH + 255)/256, 256>>>(g_offaw_p);
    deform_kernel<<<NQ, dim3(32, 8)>>>(g_value_p, g_offaw_p, refpts, g_ca_h_p, g_ca_l_p);
    gemm_bf(g_ca_h_p, g_ca_l_p, g_wh_p + OFF_OUTPW, g_wl_p + OFF_OUTPW, outp_b,
            g_proj_p, 0, 0, NQ, DM, DM, GM_F32);
    ln_kernel<<<NQ, DM>>>(g_tgt2_p, g_proj_p, norm1_g, norm1_b, g_tgt3_p, nullptr,
                          g_tgt3_h_p, g_tgt3_l_p);

    // 3) FFN
    gemm_bf(g_tgt3_h_p, g_tgt3_l_p, g_wh_p + OFF_FFN1, g_wl_p + OFF_FFN1, ffn_b1,
            0, g_ffn_h_p, g_ffn_l_p, NQ, DFFN, DM, GM_RELU_SPLIT);
    gemm_bf(g_ffn_h_p, g_ffn_l_p, g_wh_p + OFF_FFN2, g_wl_p + OFF_FFN2, ffn_b2,
            g_proj_p, 0, 0, NQ, DM, DFFN, GM_F32);
    ln_kernel<<<NQ, DM>>>(g_tgt3_p, g_proj_p, norm3_g, norm3_b, out, nullptr, nullptr, nullptr);
}

// round 9
// speedup vs baseline: 1.0489x; 1.0489x over previous
#include <cuda_runtime.h>
#include <cuda_bf16.h>
#include <math.h>
#include <stdint.h>

#define NB    8
#define LQ    1000
#define DM    256
#define NH    8
#define DH    32
#define NLV   4
#define NPT   4
#define LEN_IN 21760
#define DFFN  1024
#define NQ    (NB*LQ)    /* 8000 */
#define NSRC  (NB*LEN_IN) /* 174080 */

// ---------------- fp32 scratch ---------------------------------------------
__device__ float g_proj[NQ*DM];
__device__ float g_tgt2[NQ*DM];
__device__ float g_tgt3[NQ*DM];
__device__ float g_offaw[NQ*384];
__device__ float g_value[(size_t)NSRC*DM];
__device__ float g_cbias[384];

// ---------------- bf16 hi/lo split scratch ---------------------------------
__device__ __nv_bfloat16 g_qk_h[NQ*DM],   g_qk_l[NQ*DM];
__device__ __nv_bfloat16 g_tgt_h[NQ*DM],  g_tgt_l[NQ*DM];
__device__ __nv_bfloat16 g_qk2_h[NQ*512], g_qk2_l[NQ*512];
__device__ __nv_bfloat16 g_v2_h[NQ*DM],   g_v2_l[NQ*DM];
__device__ __nv_bfloat16 g_att_h[NQ*DM],  g_att_l[NQ*DM];
__device__ __nv_bfloat16 g_query_h[NQ*DM],g_query_l[NQ*DM];
__device__ __nv_bfloat16 g_tgt3_h[NQ*DM], g_tgt3_l[NQ*DM];
__device__ __nv_bfloat16 g_ca_h[NQ*DM],   g_ca_l[NQ*DM];
__device__ __nv_bfloat16 g_ffn_h[NQ*DFFN],g_ffn_l[NQ*DFFN];
__device__ __nv_bfloat16 g_src_h[(size_t)NSRC*DM], g_src_l[(size_t)NSRC*DM];

#define WTOT 1015808
#define OFF_SAIN  0
#define OFF_SAOUT 196608
#define OFF_OFFW  262144
#define OFF_VALW  360448
#define OFF_OUTPW 425984
#define OFF_FFN1  491520
#define OFF_FFN2  753664
__device__ __nv_bfloat16 g_wh[WTOT], g_wl[WTOT];

// =================== helpers ===============================================
__device__ __forceinline__ uint32_t smem_u32(const void* p) {
    uint32_t a;
    asm("{ .reg .u64 t; cvta.to.shared.u64 t, %1; cvt.u32.u64 %0, t; }" : "=r"(a) : "l"(p));
    return a;
}
__device__ __forceinline__ void ldmx4(uint32_t addr, uint32_t* r) {
    asm volatile("ldmatrix.sync.aligned.m8n8.x4.shared.b16 {%0,%1,%2,%3}, [%4];"
                 : "=r"(r[0]), "=r"(r[1]), "=r"(r[2]), "=r"(r[3]) : "r"(addr));
}
__device__ __forceinline__ void ldmx4t(uint32_t addr, uint32_t* r) {
    asm volatile("ldmatrix.sync.aligned.m8n8.x4.trans.shared.b16 {%0,%1,%2,%3}, [%4];"
                 : "=r"(r[0]), "=r"(r[1]), "=r"(r[2]), "=r"(r[3]) : "r"(addr));
}
__device__ __forceinline__ void mma16816(float* d, const uint32_t* a, uint32_t b0, uint32_t b1) {
    asm volatile("mma.sync.aligned.m16n8k16.row.col.f32.bf16.bf16.f32 "
                 "{%0,%1,%2,%3}, {%4,%5,%6,%7}, {%8,%9}, {%0,%1,%2,%3};"
                 : "+f"(d[0]), "+f"(d[1]), "+f"(d[2]), "+f"(d[3])
                 : "r"(a[0]), "r"(a[1]), "r"(a[2]), "r"(a[3]), "r"(b0), "r"(b1));
}
__device__ __forceinline__ void cp16z(uint32_t dst, const void* src, bool v) {
    asm volatile("cp.async.cg.shared.global [%0], [%1], 16, %2;"
                 :: "r"(dst), "l"(src), "r"(v ? 16 : 0));
}
__device__ __forceinline__ void split2(float v, __nv_bfloat16& h, __nv_bfloat16& l) {
    h = __float2bfloat16(v);
    l = __float2bfloat16(v - __bfloat162float(h));
}
__device__ __forceinline__ float ex2f(float x) {
    float r; asm("ex2.approx.ftz.f32 %0, %1;" : "=f"(r) : "f"(x)); return r;
}

#define TCSTR 40

// =================== GEMM: 128x128 CTA, 4 warps, warp tile 64x64 ===========
// 128 threads/CTA, 80KB smem (2-stage) -> 2 CTAs/SM. BK=32.
#define TILE_AH 0
#define TILE_AL 10240
#define TILE_BH 20480
#define TILE_BL 30720
#define STAGE_TOTAL 40960
#define TCG_SMEM (2*STAGE_TOTAL)

__device__ __forceinline__ void stage_load(
    uint32_t sb, const __nv_bfloat16* Ah, const __nv_bfloat16* Al,
    const __nv_bfloat16* Bh, const __nv_bfloat16* Bl,
    int M, int N, int K, int rowBase, int colBase, int k0, int tid) {
    const int r = tid;  // 0..127, one full 64B row each for A and B (hi+lo)
    {
        int gr = rowBase + r; bool av = gr < M; if (!av) gr = 0;
        const char* pa  = (const char*)(Ah + (size_t)gr * K + k0);
        const char* pal = (const char*)(Al + (size_t)gr * K + k0);
        uint32_t da  = sb + TILE_AH + r * 80;
        uint32_t dal = sb + TILE_AL + r * 80;
        #pragma unroll
        for (int j = 0; j < 4; j++) {
            cp16z(da + j * 16, pa + j * 16, av);
            cp16z(dal + j * 16, pal + j * 16, av);
        }
    }
    {
        int gc = colBase + r; bool bv = gc < N; if (!bv) gc = 0;
        const char* pb  = (const char*)(Bh + (size_t)gc * K + k0);
        const char* pbl = (const char*)(Bl + (size_t)gc * K + k0);
        uint32_t db  = sb + TILE_BH + r * 80;
        uint32_t dbl = sb + TILE_BL + r * 80;
        #pragma unroll
        for (int j = 0; j < 4; j++) {
            cp16z(db + j * 16, pb + j * 16, bv);
            cp16z(dbl + j * 16, pbl + j * 16, bv);
        }
    }
    asm volatile("cp.async.commit_group;" ::: "memory");
}

template<bool RELU, bool SPLITOUT>
__global__ __launch_bounds__(128, 2)
void tc_gemm(const __nv_bfloat16* __restrict__ Ah, const __nv_bfloat16* __restrict__ Al,
             const __nv_bfloat16* __restrict__ Bh, const __nv_bfloat16* __restrict__ Bl,
             const float* __restrict__ bias, float* __restrict__ Cf,
             __nv_bfloat16* __restrict__ Chi, __nv_bfloat16* __restrict__ Clo,
             int M, int N, int K) {
    extern __shared__ char smem[];
    const uint32_t sbase = smem_u32(smem);
    const int tid  = threadIdx.x;
    const int lane = tid & 31;
    const int wid  = tid >> 5;            // 0..3
    const int warpM = wid & 1;            // rows warpM*64
    const int warpN = wid >> 1;           // cols warpN*64
    const int rowBase = blockIdx.y * 128;
    const int colBase = blockIdx.x * 128;

    const int aRow = (lane & 15);
    const int aColOff = (lane >> 4) * 8;
    const int bRow = (lane & 7) + ((lane >> 4) & 1) * 8;
    const int bColOff = ((lane >> 3) & 1) * 8;

    float acc[4][8][4];
    #pragma unroll
    for (int mt = 0; mt < 4; mt++)
        #pragma unroll
        for (int nt = 0; nt < 8; nt++)
            #pragma unroll
            for (int i = 0; i < 4; i++) acc[mt][nt][i] = 0.f;

    const int KC = K >> 5;
    stage_load(sbase, Ah, Al, Bh, Bl, M, N, K, rowBase, colBase, 0, tid);

    for (int c = 0; c < KC; c++) {
        asm volatile("cp.async.wait_group 0;" ::: "memory");
        __syncthreads();
        if (c + 1 < KC)
            stage_load(sbase + ((c + 1) & 1) * STAGE_TOTAL, Ah, Al, Bh, Bl,
                       M, N, K, rowBase, colBase, (c + 1) << 5, tid);

        const uint32_t sb = sbase + (c & 1) * STAGE_TOTAL;
        #pragma unroll
        for (int ks = 0; ks < 32; ks += 16) {
            uint32_t ah[4][4], al[4][4];
            #pragma unroll
            for (int mt = 0; mt < 4; mt++) {
                const int r0 = warpM * 64 + mt * 16;
                uint32_t off = (uint32_t)((r0 + aRow) * TCSTR + ks + aColOff) * 2;
                ldmx4(sb + TILE_AH + off, ah[mt]);
                ldmx4(sb + TILE_AL + off, al[mt]);
            }
            #pragma unroll
            for (int nb = 0; nb < 4; nb++) {
                const int n0 = warpN * 64 + nb * 16;
                uint32_t off = (uint32_t)((n0 + bRow) * TCSTR + ks + bColOff) * 2;
                uint32_t bh[4], bl[4];
                ldmx4(sb + TILE_BH + off, bh);
                ldmx4(sb + TILE_BL + off, bl);
                #pragma unroll
                for (int mt = 0; mt < 4; mt++) {
                    #pragma unroll
                    for (int sub = 0; sub < 2; sub++) {
                        const int nt = nb * 2 + sub;
                        mma16816(acc[mt][nt], ah[mt], bh[sub*2], bh[sub*2+1]);
                        mma16816(acc[mt][nt], ah[mt], bl[sub*2], bl[sub*2+1]);
                        mma16816(acc[mt][nt], al[mt], bh[sub*2], bh[sub*2+1]);
                    }
                }
            }
        }
    }

    #pragma unroll
    for (int mt = 0; mt < 4; mt++) {
        #pragma unroll
        for (int half = 0; half < 2; half++) {
            const int row = rowBase + warpM * 64 + mt * 16 + (lane >> 2) + half * 8;
            if (row < M) {
                #pragma unroll
                for (int nt = 0; nt < 8; nt++) {
                    const int col = colBase + warpN * 64 + nt * 8 + (lane & 3) * 2;
                    float ox = acc[mt][nt][half*2+0] + bias[col];
                    float oy = acc[mt][nt][half*2+1] + bias[col+1];
                    if (RELU) { ox = fmaxf(ox, 0.f); oy = fmaxf(oy, 0.f); }
                    if (SPLITOUT) {
                        __nv_bfloat16 hx, lx, hy, ly;
                        split2(ox, hx, lx); split2(oy, hy, ly);
                        *(__nv_bfloat162*)(Chi + (size_t)row * N + col) = __nv_bfloat162(hx, hy);
                        *(__nv_bfloat162*)(Clo + (size_t)row * N + col) = __nv_bfloat162(lx, ly);
                    } else {
                        *(float2*)(Cf + (size_t)row * N + col) = make_float2(ox, oy);
                    }
                }
            }
        }
    }
}

// =================== tensor-core flash self-attention (R7, unchanged) ======
#define ATT_QH 0
#define ATT_QL 10240
#define ATT_KV(st) (20480 + (st)*20480)
#define ATT_KH_O 0
#define ATT_KL_O 5120
#define ATT_VH_O 10240
#define ATT_VL_O 15360
#define ATT_SMEM (20480 + 2*20480)
#define KSCALE 0.25503486f   /* log2(e)/sqrt(32) */

__global__ __launch_bounds__(256)
void attn_mma(const __nv_bfloat16* __restrict__ qkh, const __nv_bfloat16* __restrict__ qkl,
              const __nv_bfloat16* __restrict__ vph, const __nv_bfloat16* __restrict__ vpl,
              __nv_bfloat16* __restrict__ oh, __nv_bfloat16* __restrict__ ol) {
    extern __shared__ char smem[];
    const uint32_t sb = smem_u32(smem);
    const int tid = threadIdx.x;
    const int lane = tid & 31;
    const int w = tid >> 5;
    const int g = lane >> 2, t4 = lane & 3;
    const int qbase = blockIdx.x * 128;
    const int b = blockIdx.y >> 3, h = blockIdx.y & 7;

    {
        const int r = tid >> 1, cb = (tid & 1) * 32;
        const int gr = qbase + r;
        const bool v = gr < LQ;
        const size_t rowo = ((size_t)(b * LQ + (v ? gr : 0)) * 512 + h * 32) * 2;
        cp16z(sb + ATT_QH + r * 80 + cb,      (const char*)qkh + rowo + cb, v);
        cp16z(sb + ATT_QH + r * 80 + cb + 16, (const char*)qkh + rowo + cb + 16, v);
        cp16z(sb + ATT_QL + r * 80 + cb,      (const char*)qkl + rowo + cb, v);
        cp16z(sb + ATT_QL + r * 80 + cb + 16, (const char*)qkl + rowo + cb + 16, v);
    }
    {
        const int r = tid >> 2, j = tid & 3;
        const bool v = r < LQ;
        const size_t ko = ((size_t)(b * LQ + (v ? r : 0)) * 512 + 256 + h * 32) * 2 + j * 16;
        const size_t vo = ((size_t)(b * LQ + (v ? r : 0)) * 256 + h * 32) * 2 + j * 16;
        cp16z(sb + ATT_KV(0) + ATT_KH_O + r * 80 + j * 16, (const char*)qkh + ko, v);
        cp16z(sb + ATT_KV(0) + ATT_KL_O + r * 80 + j * 16, (const char*)qkl + ko, v);
        cp16z(sb + ATT_KV(0) + ATT_VH_O + r * 80 + j * 16, (const char*)vph + vo, v);
        cp16z(sb + ATT_KV(0) + ATT_VL_O + r * 80 + j * 16, (const char*)vpl + vo, v);
    }
    asm volatile("cp.async.commit_group;" ::: "memory");

    float m0 = -1e30f, m1 = -1e30f, l0 = 0.f, l1 = 0.f;
    float o[4][4];
    #pragma unroll
    for (int vt = 0; vt < 4; vt++)
        #pragma unroll
        for (int i = 0; i < 4; i++) o[vt][i] = 0.f;

    uint32_t qh[2][4], ql[2][4];
    const int bRow = (lane & 7) + ((lane >> 4) & 1) * 8;
    const int bColOff = ((lane >> 3) & 1) * 8;
    const int NT = (LQ + 63) / 64;

    for (int ti = 0; ti < NT; ti++) {
        asm volatile("cp.async.wait_group 0;" ::: "memory");
        __syncthreads();
        if (ti == 0) {
            #pragma unroll
            for (int kf = 0; kf < 2; kf++) {
                uint32_t off = (uint32_t)((w * 16 + (lane & 15)) * TCSTR + kf * 16 + (lane >> 4) * 8) * 2;
                ldmx4(sb + ATT_QH + off, qh[kf]);
                ldmx4(sb + ATT_QL + off, ql[kf]);
            }
        }
        if (ti + 1 < NT) {
            const int kt = (ti + 1) * 64;
            const int r = tid >> 2, j = tid & 3;
            const int kr = kt + r;
            const bool v = kr < LQ;
            const size_t ko = ((size_t)(b * LQ + (v ? kr : 0)) * 512 + 256 + h * 32) * 2 + j * 16;
            const size_t vo = ((size_t)(b * LQ + (v ? kr : 0)) * 256 + h * 32) * 2 + j * 16;
            const uint32_t st = sb + ATT_KV((ti + 1) & 1);
            cp16z(st + ATT_KH_O + r * 80 + j * 16, (const char*)qkh + ko, v);
            cp16z(st + ATT_KL_O + r * 80 + j * 16, (const char*)qkl + ko, v);
            cp16z(st + ATT_VH_O + r * 80 + j * 16, (const char*)vph + vo, v);
            cp16z(st + ATT_VL_O + r * 80 + j * 16, (const char*)vpl + vo, v);
            asm volatile("cp.async.commit_group;" ::: "memory");
        }

        const uint32_t stg = sb + ATT_KV(ti & 1);
        const int kt = ti * 64;

        float s[8][4];
        #pragma unroll
        for (int nt = 0; nt < 8; nt++)
            #pragma unroll
            for (int i = 0; i < 4; i++) s[nt][i] = 0.f;
        #pragma unroll
        for (int kf = 0; kf < 2; kf++) {
            #pragma unroll
            for (int nb = 0; nb < 4; nb++) {
                uint32_t off = (uint32_t)((nb * 16 + bRow) * TCSTR + kf * 16 + bColOff) * 2;
                uint32_t kh[4], kl[4];
                ldmx4(stg + ATT_KH_O + off, kh);
                ldmx4(stg + ATT_KL_O + off, kl);
                #pragma unroll
                for (int hf = 0; hf < 2; hf++) {
                    const int nt = nb * 2 + hf;
                    mma16816(s[nt], qh[kf], kh[hf*2], kh[hf*2+1]);
                    mma16816(s[nt], qh[kf], kl[hf*2], kl[hf*2+1]);
                    mma16816(s[nt], ql[kf], kh[hf*2], kh[hf*2+1]);
                }
            }
        }

        const int validTiles = min(8, (LQ - kt) >> 3);
        float tmax0 = -1e30f, tmax1 = -1e30f;
        #pragma unroll
        for (int nt = 0; nt < 8; nt++) {
            if (nt < validTiles) {
                s[nt][0] *= KSCALE; s[nt][1] *= KSCALE;
                s[nt][2] *= KSCALE; s[nt][3] *= KSCALE;
            } else {
                s[nt][0] = s[nt][1] = s[nt][2] = s[nt][3] = -1e30f;
            }
            tmax0 = fmaxf(tmax0, fmaxf(s[nt][0], s[nt][1]));
            tmax1 = fmaxf(tmax1, fmaxf(s[nt][2], s[nt][3]));
        }
        tmax0 = fmaxf(tmax0, __shfl_xor_sync(0xffffffffu, tmax0, 1));
        tmax0 = fmaxf(tmax0, __shfl_xor_sync(0xffffffffu, tmax0, 2));
        tmax1 = fmaxf(tmax1, __shfl_xor_sync(0xffffffffu, tmax1, 1));
        tmax1 = fmaxf(tmax1, __shfl_xor_sync(0xffffffffu, tmax1, 2));
        const float mn0 = fmaxf(m0, tmax0), mn1 = fmaxf(m1, tmax1);
        const float c0 = ex2f(m0 - mn0), c1 = ex2f(m1 - mn1);
        m0 = mn0; m1 = mn1;
        l0 *= c0; l1 *= c1;
        #pragma unroll
        for (int vt = 0; vt < 4; vt++) {
            o[vt][0] *= c0; o[vt][1] *= c0; o[vt][2] *= c1; o[vt][3] *= c1;
        }

        uint32_t ph[4][4], pl[4][4];
        #pragma unroll
        for (int nt = 0; nt < 8; nt++) {
            float p0 = ex2f(s[nt][0] - mn0), p1 = ex2f(s[nt][1] - mn0);
            float p2 = ex2f(s[nt][2] - mn1), p3 = ex2f(s[nt][3] - mn1);
            l0 += p0 + p1; l1 += p2 + p3;
            __nv_bfloat16 h0,lo0,h1,lo1,h2,lo2,h3,lo3;
            split2(p0,h0,lo0); split2(p1,h1,lo1); split2(p2,h2,lo2); split2(p3,h3,lo3);
            const int ks = nt >> 1, base = (nt & 1) * 2;
            __nv_bfloat162 ph01(h0,h1), ph23(h2,h3), pl01(lo0,lo1), pl23(lo2,lo3);
            ph[ks][base+0] = *(uint32_t*)&ph01;
            ph[ks][base+1] = *(uint32_t*)&ph23;
            pl[ks][base+0] = *(uint32_t*)&pl01;
            pl[ks][base+1] = *(uint32_t*)&pl23;
        }

        #pragma unroll
        for (int ks = 0; ks < 4; ks++) {
            const int krow = ks * 16 + (lane & 7) + ((lane >> 3) & 1) * 8;
            #pragma unroll
            for (int nh = 0; nh < 2; nh++) {
                uint32_t off = (uint32_t)(krow * TCSTR + nh * 16 + (lane >> 4) * 8) * 2;
                uint32_t vh[4], vl[4];
                ldmx4t(stg + ATT_VH_O + off, vh);
                ldmx4t(stg + ATT_VL_O + off, vl);
                #pragma unroll
                for (int sub = 0; sub < 2; sub++) {
                    const int vt = nh * 2 + sub;
                    mma16816(o[vt], ph[ks], vh[sub*2], vh[sub*2+1]);
                    mma16816(o[vt], ph[ks], vl[sub*2], vl[sub*2+1]);
                    mma16816(o[vt], pl[ks], vh[sub*2], vh[sub*2+1]);
                }
            }
        }
    }

    l0 += __shfl_xor_sync(0xffffffffu, l0, 1);
    l0 += __shfl_xor_sync(0xffffffffu, l0, 2);
    l1 += __shfl_xor_sync(0xffffffffu, l1, 1);
    l1 += __shfl_xor_sync(0xffffffffu, l1, 2);
    const float inv0 = 1.f / l0, inv1 = 1.f / l1;
    const int r0 = qbase + w * 16 + g;
    const int r1 = r0 + 8;
    #pragma unroll
    for (int half = 0; half < 2; half++) {
        const int row = half ? r1 : r0;
        const float inv = half ? inv1 : inv0;
        if (row < LQ) {
            const size_t base = ((size_t)(b * LQ + row)) * DM + h * DH;
            #pragma unroll
            for (int vt = 0; vt < 4; vt++) {
                float vx = o[vt][half*2+0] * inv;
                float vy = o[vt][half*2+1] * inv;
                __nv_bfloat16 hx,lx,hy,ly;
                split2(vx,hx,lx); split2(vy,hy,ly);
                const size_t idx = base + vt * 8 + t4 * 2;
                *(__nv_bfloat162*)(oh + idx) = __nv_bfloat162(hx,hy);
                *(__nv_bfloat162*)(ol + idx) = __nv_bfloat162(lx,ly);
            }
        }
    }
}

// ---------------- weight splitter + combined bias --------------------------
__global__ void split_weights(const float* __restrict__ w0, const float* __restrict__ w1,
                              const float* __restrict__ w2, const float* __restrict__ w3,
                              const float* __restrict__ w4, const float* __restrict__ w5,
                              const float* __restrict__ w6, const float* __restrict__ w7,
                              const float* __restrict__ off_b, const float* __restrict__ aw_b,
                              __nv_bfloat16* __restrict__ hi, __nv_bfloat16* __restrict__ lo,
                              float* __restrict__ cbias) {
    int i = blockIdx.x * blockDim.x + threadIdx.x;
    if (i < 384) cbias[i] = (i < 256) ? off_b[i] : aw_b[i - 256];
    if (i >= WTOT) return;
    const float* src; int local;
    if      (i < OFF_SAOUT) { src = w0; local = i; }
    else if (i < OFF_OFFW)  { src = w1; local = i - OFF_SAOUT; }
    else if (i < OFF_VALW)  { src = (i < 327680) ? w2 : w3; local = (i < 327680) ? i - OFF_OFFW : i - 327680; }
    else if (i < OFF_OUTPW) { src = w4; local = i - OFF_VALW; }
    else if (i < OFF_FFN1)  { src = w5; local = i - OFF_OUTPW; }
    else if (i < OFF_FFN2)  { src = w6; local = i - OFF_FFN1; }
    else                    { src = w7; local = i - OFF_FFN2; }
    __nv_bfloat16 h, l;
    split2(src[local], h, l);
    hi[i] = h; lo[i] = l;
}

// ---------------- add + split ----------------------------------------------
__global__ void add_split_kernel(const float* __restrict__ a, const float* __restrict__ b,
                                 __nv_bfloat16* __restrict__ qh, __nv_bfloat16* __restrict__ ql,
                                 __nv_bfloat16* __restrict__ th, __nv_bfloat16* __restrict__ tl,
                                 int n4) {
    int i = blockIdx.x * blockDim.x + threadIdx.x;
    if (i >= n4) return;
    float4 x = ((const float4*)a)[i];
    float4 y = ((const float4*)b)[i];
    float q0 = x.x + y.x, q1 = x.y + y.y, q2 = x.z + y.z, q3 = x.w + y.w;
    __nv_bfloat16 h0,l0,h1,l1,h2,l2,h3,l3;
    split2(q0,h0,l0); split2(q1,h1,l1); split2(q2,h2,l2); split2(q3,h3,l3);
    *(__nv_bfloat162*)(qh + i*4)     = __nv_bfloat162(h0,h1);
    *(__nv_bfloat162*)(qh + i*4 + 2) = __nv_bfloat162(h2,h3);
    *(__nv_bfloat162*)(ql + i*4)     = __nv_bfloat162(l0,l1);
    *(__nv_bfloat162*)(ql + i*4 + 2) = __nv_bfloat162(l2,l3);
    split2(x.x,h0,l0); split2(x.y,h1,l1); split2(x.z,h2,l2); split2(x.w,h3,l3);
    *(__nv_bfloat162*)(th + i*4)     = __nv_bfloat162(h0,h1);
    *(__nv_bfloat162*)(th + i*4 + 2) = __nv_bfloat162(h2,h3);
    *(__nv_bfloat162*)(tl + i*4)     = __nv_bfloat162(l0,l1);
    *(__nv_bfloat162*)(tl + i*4 + 2) = __nv_bfloat162(l2,l3);
}

// ---------------- generic fp32 -> hi/lo splitter ---------------------------
__global__ void split_kernel(const float* __restrict__ a,
                             __nv_bfloat16* __restrict__ hi, __nv_bfloat16* __restrict__ lo,
                             int n4) {
    int i = blockIdx.x * blockDim.x + threadIdx.x;
    if (i >= n4) return;
    float4 x = ((const float4*)a)[i];
    __nv_bfloat16 h0,l0,h1,l1,h2,l2,h3,l3;
    split2(x.x,h0,l0); split2(x.y,h1,l1); split2(x.z,h2,l2); split2(x.w,h3,l3);
    *(__nv_bfloat162*)(hi + i*4)     = __nv_bfloat162(h0,h1);
    *(__nv_bfloat162*)(hi + i*4 + 2) = __nv_bfloat162(h2,h3);
    *(__nv_bfloat162*)(lo + i*4)     = __nv_bfloat162(l0,l1);
    *(__nv_bfloat162*)(lo + i*4 + 2) = __nv_bfloat162(l2,l3);
}

// ---------------- LayerNorm(x+res) -----------------------------------------
__global__ __launch_bounds__(256)
void ln_kernel(const float* __restrict__ x, const float* __restrict__ res,
               const float* __restrict__ g, const float* __restrict__ bta,
               float* __restrict__ out,
               const float* __restrict__ pos,
               __nv_bfloat16* __restrict__ hi, __nv_bfloat16* __restrict__ lo) {
    __shared__ float red[8];
    const int row = blockIdx.x, t = threadIdx.x;
    const size_t idx = (size_t)row * DM + t;
    float v = x[idx] + res[idx];

    float s = v;
    #pragma unroll
    for (int o = 16; o; o >>= 1) s += __shfl_xor_sync(0xffffffffu, s, o);
    if ((t & 31) == 0) red[t >> 5] = s;
    __syncthreads();
    float mean = 0.f;
    #pragma unroll
    for (int i = 0; i < 8; i++) mean += red[i];
    mean *= (1.f / DM);
    __syncthreads();

    float d = v - mean;
    float s2 = d * d;
    #pragma unroll
    for (int o = 16; o; o >>= 1) s2 += __shfl_xor_sync(0xffffffffu, s2, o);
    if ((t & 31) == 0) red[t >> 5] = s2;
    __syncthreads();
    float var = 0.f;
    #pragma unroll
    for (int i = 0; i < 8; i++) var += red[i];
    var *= (1.f / DM);

    float o = d * rsqrtf(var + 1e-5f) * g[t] + bta[t];
    out[idx] = o;
    if (hi) {
        float tq = pos ? o + pos[idx] : o;
        __nv_bfloat16 hh, ll;
        split2(tq, hh, ll);
        hi[idx] = hh; lo[idx] = ll;
    }
}

// ---------------- attention-weight softmax ---------------------------------
__global__ void awsm_kernel(float* __restrict__ offaw) {
    int i = blockIdx.x * blockDim.x + threadIdx.x;
    if (i >= NQ * NH) return;
    float* p = offaw + (size_t)(i / NH) * 384 + 256 + (i % NH) * 16;
    float mx = -1e30f;
    #pragma unroll
    for (int j = 0; j < 16; j++) mx = fmaxf(mx, p[j]);
    float sm = 0.f, e[16];
    #pragma unroll
    for (int j = 0; j < 16; j++) { e[j] = __expf(p[j] - mx); sm += e[j]; }
    float inv = 1.f / sm;
    #pragma unroll
    for (int j = 0; j < 16; j++) p[j] = e[j] * inv;
}

// ---------------- MS-deformable sampling -----------------------------------
__global__ __launch_bounds__(256)
void deform_kernel(const float* __restrict__ value, const float* __restrict__ offaw,
                   const float* __restrict__ ref,
                   __nv_bfloat16* __restrict__ oh, __nv_bfloat16* __restrict__ ol) {
    const int qidx = blockIdx.x;
    const int b = qidx / LQ;
    const int h = threadIdx.y, d = threadIdx.x;

    const int starts[4] = {0, 16384, 20480, 21504};
    const int Wi[4]     = {128, 64, 32, 16};

    const float* vb = value + (size_t)b * LEN_IN * DM + h * DH + d;
    const size_t oq = (size_t)qidx;
    const float* offp = offaw + oq * 384;
    float acc = 0.f;

    #pragma unroll
    for (int lvl = 0; lvl < NLV; lvl++) {
        const float W = (float)Wi[lvl];
        const int   Wl = Wi[lvl];
        const int   st = starts[lvl];
        const float rx = ref[(oq * NLV + lvl) * 2 + 0];
        const float ry = ref[(oq * NLV + lvl) * 2 + 1];
        #pragma unroll
        for (int p = 0; p < NPT; p++) {
            const int oidx = ((h * NLV + lvl) * NPT + p) * 2;
            const float ox = offp[oidx + 0];
            const float oy = offp[oidx + 1];
            const float a  = offp[256 + h * 16 + lvl * 4 + p];
            const float x = (rx + ox / W) * W - 0.5f;
            const float y = (ry + oy / W) * W - 0.5f;
            const float x0f = floorf(x), y0f = floorf(y);
            const float lx = x - x0f, ly = y - y0f;
            const int x0 = (int)x0f, y0 = (int)y0f;

            const float w00 = (1.f - ly) * (1.f - lx);
            const float w01 = (1.f - ly) * lx;
            const float w10 = ly * (1.f - lx);
            const float w11 = ly * lx;

            const bool xv0 = (x0 >= 0) & (x0 < Wl);
            const bool xv1 = (x0 + 1 >= 0) & (x0 + 1 < Wl);
            const bool yv0 = (y0 >= 0) & (y0 < Wl);
            const bool yv1 = (y0 + 1 >= 0) & (y0 + 1 < Wl);

            if (yv0 & xv0) acc = fmaf(a * w00, vb[(size_t)(st + y0 * Wl + x0) * DM], acc);
            if (yv0 & xv1) acc = fmaf(a * w01, vb[(size_t)(st + y0 * Wl + x0 + 1) * DM], acc);
            if (yv1 & xv0) acc = fmaf(a * w10, vb[(size_t)(st + (y0 + 1) * Wl + x0) * DM], acc);
            if (yv1 & xv1) acc = fmaf(a * w11, vb[(size_t)(st + (y0 + 1) * Wl + x0 + 1) * DM], acc);
        }
    }
    __nv_bfloat16 hh, ll;
    split2(acc, hh, ll);
    oh[oq * DM + h * DH + d] = hh;
    ol[oq * DM + h * DH + d] = ll;
}

// ---------------- host-side orchestration ----------------------------------
enum GMode { GM_F32, GM_SPLIT, GM_RELU_SPLIT };
static inline void gemm_bf(const __nv_bfloat16* Ah, const __nv_bfloat16* Al,
                           const __nv_bfloat16* Bh, const __nv_bfloat16* Bl,
                           const float* bias, float* Cf,
                           __nv_bfloat16* Chi, __nv_bfloat16* Clo,
                           int M, int N, int K, GMode mode) {
    dim3 grid(N / 128, (M + 127) / 128);
    if (mode == GM_RELU_SPLIT)
        tc_gemm<true, true><<<grid, 128, TCG_SMEM>>>(Ah, Al, Bh, Bl, bias, Cf, Chi, Clo, M, N, K);
    else if (mode == GM_SPLIT)
        tc_gemm<false, true><<<grid, 128, TCG_SMEM>>>(Ah, Al, Bh, Bl, bias, Cf, Chi, Clo, M, N, K);
    else
        tc_gemm<false, false><<<grid, 128, TCG_SMEM>>>(Ah, Al, Bh, Bl, bias, Cf, Chi, Clo, M, N, K);
}

extern "C" void kernel_launch(void* const* d_in, const int* in_sizes, int n_in,
                              void* d_out, int out_size) {
    (void)in_sizes; (void)n_in; (void)out_size;
    const float* tgt       = (const float*)d_in[0];
    const float* query_pos = (const float*)d_in[1];
    const float* refpts    = (const float*)d_in[2];
    const float* src       = (const float*)d_in[3];
    const float* sa_in_b   = (const float*)d_in[7];
    const float* sa_out_b  = (const float*)d_in[9];
    const float* norm2_g   = (const float*)d_in[10];
    const float* norm2_b   = (const float*)d_in[11];
    const float* off_b     = (const float*)d_in[13];
    const float* aw_b      = (const float*)d_in[15];
    const float* val_b     = (const float*)d_in[17];
    const float* outp_b    = (const float*)d_in[19];
    const float* norm1_g   = (const float*)d_in[20];
    const float* norm1_b   = (const float*)d_in[21];
    const float* ffn_b1    = (const float*)d_in[23];
    const float* ffn_b2    = (const float*)d_in[25];
    const float* norm3_g   = (const float*)d_in[26];
    const float* norm3_b   = (const float*)d_in[27];
    float* out = (float*)d_out;

    cudaFuncSetAttribute(tc_gemm<false,false>, cudaFuncAttributeMaxDynamicSharedMemorySize, TCG_SMEM);
    cudaFuncSetAttribute(tc_gemm<false,true>,  cudaFuncAttributeMaxDynamicSharedMemorySize, TCG_SMEM);
    cudaFuncSetAttribute(tc_gemm<true,true>,   cudaFuncAttributeMaxDynamicSharedMemorySize, TCG_SMEM);
    cudaFuncSetAttribute(attn_mma, cudaFuncAttributeMaxDynamicSharedMemorySize, ATT_SMEM);

    void* p;
    #define SYMF(name) cudaGetSymbolAddress(&p, name); float* name##_p = (float*)p;
    #define SYMB(name) cudaGetSymbolAddress(&p, name); __nv_bfloat16* name##_p = (__nv_bfloat16*)p;
    SYMF(g_proj) SYMF(g_tgt2) SYMF(g_tgt3)
    SYMF(g_offaw) SYMF(g_value) SYMF(g_cbias)
    SYMB(g_qk_h) SYMB(g_qk_l) SYMB(g_tgt_h) SYMB(g_tgt_l)
    SYMB(g_qk2_h) SYMB(g_qk2_l) SYMB(g_v2_h) SYMB(g_v2_l)
    SYMB(g_att_h) SYMB(g_att_l) SYMB(g_query_h) SYMB(g_query_l)
    SYMB(g_tgt3_h) SYMB(g_tgt3_l) SYMB(g_ca_h) SYMB(g_ca_l)
    SYMB(g_ffn_h) SYMB(g_ffn_l) SYMB(g_src_h) SYMB(g_src_l)
    SYMB(g_wh) SYMB(g_wl)
    #undef SYMF
    #undef SYMB

    // 0) weight + input splits
    split_weights<<<(WTOT + 255)/256, 256>>>(
        (const float*)d_in[6], (const float*)d_in[8], (const float*)d_in[12],
        (const float*)d_in[14], (const float*)d_in[16], (const float*)d_in[18],
        (const float*)d_in[22], (const float*)d_in[24],
        off_b, aw_b, g_wh_p, g_wl_p, g_cbias_p);
    const int n4 = NQ * DM / 4;
    add_split_kernel<<<(n4 + 255)/256, 256>>>(tgt, query_pos, g_qk_h_p, g_qk_l_p,
                                              g_tgt_h_p, g_tgt_l_p, n4);
    const int ns4 = (int)((size_t)NSRC * DM / 4);
    split_kernel<<<(ns4 + 255)/256, 256>>>(src, g_src_h_p, g_src_l_p, ns4);

    // 1) self-attn
    gemm_bf(g_qk_h_p, g_qk_l_p, g_wh_p + OFF_SAIN, g_wl_p + OFF_SAIN, sa_in_b,
            0, g_qk2_h_p, g_qk2_l_p, NQ, 512, DM, GM_SPLIT);
    gemm_bf(g_tgt_h_p, g_tgt_l_p, g_wh_p + OFF_SAIN + 131072, g_wl_p + OFF_SAIN + 131072,
            sa_in_b + 2*DM, 0, g_v2_h_p, g_v2_l_p, NQ, DM, DM, GM_SPLIT);
    attn_mma<<<dim3(8, NB * NH), 256, ATT_SMEM>>>(g_qk2_h_p, g_qk2_l_p, g_v2_h_p, g_v2_l_p,
                                                  g_att_h_p, g_att_l_p);
    gemm_bf(g_att_h_p, g_att_l_p, g_wh_p + OFF_SAOUT, g_wl_p + OFF_SAOUT, sa_out_b,
            g_proj_p, 0, 0, NQ, DM, DM, GM_F32);
    ln_kernel<<<NQ, DM>>>(tgt, g_proj_p, norm2_g, norm2_b, g_tgt2_p, query_pos,
                          g_query_h_p, g_query_l_p);

    // 2) cross-attn
    gemm_bf(g_src_h_p, g_src_l_p, g_wh_p + OFF_VALW, g_wl_p + OFF_VALW, val_b,
            g_value_p, 0, 0, NSRC, DM, DM, GM_F32);
    gemm_bf(g_query_h_p, g_query_l_p, g_wh_p + OFF_OFFW, g_wl_p + OFF_OFFW, g_cbias_p,
            g_offaw_p, 0, 0, NQ, 384, DM, GM_F32);
    awsm_kernel<<<(NQ * NH + 255)/256, 256>>>(g_offaw_p);
    deform_kernel<<<NQ, dim3(32, 8)>>>(g_value_p, g_offaw_p, refpts, g_ca_h_p, g_ca_l_p);
    gemm_bf(g_ca_h_p, g_ca_l_p, g_wh_p + OFF_OUTPW, g_wl_p + OFF_OUTPW, outp_b,
            g_proj_p, 0, 0, NQ, DM, DM, GM_F32);
    ln_kernel<<<NQ, DM>>>(g_tgt2_p, g_proj_p, norm1_g, norm1_b, g_tgt3_p, nullptr,
                          g_tgt3_h_p, g_tgt3_l_p);

    // 3) FFN
    gemm_bf(g_tgt3_h_p, g_tgt3_l_p, g_wh_p + OFF_FFN1, g_wl_p + OFF_FFN1, ffn_b1,
            0, g_ffn_h_p, g_ffn_l_p, NQ, DFFN, DM, GM_RELU_SPLIT);
    gemm_bf(g_ffn_h_p, g_ffn_l_p, g_wh_p + OFF_FFN2, g_wl_p + OFF_FFN2, ffn_b2,
            g_proj_p, 0, 0, NQ, DM, DFFN, GM_F32);
    ln_kernel<<<NQ, DM>>>(g_tgt3_p, g_proj_p, norm3_g, norm3_b, out, nullptr, nullptr, nullptr);
}

// round 10
// speedup vs baseline: 1.3071x; 1.2461x over previous
#include <cuda_runtime.h>
#include <cuda_bf16.h>
#include <cuda_fp16.h>
#include <math.h>
#include <stdint.h>

#define NB    8
#define LQ    1000
#define DM    256
#define NH    8
#define DH    32
#define NLV   4
#define NPT   4
#define LEN_IN 21760
#define DFFN  1024
#define NQ    (NB*LQ)    /* 8000 */
#define NSRC  (NB*LEN_IN) /* 174080 */

// ---------------- fp32 scratch ---------------------------------------------
__device__ float g_proj[NQ*DM];
__device__ float g_tgt2[NQ*DM];
__device__ float g_tgt3[NQ*DM];
__device__ float g_offaw[NQ*384];
__device__ float g_value[(size_t)NSRC*DM];
__device__ float g_cbias[384];

// ---------------- bf16 hi/lo split scratch ---------------------------------
__device__ __nv_bfloat16 g_qk_h[NQ*DM],   g_qk_l[NQ*DM];
__device__ __nv_bfloat16 g_tgt_h[NQ*DM],  g_tgt_l[NQ*DM];
__device__ __nv_bfloat16 g_qk2_h[NQ*512], g_qk2_l[NQ*512];
__device__ __nv_bfloat16 g_v2_h[NQ*DM],   g_v2_l[NQ*DM];
__device__ __nv_bfloat16 g_att_h[NQ*DM],  g_att_l[NQ*DM];
__device__ __nv_bfloat16 g_query_h[NQ*DM],g_query_l[NQ*DM];
__device__ __nv_bfloat16 g_tgt3_h[NQ*DM], g_tgt3_l[NQ*DM];
__device__ __nv_bfloat16 g_ca_h[NQ*DM],   g_ca_l[NQ*DM];
__device__ __nv_bfloat16 g_ffn_h[NQ*DFFN],g_ffn_l[NQ*DFFN];

// ---------------- fp16 value-path scratch -----------------------------------
__device__ __half g_src16[(size_t)NSRC*DM];     // src hi only
__device__ __half g_vw16h[65536], g_vw16l[65536]; // val_w hi/lo

#define WTOT 1015808
#define OFF_SAIN  0
#define OFF_SAOUT 196608
#define OFF_OFFW  262144
#define OFF_VALW  360448
#define OFF_OUTPW 425984
#define OFF_FFN1  491520
#define OFF_FFN2  753664
__device__ __nv_bfloat16 g_wh[WTOT], g_wl[WTOT];

// =================== helpers ===============================================
__device__ __forceinline__ uint32_t smem_u32(const void* p) {
    uint32_t a;
    asm("{ .reg .u64 t; cvta.to.shared.u64 t, %1; cvt.u32.u64 %0, t; }" : "=r"(a) : "l"(p));
    return a;
}
__device__ __forceinline__ void ldmx4(uint32_t addr, uint32_t* r) {
    asm volatile("ldmatrix.sync.aligned.m8n8.x4.shared.b16 {%0,%1,%2,%3}, [%4];"
                 : "=r"(r[0]), "=r"(r[1]), "=r"(r[2]), "=r"(r[3]) : "r"(addr));
}
__device__ __forceinline__ void ldmx4t(uint32_t addr, uint32_t* r) {
    asm volatile("ldmatrix.sync.aligned.m8n8.x4.trans.shared.b16 {%0,%1,%2,%3}, [%4];"
                 : "=r"(r[0]), "=r"(r[1]), "=r"(r[2]), "=r"(r[3]) : "r"(addr));
}
__device__ __forceinline__ void mma16816(float* d, const uint32_t* a, uint32_t b0, uint32_t b1) {
    asm volatile("mma.sync.aligned.m16n8k16.row.col.f32.bf16.bf16.f32 "
                 "{%0,%1,%2,%3}, {%4,%5,%6,%7}, {%8,%9}, {%0,%1,%2,%3};"
                 : "+f"(d[0]), "+f"(d[1]), "+f"(d[2]), "+f"(d[3])
                 : "r"(a[0]), "r"(a[1]), "r"(a[2]), "r"(a[3]), "r"(b0), "r"(b1));
}
__device__ __forceinline__ void mma16816h(float* d, const uint32_t* a, uint32_t b0, uint32_t b1) {
    asm volatile("mma.sync.aligned.m16n8k16.row.col.f32.f16.f16.f32 "
                 "{%0,%1,%2,%3}, {%4,%5,%6,%7}, {%8,%9}, {%0,%1,%2,%3};"
                 : "+f"(d[0]), "+f"(d[1]), "+f"(d[2]), "+f"(d[3])
                 : "r"(a[0]), "r"(a[1]), "r"(a[2]), "r"(a[3]), "r"(b0), "r"(b1));
}
__device__ __forceinline__ void cp16z(uint32_t dst, const void* src, bool v) {
    asm volatile("cp.async.cg.shared.global [%0], [%1], 16, %2;"
                 :: "r"(dst), "l"(src), "r"(v ? 16 : 0));
}
__device__ __forceinline__ void split2(float v, __nv_bfloat16& h, __nv_bfloat16& l) {
    h = __float2bfloat16(v);
    l = __float2bfloat16(v - __bfloat162float(h));
}
__device__ __forceinline__ float ex2f(float x) {
    float r; asm("ex2.approx.ftz.f32 %0, %1;" : "=f"(r) : "f"(x)); return r;
}

#define TCSTR 40

// =================== bf16-split tensor GEMM (R7 config, verbatim) ==========
#define TILE_AH 0
#define TILE_AL 10240
#define TILE_BH 20480
#define TILE_BL 30720
#define STAGE_TOTAL 40960
#define TCG_SMEM (2*STAGE_TOTAL)

__device__ __forceinline__ void stage_load(
    uint32_t sb, const __nv_bfloat16* Ah, const __nv_bfloat16* Al,
    const __nv_bfloat16* Bh, const __nv_bfloat16* Bl,
    int M, int N, int K, int rowBase, int colBase, int k0, int ldR, int ldC) {
    int gr = rowBase + ldR; bool av = gr < M; if (!av) gr = 0;
    const char* pa  = (const char*)(Ah + (size_t)gr * K + k0) + ldC;
    const char* pal = (const char*)(Al + (size_t)gr * K + k0) + ldC;
    uint32_t da  = sb + TILE_AH + ldR * 80 + ldC;
    uint32_t dal = sb + TILE_AL + ldR * 80 + ldC;
    cp16z(da, pa, av);        cp16z(da + 16, pa + 16, av);
    cp16z(dal, pal, av);      cp16z(dal + 16, pal + 16, av);
    int gc = colBase + ldR; bool bv = gc < N; if (!bv) gc = 0;
    const char* pb  = (const char*)(Bh + (size_t)gc * K + k0) + ldC;
    const char* pbl = (const char*)(Bl + (size_t)gc * K + k0) + ldC;
    uint32_t db  = sb + TILE_BH + ldR * 80 + ldC;
    uint32_t dbl = sb + TILE_BL + ldR * 80 + ldC;
    cp16z(db, pb, bv);        cp16z(db + 16, pb + 16, bv);
    cp16z(dbl, pbl, bv);      cp16z(dbl + 16, pbl + 16, bv);
    asm volatile("cp.async.commit_group;" ::: "memory");
}

template<bool RELU, bool SPLITOUT>
__global__ __launch_bounds__(256)
void tc_gemm_bf(const __nv_bfloat16* __restrict__ Ah, const __nv_bfloat16* __restrict__ Al,
                const __nv_bfloat16* __restrict__ Bh, const __nv_bfloat16* __restrict__ Bl,
                const float* __restrict__ bias, float* __restrict__ Cf,
                __nv_bfloat16* __restrict__ Chi, __nv_bfloat16* __restrict__ Clo,
                int M, int N, int K) {
    extern __shared__ char smem[];
    const uint32_t sbase = smem_u32(smem);
    const int tid  = threadIdx.x;
    const int lane = tid & 31;
    const int wid  = tid >> 5;
    const int warpM = wid & 3;
    const int warpN = wid >> 2;
    const int rowBase = blockIdx.y * 128;
    const int colBase = blockIdx.x * 128;
    const int ldR = tid >> 1;
    const int ldC = (tid & 1) * 32;

    const int aRow = (lane & 15);
    const int aColOff = (lane >> 4) * 8;
    const int bRow = (lane & 7) + ((lane >> 4) & 1) * 8;
    const int bColOff = ((lane >> 3) & 1) * 8;

    float acc[2][8][4];
    #pragma unroll
    for (int mt = 0; mt < 2; mt++)
        #pragma unroll
        for (int nt = 0; nt < 8; nt++)
            #pragma unroll
            for (int i = 0; i < 4; i++) acc[mt][nt][i] = 0.f;

    const int KC = K >> 5;
    stage_load(sbase, Ah, Al, Bh, Bl, M, N, K, rowBase, colBase, 0, ldR, ldC);

    for (int c = 0; c < KC; c++) {
        asm volatile("cp.async.wait_group 0;" ::: "memory");
        __syncthreads();
        if (c + 1 < KC)
            stage_load(sbase + ((c + 1) & 1) * STAGE_TOTAL, Ah, Al, Bh, Bl,
                       M, N, K, rowBase, colBase, (c + 1) << 5, ldR, ldC);

        const uint32_t sb = sbase + (c & 1) * STAGE_TOTAL;
        #pragma unroll
        for (int ks = 0; ks < 32; ks += 16) {
            uint32_t ah[2][4], al[2][4];
            #pragma unroll
            for (int mt = 0; mt < 2; mt++) {
                const int r0 = warpM * 32 + mt * 16;
                uint32_t off = (uint32_t)((r0 + aRow) * TCSTR + ks + aColOff) * 2;
                ldmx4(sb + TILE_AH + off, ah[mt]);
                ldmx4(sb + TILE_AL + off, al[mt]);
            }
            uint32_t bh[4][4], bl[4][4];
            #pragma unroll
            for (int nb = 0; nb < 4; nb++) {
                const int n0 = warpN * 64 + nb * 16;
                uint32_t off = (uint32_t)((n0 + bRow) * TCSTR + ks + bColOff) * 2;
                ldmx4(sb + TILE_BH + off, bh[nb]);
                ldmx4(sb + TILE_BL + off, bl[nb]);
            }
            #pragma unroll
            for (int mt = 0; mt < 2; mt++) {
                #pragma unroll
                for (int nt = 0; nt < 8; nt++) {
                    const int nb = nt >> 1, hi = (nt & 1) * 2;
                    mma16816(acc[mt][nt], ah[mt], bh[nb][hi], bh[nb][hi+1]);
                    mma16816(acc[mt][nt], ah[mt], bl[nb][hi], bl[nb][hi+1]);
                    mma16816(acc[mt][nt], al[mt], bh[nb][hi], bh[nb][hi+1]);
                }
            }
        }
    }

    #pragma unroll
    for (int mt = 0; mt < 2; mt++) {
        #pragma unroll
        for (int half = 0; half < 2; half++) {
            const int row = rowBase + warpM * 32 + mt * 16 + (lane >> 2) + half * 8;
            if (row < M) {
                #pragma unroll
                for (int nt = 0; nt < 8; nt++) {
                    const int col = colBase + warpN * 64 + nt * 8 + (lane & 3) * 2;
                    float ox = acc[mt][nt][half*2+0] + bias[col];
                    float oy = acc[mt][nt][half*2+1] + bias[col+1];
                    if (RELU) { ox = fmaxf(ox, 0.f); oy = fmaxf(oy, 0.f); }
                    if (SPLITOUT) {
                        __nv_bfloat16 hx, lx, hy, ly;
                        split2(ox, hx, lx); split2(oy, hy, ly);
                        *(__nv_bfloat162*)(Chi + (size_t)row * N + col) = __nv_bfloat162(hx, hy);
                        *(__nv_bfloat162*)(Clo + (size_t)row * N + col) = __nv_bfloat162(lx, ly);
                    } else {
                        *(float2*)(Cf + (size_t)row * N + col) = make_float2(ox, oy);
                    }
                }
            }
        }
    }
}

// =================== fp16 2-term GEMM (value path) =========================
// C = Ah@Bh^T + Ah@Bl^T + bias.  Same 128x128/8-warp shape; stage = 30KB.
#define H2_A  0
#define H2_BH 10240
#define H2_BL 20480
#define H2_STAGE 30720
#define H2_SMEM (2*H2_STAGE)

__device__ __forceinline__ void stage_load_h2(
    uint32_t sb, const __half* A, const __half* Bh, const __half* Bl,
    int M, int N, int K, int rowBase, int colBase, int k0, int ldR, int ldC) {
    int gr = rowBase + ldR; bool av = gr < M; if (!av) gr = 0;
    const char* pa = (const char*)(A + (size_t)gr * K + k0) + ldC;
    uint32_t da = sb + H2_A + ldR * 80 + ldC;
    cp16z(da, pa, av);        cp16z(da + 16, pa + 16, av);
    int gc = colBase + ldR; bool bv = gc < N; if (!bv) gc = 0;
    const char* pb  = (const char*)(Bh + (size_t)gc * K + k0) + ldC;
    const char* pbl = (const char*)(Bl + (size_t)gc * K + k0) + ldC;
    uint32_t db  = sb + H2_BH + ldR * 80 + ldC;
    uint32_t dbl = sb + H2_BL + ldR * 80 + ldC;
    cp16z(db, pb, bv);        cp16z(db + 16, pb + 16, bv);
    cp16z(dbl, pbl, bv);      cp16z(dbl + 16, pbl + 16, bv);
    asm volatile("cp.async.commit_group;" ::: "memory");
}

__global__ __launch_bounds__(256)
void tc_gemm_h2(const __half* __restrict__ A, const __half* __restrict__ Bh,
                const __half* __restrict__ Bl, const float* __restrict__ bias,
                float* __restrict__ Cf, int M, int N, int K) {
    extern __shared__ char smem[];
    const uint32_t sbase = smem_u32(smem);
    const int tid  = threadIdx.x;
    const int lane = tid & 31;
    const int wid  = tid >> 5;
    const int warpM = wid & 3;
    const int warpN = wid >> 2;
    const int rowBase = blockIdx.y * 128;
    const int colBase = blockIdx.x * 128;
    const int ldR = tid >> 1;
    const int ldC = (tid & 1) * 32;

    const int aRow = (lane & 15);
    const int aColOff = (lane >> 4) * 8;
    const int bRow = (lane & 7) + ((lane >> 4) & 1) * 8;
    const int bColOff = ((lane >> 3) & 1) * 8;

    float acc[2][8][4];
    #pragma unroll
    for (int mt = 0; mt < 2; mt++)
        #pragma unroll
        for (int nt = 0; nt < 8; nt++)
            #pragma unroll
            for (int i = 0; i < 4; i++) acc[mt][nt][i] = 0.f;

    const int KC = K >> 5;
    stage_load_h2(sbase, A, Bh, Bl, M, N, K, rowBase, colBase, 0, ldR, ldC);

    for (int c = 0; c < KC; c++) {
        asm volatile("cp.async.wait_group 0;" ::: "memory");
        __syncthreads();
        if (c + 1 < KC)
            stage_load_h2(sbase + ((c + 1) & 1) * H2_STAGE, A, Bh, Bl,
                          M, N, K, rowBase, colBase, (c + 1) << 5, ldR, ldC);

        const uint32_t sb = sbase + (c & 1) * H2_STAGE;
        #pragma unroll
        for (int ks = 0; ks < 32; ks += 16) {
            uint32_t ah[2][4];
            #pragma unroll
            for (int mt = 0; mt < 2; mt++) {
                const int r0 = warpM * 32 + mt * 16;
                uint32_t off = (uint32_t)((r0 + aRow) * TCSTR + ks + aColOff) * 2;
                ldmx4(sb + H2_A + off, ah[mt]);
            }
            uint32_t bh[4][4], bl[4][4];
            #pragma unroll
            for (int nb = 0; nb < 4; nb++) {
                const int n0 = warpN * 64 + nb * 16;
                uint32_t off = (uint32_t)((n0 + bRow) * TCSTR + ks + bColOff) * 2;
                ldmx4(sb + H2_BH + off, bh[nb]);
                ldmx4(sb + H2_BL + off, bl[nb]);
            }
            #pragma unroll
            for (int mt = 0; mt < 2; mt++) {
                #pragma unroll
                for (int nt = 0; nt < 8; nt++) {
                    const int nb = nt >> 1, hi = (nt & 1) * 2;
                    mma16816h(acc[mt][nt], ah[mt], bh[nb][hi], bh[nb][hi+1]);
                    mma16816h(acc[mt][nt], ah[mt], bl[nb][hi], bl[nb][hi+1]);
                }
            }
        }
    }

    #pragma unroll
    for (int mt = 0; mt < 2; mt++) {
        #pragma unroll
        for (int half = 0; half < 2; half++) {
            const int row = rowBase + warpM * 32 + mt * 16 + (lane >> 2) + half * 8;
            if (row < M) {
                #pragma unroll
                for (int nt = 0; nt < 8; nt++) {
                    const int col = colBase + warpN * 64 + nt * 8 + (lane & 3) * 2;
                    float ox = acc[mt][nt][half*2+0] + bias[col];
                    float oy = acc[mt][nt][half*2+1] + bias[col+1];
                    *(float2*)(Cf + (size_t)row * N + col) = make_float2(ox, oy);
                }
            }
        }
    }
}

// =================== tensor-core flash self-attention (R7, verbatim) =======
#define ATT_QH 0
#define ATT_QL 10240
#define ATT_KV(st) (20480 + (st)*20480)
#define ATT_KH_O 0
#define ATT_KL_O 5120
#define ATT_VH_O 10240
#define ATT_VL_O 15360
#define ATT_SMEM (20480 + 2*20480)
#define KSCALE 0.25503486f   /* log2(e)/sqrt(32) */

__global__ __launch_bounds__(256)
void attn_mma(const __nv_bfloat16* __restrict__ qkh, const __nv_bfloat16* __restrict__ qkl,
              const __nv_bfloat16* __restrict__ vph, const __nv_bfloat16* __restrict__ vpl,
              __nv_bfloat16* __restrict__ oh, __nv_bfloat16* __restrict__ ol) {
    extern __shared__ char smem[];
    const uint32_t sb = smem_u32(smem);
    const int tid = threadIdx.x;
    const int lane = tid & 31;
    const int w = tid >> 5;
    const int g = lane >> 2, t4 = lane & 3;
    const int qbase = blockIdx.x * 128;
    const int b = blockIdx.y >> 3, h = blockIdx.y & 7;

    {
        const int r = tid >> 1, cb = (tid & 1) * 32;
        const int gr = qbase + r;
        const bool v = gr < LQ;
        const size_t rowo = ((size_t)(b * LQ + (v ? gr : 0)) * 512 + h * 32) * 2;
        cp16z(sb + ATT_QH + r * 80 + cb,      (const char*)qkh + rowo + cb, v);
        cp16z(sb + ATT_QH + r * 80 + cb + 16, (const char*)qkh + rowo + cb + 16, v);
        cp16z(sb + ATT_QL + r * 80 + cb,      (const char*)qkl + rowo + cb, v);
        cp16z(sb + ATT_QL + r * 80 + cb + 16, (const char*)qkl + rowo + cb + 16, v);
    }
    {
        const int r = tid >> 2, j = tid & 3;
        const bool v = r < LQ;
        const size_t ko = ((size_t)(b * LQ + (v ? r : 0)) * 512 + 256 + h * 32) * 2 + j * 16;
        const size_t vo = ((size_t)(b * LQ + (v ? r : 0)) * 256 + h * 32) * 2 + j * 16;
        cp16z(sb + ATT_KV(0) + ATT_KH_O + r * 80 + j * 16, (const char*)qkh + ko, v);
        cp16z(sb + ATT_KV(0) + ATT_KL_O + r * 80 + j * 16, (const char*)qkl + ko, v);
        cp16z(sb + ATT_KV(0) + ATT_VH_O + r * 80 + j * 16, (const char*)vph + vo, v);
        cp16z(sb + ATT_KV(0) + ATT_VL_O + r * 80 + j * 16, (const char*)vpl + vo, v);
    }
    asm volatile("cp.async.commit_group;" ::: "memory");

    float m0 = -1e30f, m1 = -1e30f, l0 = 0.f, l1 = 0.f;
    float o[4][4];
    #pragma unroll
    for (int vt = 0; vt < 4; vt++)
        #pragma unroll
        for (int i = 0; i < 4; i++) o[vt][i] = 0.f;

    uint32_t qh[2][4], ql[2][4];
    const int bRow = (lane & 7) + ((lane >> 4) & 1) * 8;
    const int bColOff = ((lane >> 3) & 1) * 8;
    const int NT = (LQ + 63) / 64;

    for (int ti = 0; ti < NT; ti++) {
        asm volatile("cp.async.wait_group 0;" ::: "memory");
        __syncthreads();
        if (ti == 0) {
            #pragma unroll
            for (int kf = 0; kf < 2; kf++) {
                uint32_t off = (uint32_t)((w * 16 + (lane & 15)) * TCSTR + kf * 16 + (lane >> 4) * 8) * 2;
                ldmx4(sb + ATT_QH + off, qh[kf]);
                ldmx4(sb + ATT_QL + off, ql[kf]);
            }
        }
        if (ti + 1 < NT) {
            const int kt = (ti + 1) * 64;
            const int r = tid >> 2, j = tid & 3;
            const int kr = kt + r;
            const bool v = kr < LQ;
            const size_t ko = ((size_t)(b * LQ + (v ? kr : 0)) * 512 + 256 + h * 32) * 2 + j * 16;
            const size_t vo = ((size_t)(b * LQ + (v ? kr : 0)) * 256 + h * 32) * 2 + j * 16;
            const uint32_t st = sb + ATT_KV((ti + 1) & 1);
            cp16z(st + ATT_KH_O + r * 80 + j * 16, (const char*)qkh + ko, v);
            cp16z(st + ATT_KL_O + r * 80 + j * 16, (const char*)qkl + ko, v);
            cp16z(st + ATT_VH_O + r * 80 + j * 16, (const char*)vph + vo, v);
            cp16z(st + ATT_VL_O + r * 80 + j * 16, (const char*)vpl + vo, v);
            asm volatile("cp.async.commit_group;" ::: "memory");
        }

        const uint32_t stg = sb + ATT_KV(ti & 1);
        const int kt = ti * 64;

        float s[8][4];
        #pragma unroll
        for (int nt = 0; nt < 8; nt++)
            #pragma unroll
            for (int i = 0; i < 4; i++) s[nt][i] = 0.f;
        #pragma unroll
        for (int kf = 0; kf < 2; kf++) {
            #pragma unroll
            for (int nb = 0; nb < 4; nb++) {
                uint32_t off = (uint32_t)((nb * 16 + bRow) * TCSTR + kf * 16 + bColOff) * 2;
                uint32_t kh[4], kl[4];
                ldmx4(stg + ATT_KH_O + off, kh);
                ldmx4(stg + ATT_KL_O + off, kl);
                #pragma unroll
                for (int hf = 0; hf < 2; hf++) {
                    const int nt = nb * 2 + hf;
                    mma16816(s[nt], qh[kf], kh[hf*2], kh[hf*2+1]);
                    mma16816(s[nt], qh[kf], kl[hf*2], kl[hf*2+1]);
                    mma16816(s[nt], ql[kf], kh[hf*2], kh[hf*2+1]);
                }
            }
        }

        const int validTiles = min(8, (LQ - kt) >> 3);
        float tmax0 = -1e30f, tmax1 = -1e30f;
        #pragma unroll
        for (int nt = 0; nt < 8; nt++) {
            if (nt < validTiles) {
                s[nt][0] *= KSCALE; s[nt][1] *= KSCALE;
                s[nt][2] *= KSCALE; s[nt][3] *= KSCALE;
            } else {
                s[nt][0] = s[nt][1] = s[nt][2] = s[nt][3] = -1e30f;
            }
            tmax0 = fmaxf(tmax0, fmaxf(s[nt][0], s[nt][1]));
            tmax1 = fmaxf(tmax1, fmaxf(s[nt][2], s[nt][3]));
        }
        tmax0 = fmaxf(tmax0, __shfl_xor_sync(0xffffffffu, tmax0, 1));
        tmax0 = fmaxf(tmax0, __shfl_xor_sync(0xffffffffu, tmax0, 2));
        tmax1 = fmaxf(tmax1, __shfl_xor_sync(0xffffffffu, tmax1, 1));
        tmax1 = fmaxf(tmax1, __shfl_xor_sync(0xffffffffu, tmax1, 2));
        const float mn0 = fmaxf(m0, tmax0), mn1 = fmaxf(m1, tmax1);
        const float c0 = ex2f(m0 - mn0), c1 = ex2f(m1 - mn1);
        m0 = mn0; m1 = mn1;
        l0 *= c0; l1 *= c1;
        #pragma unroll
        for (int vt = 0; vt < 4; vt++) {
            o[vt][0] *= c0; o[vt][1] *= c0; o[vt][2] *= c1; o[vt][3] *= c1;
        }

        uint32_t ph[4][4], pl[4][4];
        #pragma unroll
        for (int nt = 0; nt < 8; nt++) {
            float p0 = ex2f(s[nt][0] - mn0), p1 = ex2f(s[nt][1] - mn0);
            float p2 = ex2f(s[nt][2] - mn1), p3 = ex2f(s[nt][3] - mn1);
            l0 += p0 + p1; l1 += p2 + p3;
            __nv_bfloat16 h0,lo0,h1,lo1,h2,lo2,h3,lo3;
            split2(p0,h0,lo0); split2(p1,h1,lo1); split2(p2,h2,lo2); split2(p3,h3,lo3);
            const int ks = nt >> 1, base = (nt & 1) * 2;
            __nv_bfloat162 ph01(h0,h1), ph23(h2,h3), pl01(lo0,lo1), pl23(lo2,lo3);
            ph[ks][base+0] = *(uint32_t*)&ph01;
            ph[ks][base+1] = *(uint32_t*)&ph23;
            pl[ks][base+0] = *(uint32_t*)&pl01;
            pl[ks][base+1] = *(uint32_t*)&pl23;
        }

        #pragma unroll
        for (int ks = 0; ks < 4; ks++) {
            const int krow = ks * 16 + (lane & 7) + ((lane >> 3) & 1) * 8;
            #pragma unroll
            for (int nh = 0; nh < 2; nh++) {
                uint32_t off = (uint32_t)(krow * TCSTR + nh * 16 + (lane >> 4) * 8) * 2;
                uint32_t vh[4], vl[4];
                ldmx4t(stg + ATT_VH_O + off, vh);
                ldmx4t(stg + ATT_VL_O + off, vl);
                #pragma unroll
                for (int sub = 0; sub < 2; sub++) {
                    const int vt = nh * 2 + sub;
                    mma16816(o[vt], ph[ks], vh[sub*2], vh[sub*2+1]);
                    mma16816(o[vt], ph[ks], vl[sub*2], vl[sub*2+1]);
                    mma16816(o[vt], pl[ks], vh[sub*2], vh[sub*2+1]);
                }
            }
        }
    }

    l0 += __shfl_xor_sync(0xffffffffu, l0, 1);
    l0 += __shfl_xor_sync(0xffffffffu, l0, 2);
    l1 += __shfl_xor_sync(0xffffffffu, l1, 1);
    l1 += __shfl_xor_sync(0xffffffffu, l1, 2);
    const float inv0 = 1.f / l0, inv1 = 1.f / l1;
    const int r0 = qbase + w * 16 + g;
    const int r1 = r0 + 8;
    #pragma unroll
    for (int half = 0; half < 2; half++) {
        const int row = half ? r1 : r0;
        const float inv = half ? inv1 : inv0;
        if (row < LQ) {
            const size_t base = ((size_t)(b * LQ + row)) * DM + h * DH;
            #pragma unroll
            for (int vt = 0; vt < 4; vt++) {
                float vx = o[vt][half*2+0] * inv;
                float vy = o[vt][half*2+1] * inv;
                __nv_bfloat16 hx,lx,hy,ly;
                split2(vx,hx,lx); split2(vy,hy,ly);
                const size_t idx = base + vt * 8 + t4 * 2;
                *(__nv_bfloat162*)(oh + idx) = __nv_bfloat162(hx,hy);
                *(__nv_bfloat162*)(ol + idx) = __nv_bfloat162(lx,ly);
            }
        }
    }
}

// ---------------- weight splitter + combined bias + fp16 val_w -------------
__global__ void split_weights(const float* __restrict__ w0, const float* __restrict__ w1,
                              const float* __restrict__ w2, const float* __restrict__ w3,
                              const float* __restrict__ w4, const float* __restrict__ w5,
                              const float* __restrict__ w6, const float* __restrict__ w7,
                              const float* __restrict__ off_b, const float* __restrict__ aw_b,
                              __nv_bfloat16* __restrict__ hi, __nv_bfloat16* __restrict__ lo,
                              float* __restrict__ cbias,
                              __half* __restrict__ vwh, __half* __restrict__ vwl) {
    int i = blockIdx.x * blockDim.x + threadIdx.x;
    if (i < 384) cbias[i] = (i < 256) ? off_b[i] : aw_b[i - 256];
    if (i >= WTOT) return;
    const float* src; int local;
    if      (i < OFF_SAOUT) { src = w0; local = i; }
    else if (i < OFF_OFFW)  { src = w1; local = i - OFF_SAOUT; }
    else if (i < OFF_VALW)  { src = (i < 327680) ? w2 : w3; local = (i < 327680) ? i - OFF_OFFW : i - 327680; }
    else if (i < OFF_OUTPW) { src = w4; local = i - OFF_VALW; }
    else if (i < OFF_FFN1)  { src = w5; local = i - OFF_OUTPW; }
    else if (i < OFF_FFN2)  { src = w6; local = i - OFF_FFN1; }
    else                    { src = w7; local = i - OFF_FFN2; }
    float v = src[local];
    __nv_bfloat16 h, l;
    split2(v, h, l);
    hi[i] = h; lo[i] = l;
    if (i >= OFF_VALW && i < OFF_OUTPW) {
        __half hh = __float2half(v);
        __half hl = __float2half(v - __half2float(hh));
        vwh[i - OFF_VALW] = hh;
        vwl[i - OFF_VALW] = hl;
    }
}

// ---------------- add + split ----------------------------------------------
__global__ void add_split_kernel(const float* __restrict__ a, const float* __restrict__ b,
                                 __nv_bfloat16* __restrict__ qh, __nv_bfloat16* __restrict__ ql,
                                 __nv_bfloat16* __restrict__ th, __nv_bfloat16* __restrict__ tl,
                                 int n4) {
    int i = blockIdx.x * blockDim.x + threadIdx.x;
    if (i >= n4) return;
    float4 x = ((const float4*)a)[i];
    float4 y = ((const float4*)b)[i];
    float q0 = x.x + y.x, q1 = x.y + y.y, q2 = x.z + y.z, q3 = x.w + y.w;
    __nv_bfloat16 h0,l0,h1,l1,h2,l2,h3,l3;
    split2(q0,h0,l0); split2(q1,h1,l1); split2(q2,h2,l2); split2(q3,h3,l3);
    *(__nv_bfloat162*)(qh + i*4)     = __nv_bfloat162(h0,h1);
    *(__nv_bfloat162*)(qh + i*4 + 2) = __nv_bfloat162(h2,h3);
    *(__nv_bfloat162*)(ql + i*4)     = __nv_bfloat162(l0,l1);
    *(__nv_bfloat162*)(ql + i*4 + 2) = __nv_bfloat162(l2,l3);
    split2(x.x,h0,l0); split2(x.y,h1,l1); split2(x.z,h2,l2); split2(x.w,h3,l3);
    *(__nv_bfloat162*)(th + i*4)     = __nv_bfloat162(h0,h1);
    *(__nv_bfloat162*)(th + i*4 + 2) = __nv_bfloat162(h2,h3);
    *(__nv_bfloat162*)(tl + i*4)     = __nv_bfloat162(l0,l1);
    *(__nv_bfloat162*)(tl + i*4 + 2) = __nv_bfloat162(l2,l3);
}

// ---------------- fp32 -> fp16 converter (src) ------------------------------
__global__ void cvt_f16_kernel(const float* __restrict__ a, __half* __restrict__ o, int n4) {
    int i = blockIdx.x * blockDim.x + threadIdx.x;
    if (i >= n4) return;
    float4 x = ((const float4*)a)[i];
    __half2 p0(__float2half(x.x), __float2half(x.y));
    __half2 p1(__float2half(x.z), __float2half(x.w));
    *(__half2*)(o + i*4)     = p0;
    *(__half2*)(o + i*4 + 2) = p1;
}

// ---------------- LayerNorm(x+res) -----------------------------------------
__global__ __launch_bounds__(256)
void ln_kernel(const float* __restrict__ x, const float* __restrict__ res,
               const float* __restrict__ g, const float* __restrict__ bta,
               float* __restrict__ out,
               const float* __restrict__ pos,
               __nv_bfloat16* __restrict__ hi, __nv_bfloat16* __restrict__ lo) {
    __shared__ float red[8];
    const int row = blockIdx.x, t = threadIdx.x;
    const size_t idx = (size_t)row * DM + t;
    float v = x[idx] + res[idx];

    float s = v;
    #pragma unroll
    for (int o = 16; o; o >>= 1) s += __shfl_xor_sync(0xffffffffu, s, o);
    if ((t & 31) == 0) red[t >> 5] = s;
    __syncthreads();
    float mean = 0.f;
    #pragma unroll
    for (int i = 0; i < 8; i++) mean += red[i];
    mean *= (1.f / DM);
    __syncthreads();

    float d = v - mean;
    float s2 = d * d;
    #pragma unroll
    for (int o = 16; o; o >>= 1) s2 += __shfl_xor_sync(0xffffffffu, s2, o);
    if ((t & 31) == 0) red[t >> 5] = s2;
    __syncthreads();
    float var = 0.f;
    #pragma unroll
    for (int i = 0; i < 8; i++) var += red[i];
    var *= (1.f / DM);

    float o = d * rsqrtf(var + 1e-5f) * g[t] + bta[t];
    out[idx] = o;
    if (hi) {
        float tq = pos ? o + pos[idx] : o;
        __nv_bfloat16 hh, ll;
        split2(tq, hh, ll);
        hi[idx] = hh; lo[idx] = ll;
    }
}

// ---------------- attention-weight softmax ---------------------------------
__global__ void awsm_kernel(float* __restrict__ offaw) {
    int i = blockIdx.x * blockDim.x + threadIdx.x;
    if (i >= NQ * NH) return;
    float* p = offaw + (size_t)(i / NH) * 384 + 256 + (i % NH) * 16;
    float mx = -1e30f;
    #pragma unroll
    for (int j = 0; j < 16; j++) mx = fmaxf(mx, p[j]);
    float sm = 0.f, e[16];
    #pragma unroll
    for (int j = 0; j < 16; j++) { e[j] = __expf(p[j] - mx); sm += e[j]; }
    float inv = 1.f / sm;
    #pragma unroll
    for (int j = 0; j < 16; j++) p[j] = e[j] * inv;
}

// ---------------- MS-deformable sampling -----------------------------------
__global__ __launch_bounds__(256)
void deform_kernel(const float* __restrict__ value, const float* __restrict__ offaw,
                   const float* __restrict__ ref,
                   __nv_bfloat16* __restrict__ oh, __nv_bfloat16* __restrict__ ol) {
    const int qidx = blockIdx.x;
    const int b = qidx / LQ;
    const int h = threadIdx.y, d = threadIdx.x;

    const int starts[4] = {0, 16384, 20480, 21504};
    const int Wi[4]     = {128, 64, 32, 16};

    const float* vb = value + (size_t)b * LEN_IN * DM + h * DH + d;
    const size_t oq = (size_t)qidx;
    const float* offp = offaw + oq * 384;
    float acc = 0.f;

    #pragma unroll
    for (int lvl = 0; lvl < NLV; lvl++) {
        const float W = (float)Wi[lvl];
        const int   Wl = Wi[lvl];
        const int   st = starts[lvl];
        const float rx = ref[(oq * NLV + lvl) * 2 + 0];
        const float ry = ref[(oq * NLV + lvl) * 2 + 1];
        #pragma unroll
        for (int p = 0; p < NPT; p++) {
            const int oidx = ((h * NLV + lvl) * NPT + p) * 2;
            const float ox = offp[oidx + 0];
            const float oy = offp[oidx + 1];
            const float a  = offp[256 + h * 16 + lvl * 4 + p];
            const float x = (rx + ox / W) * W - 0.5f;
            const float y = (ry + oy / W) * W - 0.5f;
            const float x0f = floorf(x), y0f = floorf(y);
            const float lx = x - x0f, ly = y - y0f;
            const int x0 = (int)x0f, y0 = (int)y0f;

            const float w00 = (1.f - ly) * (1.f - lx);
            const float w01 = (1.f - ly) * lx;
            const float w10 = ly * (1.f - lx);
            const float w11 = ly * lx;

            const bool xv0 = (x0 >= 0) & (x0 < Wl);
            const bool xv1 = (x0 + 1 >= 0) & (x0 + 1 < Wl);
            const bool yv0 = (y0 >= 0) & (y0 < Wl);
            const bool yv1 = (y0 + 1 >= 0) & (y0 + 1 < Wl);

            if (yv0 & xv0) acc = fmaf(a * w00, vb[(size_t)(st + y0 * Wl + x0) * DM], acc);
            if (yv0 & xv1) acc = fmaf(a * w01, vb[(size_t)(st + y0 * Wl + x0 + 1) * DM], acc);
            if (yv1 & xv0) acc = fmaf(a * w10, vb[(size_t)(st + (y0 + 1) * Wl + x0) * DM], acc);
            if (yv1 & xv1) acc = fmaf(a * w11, vb[(size_t)(st + (y0 + 1) * Wl + x0 + 1) * DM], acc);
        }
    }
    __nv_bfloat16 hh, ll;
    split2(acc, hh, ll);
    oh[oq * DM + h * DH + d] = hh;
    ol[oq * DM + h * DH + d] = ll;
}

// ---------------- host-side orchestration ----------------------------------
enum GMode { GM_F32, GM_SPLIT, GM_RELU_SPLIT };
static inline void gemm_bf(const __nv_bfloat16* Ah, const __nv_bfloat16* Al,
                           const __nv_bfloat16* Bh, const __nv_bfloat16* Bl,
                           const float* bias, float* Cf,
                           __nv_bfloat16* Chi, __nv_bfloat16* Clo,
                           int M, int N, int K, GMode mode) {
    dim3 grid(N / 128, (M + 127) / 128);
    if (mode == GM_RELU_SPLIT)
        tc_gemm_bf<true, true><<<grid, 256, TCG_SMEM>>>(Ah, Al, Bh, Bl, bias, Cf, Chi, Clo, M, N, K);
    else if (mode == GM_SPLIT)
        tc_gemm_bf<false, true><<<grid, 256, TCG_SMEM>>>(Ah, Al, Bh, Bl, bias, Cf, Chi, Clo, M, N, K);
    else
        tc_gemm_bf<false, false><<<grid, 256, TCG_SMEM>>>(Ah, Al, Bh, Bl, bias, Cf, Chi, Clo, M, N, K);
}

extern "C" void kernel_launch(void* const* d_in, const int* in_sizes, int n_in,
                              void* d_out, int out_size) {
    (void)in_sizes; (void)n_in; (void)out_size;
    const float* tgt       = (const float*)d_in[0];
    const float* query_pos = (const float*)d_in[1];
    const float* refpts    = (const float*)d_in[2];
    const float* src       = (const float*)d_in[3];
    const float* sa_in_b   = (const float*)d_in[7];
    const float* sa_out_b  = (const float*)d_in[9];
    const float* norm2_g   = (const float*)d_in[10];
    const float* norm2_b   = (const float*)d_in[11];
    const float* off_b     = (const float*)d_in[13];
    const float* aw_b      = (const float*)d_in[15];
    const float* val_b     = (const float*)d_in[17];
    const float* outp_b    = (const float*)d_in[19];
    const float* norm1_g   = (const float*)d_in[20];
    const float* norm1_b   = (const float*)d_in[21];
    const float* ffn_b1    = (const float*)d_in[23];
    const float* ffn_b2    = (const float*)d_in[25];
    const float* norm3_g   = (const float*)d_in[26];
    const float* norm3_b   = (const float*)d_in[27];
    float* out = (float*)d_out;

    cudaFuncSetAttribute(tc_gemm_bf<false,false>, cudaFuncAttributeMaxDynamicSharedMemorySize, TCG_SMEM);
    cudaFuncSetAttribute(tc_gemm_bf<false,true>,  cudaFuncAttributeMaxDynamicSharedMemorySize, TCG_SMEM);
    cudaFuncSetAttribute(tc_gemm_bf<true,true>,   cudaFuncAttributeMaxDynamicSharedMemorySize, TCG_SMEM);
    cudaFuncSetAttribute(tc_gemm_h2, cudaFuncAttributeMaxDynamicSharedMemorySize, H2_SMEM);
    cudaFuncSetAttribute(attn_mma, cudaFuncAttributeMaxDynamicSharedMemorySize, ATT_SMEM);

    void* p;
    #define SYMF(name) cudaGetSymbolAddress(&p, name); float* name##_p = (float*)p;
    #define SYMB(name) cudaGetSymbolAddress(&p, name); __nv_bfloat16* name##_p = (__nv_bfloat16*)p;
    #define SYMH(name) cudaGetSymbolAddress(&p, name); __half* name##_p = (__half*)p;
    SYMF(g_proj) SYMF(g_tgt2) SYMF(g_tgt3)
    SYMF(g_offaw) SYMF(g_value) SYMF(g_cbias)
    SYMB(g_qk_h) SYMB(g_qk_l) SYMB(g_tgt_h) SYMB(g_tgt_l)
    SYMB(g_qk2_h) SYMB(g_qk2_l) SYMB(g_v2_h) SYMB(g_v2_l)
    SYMB(g_att_h) SYMB(g_att_l) SYMB(g_query_h) SYMB(g_query_l)
    SYMB(g_tgt3_h) SYMB(g_tgt3_l) SYMB(g_ca_h) SYMB(g_ca_l)
    SYMB(g_ffn_h) SYMB(g_ffn_l)
    SYMB(g_wh) SYMB(g_wl)
    SYMH(g_src16) SYMH(g_vw16h) SYMH(g_vw16l)
    #undef SYMF
    #undef SYMB
    #undef SYMH

    // 0) weight + input splits
    split_weights<<<(WTOT + 255)/256, 256>>>(
        (const float*)d_in[6], (const float*)d_in[8], (const float*)d_in[12],
        (const float*)d_in[14], (const float*)d_in[16], (const float*)d_in[18],
        (const float*)d_in[22], (const float*)d_in[24],
        off_b, aw_b, g_wh_p, g_wl_p, g_cbias_p, g_vw16h_p, g_vw16l_p);
    const int n4 = NQ * DM / 4;
    add_split_kernel<<<(n4 + 255)/256, 256>>>(tgt, query_pos, g_qk_h_p, g_qk_l_p,
                                              g_tgt_h_p, g_tgt_l_p, n4);
    const int ns4 = (int)((size_t)NSRC * DM / 4);
    cvt_f16_kernel<<<(ns4 + 255)/256, 256>>>(src, g_src16_p, ns4);

    // 1) self-attn
    gemm_bf(g_qk_h_p, g_qk_l_p, g_wh_p + OFF_SAIN, g_wl_p + OFF_SAIN, sa_in_b,
            0, g_qk2_h_p, g_qk2_l_p, NQ, 512, DM, GM_SPLIT);
    gemm_bf(g_tgt_h_p, g_tgt_l_p, g_wh_p + OFF_SAIN + 131072, g_wl_p + OFF_SAIN + 131072,
            sa_in_b + 2*DM, 0, g_v2_h_p, g_v2_l_p, NQ, DM, DM, GM_SPLIT);
    attn_mma<<<dim3(8, NB * NH), 256, ATT_SMEM>>>(g_qk2_h_p, g_qk2_l_p, g_v2_h_p, g_v2_l_p,
                                                  g_att_h_p, g_att_l_p);
    gemm_bf(g_att_h_p, g_att_l_p, g_wh_p + OFF_SAOUT, g_wl_p + OFF_SAOUT, sa_out_b,
            g_proj_p, 0, 0, NQ, DM, DM, GM_F32);
    ln_kernel<<<NQ, DM>>>(tgt, g_proj_p, norm2_g, norm2_b, g_tgt2_p, query_pos,
                          g_query_h_p, g_query_l_p);

    // 2) cross-attn — value GEMM on fp16 2-term path
    {
        dim3 grid(DM / 128, (NSRC + 127) / 128);
        tc_gemm_h2<<<grid, 256, H2_SMEM>>>(g_src16_p, g_vw16h_p, g_vw16l_p, val_b,
                                           g_value_p, NSRC, DM, DM);
    }
    gemm_bf(g_query_h_p, g_query_l_p, g_wh_p + OFF_OFFW, g_wl_p + OFF_OFFW, g_cbias_p,
            g_offaw_p, 0, 0, NQ, 384, DM, GM_F32);
    awsm_kernel<<<(NQ * NH + 255)/256, 256>>>(g_offaw_p);
    deform_kernel<<<NQ, dim3(32, 8)>>>(g_value_p, g_offaw_p, refpts, g_ca_h_p, g_ca_l_p);
    gemm_bf(g_ca_h_p, g_ca_l_p, g_wh_p + OFF_OUTPW, g_wl_p + OFF_OUTPW, outp_b,
            g_proj_p, 0, 0, NQ, DM, DM, GM_F32);
    ln_kernel<<<NQ, DM>>>(g_tgt2_p, g_proj_p, norm1_g, norm1_b, g_tgt3_p, nullptr,
                          g_tgt3_h_p, g_tgt3_l_p);

    // 3) FFN
    gemm_bf(g_tgt3_h_p, g_tgt3_l_p, g_wh_p + OFF_FFN1, g_wl_p + OFF_FFN1, ffn_b1,
            0, g_ffn_h_p, g_ffn_l_p, NQ, DFFN, DM, GM_RELU_SPLIT);
    gemm_bf(g_ffn_h_p, g_ffn_l_p, g_wh_p + OFF_FFN2, g_wl_p + OFF_FFN2, ffn_b2,
            g_proj_p, 0, 0, NQ, DM, DFFN, GM_F32);
    ln_kernel<<<NQ, DM>>>(g_tgt3_p, g_proj_p, norm3_g, norm3_b, out, nullptr, nullptr, nullptr);
}

// round 11
// speedup vs baseline: 1.5188x; 1.1620x over previous
#include <cuda_runtime.h>
#include <cuda_fp16.h>
#include <math.h>
#include <stdint.h>

#define NB    8
#define LQ    1000
#define DM    256
#define NH    8
#define DH    32
#define NLV   4
#define NPT   4
#define LEN_IN 21760
#define DFFN  1024
#define NQ    (NB*LQ)    /* 8000 */
#define NSRC  (NB*LEN_IN) /* 174080 */

// ---------------- fp32 scratch ---------------------------------------------
__device__ float g_proj[NQ*DM];
__device__ float g_tgt2[NQ*DM];
__device__ float g_tgt3[NQ*DM];
__device__ float g_offaw[NQ*384];
__device__ float g_value[(size_t)NSRC*DM];
__device__ float g_cbias[384];

// ---------------- fp16 scratch ----------------------------------------------
__device__ __half g_qk16[NQ*DM];        // tgt+pos (A side)
__device__ __half g_tgt16[NQ*DM];       // tgt (A side)
__device__ __half g_qk2_h[NQ*512], g_qk2_l[NQ*512];   // q|k proj (K needs hi/lo)
__device__ __half g_v2_h[NQ*DM],   g_v2_l[NQ*DM];     // v proj (hi/lo)
__device__ __half g_att16[NQ*DM];       // attention out (A side)
__device__ __half g_query16[NQ*DM];     // tgt2+pos (A side)
__device__ __half g_tgt3_16[NQ*DM];     // tgt3 (A side)
__device__ __half g_ca16[NQ*DM];        // deform out (A side)
__device__ __half g_ffn16[NQ*DFFN];     // ffn hidden (A side)
__device__ __half g_src16[(size_t)NSRC*DM];

#define WTOT 1015808
#define OFF_SAIN  0
#define OFF_SAOUT 196608
#define OFF_OFFW  262144
#define OFF_VALW  360448
#define OFF_OUTPW 425984
#define OFF_FFN1  491520
#define OFF_FFN2  753664
__device__ __half g_w16h[WTOT], g_w16l[WTOT];

// =================== helpers ===============================================
__device__ __forceinline__ uint32_t smem_u32(const void* p) {
    uint32_t a;
    asm("{ .reg .u64 t; cvta.to.shared.u64 t, %1; cvt.u32.u64 %0, t; }" : "=r"(a) : "l"(p));
    return a;
}
__device__ __forceinline__ void ldmx4(uint32_t addr, uint32_t* r) {
    asm volatile("ldmatrix.sync.aligned.m8n8.x4.shared.b16 {%0,%1,%2,%3}, [%4];"
                 : "=r"(r[0]), "=r"(r[1]), "=r"(r[2]), "=r"(r[3]) : "r"(addr));
}
__device__ __forceinline__ void ldmx4t(uint32_t addr, uint32_t* r) {
    asm volatile("ldmatrix.sync.aligned.m8n8.x4.trans.shared.b16 {%0,%1,%2,%3}, [%4];"
                 : "=r"(r[0]), "=r"(r[1]), "=r"(r[2]), "=r"(r[3]) : "r"(addr));
}
__device__ __forceinline__ void mmah(float* d, const uint32_t* a, uint32_t b0, uint32_t b1) {
    asm volatile("mma.sync.aligned.m16n8k16.row.col.f32.f16.f16.f32 "
                 "{%0,%1,%2,%3}, {%4,%5,%6,%7}, {%8,%9}, {%0,%1,%2,%3};"
                 : "+f"(d[0]), "+f"(d[1]), "+f"(d[2]), "+f"(d[3])
                 : "r"(a[0]), "r"(a[1]), "r"(a[2]), "r"(a[3]), "r"(b0), "r"(b1));
}
__device__ __forceinline__ void cp16z(uint32_t dst, const void* src, bool v) {
    asm volatile("cp.async.cg.shared.global [%0], [%1], 16, %2;"
                 :: "r"(dst), "l"(src), "r"(v ? 16 : 0));
}
__device__ __forceinline__ void hsplit(float v, __half& h, __half& l) {
    h = __float2half(v);
    l = __float2half(v - __half2float(h));
}
__device__ __forceinline__ float ex2f(float x) {
    float r; asm("ex2.approx.ftz.f32 %0, %1;" : "=f"(r) : "f"(x)); return r;
}

#define TCSTR 40

// =================== fp16 2-term GEMM ======================================
// C[M,N] = A@Bh^T + A@Bl^T + bias. 128x128, 8 warps (32x64), 2-stage.
// OUT: 0 = fp32, 1 = fp16 single (opt RELU), 2 = fp16 hi/lo.
#define H2_A  0
#define H2_BH 10240
#define H2_BL 20480
#define H2_STAGE 30720
#define H2_SMEM (2*H2_STAGE)

__device__ __forceinline__ void stage_load_h2(
    uint32_t sb, const __half* A, const __half* Bh, const __half* Bl,
    int M, int N, int K, int rowBase, int colBase, int k0, int ldR, int ldC) {
    int gr = rowBase + ldR; bool av = gr < M; if (!av) gr = 0;
    const char* pa = (const char*)(A + (size_t)gr * K + k0) + ldC;
    uint32_t da = sb + H2_A + ldR * 80 + ldC;
    cp16z(da, pa, av);        cp16z(da + 16, pa + 16, av);
    int gc = colBase + ldR; bool bv = gc < N; if (!bv) gc = 0;
    const char* pb  = (const char*)(Bh + (size_t)gc * K + k0) + ldC;
    const char* pbl = (const char*)(Bl + (size_t)gc * K + k0) + ldC;
    uint32_t db  = sb + H2_BH + ldR * 80 + ldC;
    uint32_t dbl = sb + H2_BL + ldR * 80 + ldC;
    cp16z(db, pb, bv);        cp16z(db + 16, pb + 16, bv);
    cp16z(dbl, pbl, bv);      cp16z(dbl + 16, pbl + 16, bv);
    asm volatile("cp.async.commit_group;" ::: "memory");
}

template<bool RELU, int OUT>
__global__ __launch_bounds__(256)
void tc_gemm(const __half* __restrict__ A, const __half* __restrict__ Bh,
             const __half* __restrict__ Bl, const float* __restrict__ bias,
             float* __restrict__ Cf, __half* __restrict__ C16,
             __half* __restrict__ C16l, int M, int N, int K) {
    extern __shared__ char smem[];
    const uint32_t sbase = smem_u32(smem);
    const int tid  = threadIdx.x;
    const int lane = tid & 31;
    const int wid  = tid >> 5;
    const int warpM = wid & 3;
    const int warpN = wid >> 2;
    const int rowBase = blockIdx.y * 128;
    const int colBase = blockIdx.x * 128;
    const int ldR = tid >> 1;
    const int ldC = (tid & 1) * 32;

    const int aRow = (lane & 15);
    const int aColOff = (lane >> 4) * 8;
    const int bRow = (lane & 7) + ((lane >> 4) & 1) * 8;
    const int bColOff = ((lane >> 3) & 1) * 8;

    float acc[2][8][4];
    #pragma unroll
    for (int mt = 0; mt < 2; mt++)
        #pragma unroll
        for (int nt = 0; nt < 8; nt++)
            #pragma unroll
            for (int i = 0; i < 4; i++) acc[mt][nt][i] = 0.f;

    const int KC = K >> 5;
    stage_load_h2(sbase, A, Bh, Bl, M, N, K, rowBase, colBase, 0, ldR, ldC);

    for (int c = 0; c < KC; c++) {
        asm volatile("cp.async.wait_group 0;" ::: "memory");
        __syncthreads();
        if (c + 1 < KC)
            stage_load_h2(sbase + ((c + 1) & 1) * H2_STAGE, A, Bh, Bl,
                          M, N, K, rowBase, colBase, (c + 1) << 5, ldR, ldC);

        const uint32_t sb = sbase + (c & 1) * H2_STAGE;
        #pragma unroll
        for (int ks = 0; ks < 32; ks += 16) {
            uint32_t ah[2][4];
            #pragma unroll
            for (int mt = 0; mt < 2; mt++) {
                const int r0 = warpM * 32 + mt * 16;
                uint32_t off = (uint32_t)((r0 + aRow) * TCSTR + ks + aColOff) * 2;
                ldmx4(sb + H2_A + off, ah[mt]);
            }
            uint32_t bh[4][4], bl[4][4];
            #pragma unroll
            for (int nb = 0; nb < 4; nb++) {
                const int n0 = warpN * 64 + nb * 16;
                uint32_t off = (uint32_t)((n0 + bRow) * TCSTR + ks + bColOff) * 2;
                ldmx4(sb + H2_BH + off, bh[nb]);
                ldmx4(sb + H2_BL + off, bl[nb]);
            }
            #pragma unroll
            for (int mt = 0; mt < 2; mt++) {
                #pragma unroll
                for (int nt = 0; nt < 8; nt++) {
                    const int nb = nt >> 1, hi = (nt & 1) * 2;
                    mmah(acc[mt][nt], ah[mt], bh[nb][hi], bh[nb][hi+1]);
                    mmah(acc[mt][nt], ah[mt], bl[nb][hi], bl[nb][hi+1]);
                }
            }
        }
    }

    #pragma unroll
    for (int mt = 0; mt < 2; mt++) {
        #pragma unroll
        for (int half = 0; half < 2; half++) {
            const int row = rowBase + warpM * 32 + mt * 16 + (lane >> 2) + half * 8;
            if (row < M) {
                #pragma unroll
                for (int nt = 0; nt < 8; nt++) {
                    const int col = colBase + warpN * 64 + nt * 8 + (lane & 3) * 2;
                    float ox = acc[mt][nt][half*2+0] + bias[col];
                    float oy = acc[mt][nt][half*2+1] + bias[col+1];
                    if (RELU) { ox = fmaxf(ox, 0.f); oy = fmaxf(oy, 0.f); }
                    if (OUT == 0) {
                        *(float2*)(Cf + (size_t)row * N + col) = make_float2(ox, oy);
                    } else if (OUT == 1) {
                        *(__half2*)(C16 + (size_t)row * N + col) =
                            __half2(__float2half(ox), __float2half(oy));
                    } else {
                        __half hx, lx, hy, ly;
                        hsplit(ox, hx, lx); hsplit(oy, hy, ly);
                        *(__half2*)(C16 + (size_t)row * N + col)  = __half2(hx, hy);
                        *(__half2*)(C16l + (size_t)row * N + col) = __half2(lx, ly);
                    }
                }
            }
        }
    }
}

// =================== fp16 tensor-core flash self-attention =================
// S = Qh@(Kh+Kl)^T (2-term), online softmax, O += Ph@(Vh+Vl) (2-term).
#define ATT_QH 0
#define ATT_KV(st) (10240 + (st)*20480)
#define ATT_KH_O 0
#define ATT_KL_O 5120
#define ATT_VH_O 10240
#define ATT_VL_O 15360
#define ATT_SMEM (10240 + 2*20480)
#define KSCALE 0.25503486f   /* log2(e)/sqrt(32) */

__global__ __launch_bounds__(256)
void attn_mma(const __half* __restrict__ qkh, const __half* __restrict__ qkl,
              const __half* __restrict__ vph, const __half* __restrict__ vpl,
              __half* __restrict__ oh) {
    extern __shared__ char smem[];
    const uint32_t sb = smem_u32(smem);
    const int tid = threadIdx.x;
    const int lane = tid & 31;
    const int w = tid >> 5;
    const int g = lane >> 2, t4 = lane & 3;
    const int qbase = blockIdx.x * 128;
    const int b = blockIdx.y >> 3, h = blockIdx.y & 7;

    {   // Q hi only
        const int r = tid >> 1, cb = (tid & 1) * 32;
        const int gr = qbase + r;
        const bool v = gr < LQ;
        const size_t rowo = ((size_t)(b * LQ + (v ? gr : 0)) * 512 + h * 32) * 2;
        cp16z(sb + ATT_QH + r * 80 + cb,      (const char*)qkh + rowo + cb, v);
        cp16z(sb + ATT_QH + r * 80 + cb + 16, (const char*)qkh + rowo + cb + 16, v);
    }
    {
        const int r = tid >> 2, j = tid & 3;
        const bool v = r < LQ;
        const size_t ko = ((size_t)(b * LQ + (v ? r : 0)) * 512 + 256 + h * 32) * 2 + j * 16;
        const size_t vo = ((size_t)(b * LQ + (v ? r : 0)) * 256 + h * 32) * 2 + j * 16;
        cp16z(sb + ATT_KV(0) + ATT_KH_O + r * 80 + j * 16, (const char*)qkh + ko, v);
        cp16z(sb + ATT_KV(0) + ATT_KL_O + r * 80 + j * 16, (const char*)qkl + ko, v);
        cp16z(sb + ATT_KV(0) + ATT_VH_O + r * 80 + j * 16, (const char*)vph + vo, v);
        cp16z(sb + ATT_KV(0) + ATT_VL_O + r * 80 + j * 16, (const char*)vpl + vo, v);
    }
    asm volatile("cp.async.commit_group;" ::: "memory");

    float m0 = -1e30f, m1 = -1e30f, l0 = 0.f, l1 = 0.f;
    float o[4][4];
    #pragma unroll
    for (int vt = 0; vt < 4; vt++)
        #pragma unroll
        for (int i = 0; i < 4; i++) o[vt][i] = 0.f;

    uint32_t qh[2][4];
    const int bRow = (lane & 7) + ((lane >> 4) & 1) * 8;
    const int bColOff = ((lane >> 3) & 1) * 8;
    const int NT = (LQ + 63) / 64;

    for (int ti = 0; ti < NT; ti++) {
        asm volatile("cp.async.wait_group 0;" ::: "memory");
        __syncthreads();
        if (ti == 0) {
            #pragma unroll
            for (int kf = 0; kf < 2; kf++) {
                uint32_t off = (uint32_t)((w * 16 + (lane & 15)) * TCSTR + kf * 16 + (lane >> 4) * 8) * 2;
                ldmx4(sb + ATT_QH + off, qh[kf]);
            }
        }
        if (ti + 1 < NT) {
            const int kt = (ti + 1) * 64;
            const int r = tid >> 2, j = tid & 3;
            const int kr = kt + r;
            const bool v = kr < LQ;
            const size_t ko = ((size_t)(b * LQ + (v ? kr : 0)) * 512 + 256 + h * 32) * 2 + j * 16;
            const size_t vo = ((size_t)(b * LQ + (v ? kr : 0)) * 256 + h * 32) * 2 + j * 16;
            const uint32_t st = sb + ATT_KV((ti + 1) & 1);
            cp16z(st + ATT_KH_O + r * 80 + j * 16, (const char*)qkh + ko, v);
            cp16z(st + ATT_KL_O + r * 80 + j * 16, (const char*)qkl + ko, v);
            cp16z(st + ATT_VH_O + r * 80 + j * 16, (const char*)vph + vo, v);
            cp16z(st + ATT_VL_O + r * 80 + j * 16, (const char*)vpl + vo, v);
            asm volatile("cp.async.commit_group;" ::: "memory");
        }

        const uint32_t stg = sb + ATT_KV(ti & 1);
        const int kt = ti * 64;

        float s[8][4];
        #pragma unroll
        for (int nt = 0; nt < 8; nt++)
            #pragma unroll
            for (int i = 0; i < 4; i++) s[nt][i] = 0.f;
        #pragma unroll
        for (int kf = 0; kf < 2; kf++) {
            #pragma unroll
            for (int nb = 0; nb < 4; nb++) {
                uint32_t off = (uint32_t)((nb * 16 + bRow) * TCSTR + kf * 16 + bColOff) * 2;
                uint32_t kh[4], kl[4];
                ldmx4(stg + ATT_KH_O + off, kh);
                ldmx4(stg + ATT_KL_O + off, kl);
                #pragma unroll
                for (int hf = 0; hf < 2; hf++) {
                    const int nt = nb * 2 + hf;
                    mmah(s[nt], qh[kf], kh[hf*2], kh[hf*2+1]);
                    mmah(s[nt], qh[kf], kl[hf*2], kl[hf*2+1]);
                }
            }
        }

        const int validTiles = min(8, (LQ - kt) >> 3);
        float tmax0 = -1e30f, tmax1 = -1e30f;
        #pragma unroll
        for (int nt = 0; nt < 8; nt++) {
            if (nt < validTiles) {
                s[nt][0] *= KSCALE; s[nt][1] *= KSCALE;
                s[nt][2] *= KSCALE; s[nt][3] *= KSCALE;
            } else {
                s[nt][0] = s[nt][1] = s[nt][2] = s[nt][3] = -1e30f;
            }
            tmax0 = fmaxf(tmax0, fmaxf(s[nt][0], s[nt][1]));
            tmax1 = fmaxf(tmax1, fmaxf(s[nt][2], s[nt][3]));
        }
        tmax0 = fmaxf(tmax0, __shfl_xor_sync(0xffffffffu, tmax0, 1));
        tmax0 = fmaxf(tmax0, __shfl_xor_sync(0xffffffffu, tmax0, 2));
        tmax1 = fmaxf(tmax1, __shfl_xor_sync(0xffffffffu, tmax1, 1));
        tmax1 = fmaxf(tmax1, __shfl_xor_sync(0xffffffffu, tmax1, 2));
        const float mn0 = fmaxf(m0, tmax0), mn1 = fmaxf(m1, tmax1);
        const float c0 = ex2f(m0 - mn0), c1 = ex2f(m1 - mn1);
        m0 = mn0; m1 = mn1;
        l0 *= c0; l1 *= c1;
        #pragma unroll
        for (int vt = 0; vt < 4; vt++) {
            o[vt][0] *= c0; o[vt][1] *= c0; o[vt][2] *= c1; o[vt][3] *= c1;
        }

        uint32_t ph[4][4];
        #pragma unroll
        for (int nt = 0; nt < 8; nt++) {
            float p0 = ex2f(s[nt][0] - mn0), p1 = ex2f(s[nt][1] - mn0);
            float p2 = ex2f(s[nt][2] - mn1), p3 = ex2f(s[nt][3] - mn1);
            l0 += p0 + p1; l1 += p2 + p3;
            const int ks = nt >> 1, base = (nt & 1) * 2;
            __half2 p01(__float2half(p0), __float2half(p1));
            __half2 p23(__float2half(p2), __float2half(p3));
            ph[ks][base+0] = *(uint32_t*)&p01;
            ph[ks][base+1] = *(uint32_t*)&p23;
        }

        #pragma unroll
        for (int ks = 0; ks < 4; ks++) {
            const int krow = ks * 16 + (lane & 7) + ((lane >> 3) & 1) * 8;
            #pragma unroll
            for (int nh = 0; nh < 2; nh++) {
                uint32_t off = (uint32_t)(krow * TCSTR + nh * 16 + (lane >> 4) * 8) * 2;
                uint32_t vh[4], vl[4];
                ldmx4t(stg + ATT_VH_O + off, vh);
                ldmx4t(stg + ATT_VL_O + off, vl);
                #pragma unroll
                for (int sub = 0; sub < 2; sub++) {
                    const int vt = nh * 2 + sub;
                    mmah(o[vt], ph[ks], vh[sub*2], vh[sub*2+1]);
                    mmah(o[vt], ph[ks], vl[sub*2], vl[sub*2+1]);
                }
            }
        }
    }

    l0 += __shfl_xor_sync(0xffffffffu, l0, 1);
    l0 += __shfl_xor_sync(0xffffffffu, l0, 2);
    l1 += __shfl_xor_sync(0xffffffffu, l1, 1);
    l1 += __shfl_xor_sync(0xffffffffu, l1, 2);
    const float inv0 = 1.f / l0, inv1 = 1.f / l1;
    const int r0 = qbase + w * 16 + g;
    const int r1 = r0 + 8;
    #pragma unroll
    for (int half = 0; half < 2; half++) {
        const int row = half ? r1 : r0;
        const float inv = half ? inv1 : inv0;
        if (row < LQ) {
            const size_t base = ((size_t)(b * LQ + row)) * DM + h * DH;
            #pragma unroll
            for (int vt = 0; vt < 4; vt++) {
                float vx = o[vt][half*2+0] * inv;
                float vy = o[vt][half*2+1] * inv;
                *(__half2*)(oh + base + vt * 8 + t4 * 2) =
                    __half2(__float2half(vx), __float2half(vy));
            }
        }
    }
}

// ---------------- weight splitter (fp16 hi/lo) + combined bias -------------
__global__ void split_weights(const float* __restrict__ w0, const float* __restrict__ w1,
                              const float* __restrict__ w2, const float* __restrict__ w3,
                              const float* __restrict__ w4, const float* __restrict__ w5,
                              const float* __restrict__ w6, const float* __restrict__ w7,
                              const float* __restrict__ off_b, const float* __restrict__ aw_b,
                              __half* __restrict__ hi, __half* __restrict__ lo,
                              float* __restrict__ cbias) {
    int i = blockIdx.x * blockDim.x + threadIdx.x;
    if (i < 384) cbias[i] = (i < 256) ? off_b[i] : aw_b[i - 256];
    if (i >= WTOT) return;
    const float* src; int local;
    if      (i < OFF_SAOUT) { src = w0; local = i; }
    else if (i < OFF_OFFW)  { src = w1; local = i - OFF_SAOUT; }
    else if (i < OFF_VALW)  { src = (i < 327680) ? w2 : w3; local = (i < 327680) ? i - OFF_OFFW : i - 327680; }
    else if (i < OFF_OUTPW) { src = w4; local = i - OFF_VALW; }
    else if (i < OFF_FFN1)  { src = w5; local = i - OFF_OUTPW; }
    else if (i < OFF_FFN2)  { src = w6; local = i - OFF_FFN1; }
    else                    { src = w7; local = i - OFF_FFN2; }
    __half h, l;
    hsplit(src[local], h, l);
    hi[i] = h; lo[i] = l;
}

// ---------------- add + fp16 convert (qk = tgt+pos, tgt) -------------------
__global__ void add_cvt_kernel(const float* __restrict__ a, const float* __restrict__ b,
                               __half* __restrict__ q16, __half* __restrict__ t16, int n4) {
    int i = blockIdx.x * blockDim.x + threadIdx.x;
    if (i >= n4) return;
    float4 x = ((const float4*)a)[i];
    float4 y = ((const float4*)b)[i];
    *(__half2*)(q16 + i*4)     = __half2(__float2half(x.x + y.x), __float2half(x.y + y.y));
    *(__half2*)(q16 + i*4 + 2) = __half2(__float2half(x.z + y.z), __float2half(x.w + y.w));
    *(__half2*)(t16 + i*4)     = __half2(__float2half(x.x), __float2half(x.y));
    *(__half2*)(t16 + i*4 + 2) = __half2(__float2half(x.z), __float2half(x.w));
}

// ---------------- fp32 -> fp16 converter ------------------------------------
__global__ void cvt_f16_kernel(const float* __restrict__ a, __half* __restrict__ o, int n4) {
    int i = blockIdx.x * blockDim.x + threadIdx.x;
    if (i >= n4) return;
    float4 x = ((const float4*)a)[i];
    *(__half2*)(o + i*4)     = __half2(__float2half(x.x), __float2half(x.y));
    *(__half2*)(o + i*4 + 2) = __half2(__float2half(x.z), __float2half(x.w));
}

// ---------------- LayerNorm(x+res) -> fp32 (+ optional fp16 of out+pos) ----
__global__ __launch_bounds__(256)
void ln_kernel(const float* __restrict__ x, const float* __restrict__ res,
               const float* __restrict__ g, const float* __restrict__ bta,
               float* __restrict__ out,
               const float* __restrict__ pos, __half* __restrict__ o16) {
    __shared__ float red[8];
    const int row = blockIdx.x, t = threadIdx.x;
    const size_t idx = (size_t)row * DM + t;
    float v = x[idx] + res[idx];

    float s = v;
    #pragma unroll
    for (int o = 16; o; o >>= 1) s += __shfl_xor_sync(0xffffffffu, s, o);
    if ((t & 31) == 0) red[t >> 5] = s;
    __syncthreads();
    float mean = 0.f;
    #pragma unroll
    for (int i = 0; i < 8; i++) mean += red[i];
    mean *= (1.f / DM);
    __syncthreads();

    float d = v - mean;
    float s2 = d * d;
    #pragma unroll
    for (int o = 16; o; o >>= 1) s2 += __shfl_xor_sync(0xffffffffu, s2, o);
    if ((t & 31) == 0) red[t >> 5] = s2;
    __syncthreads();
    float var = 0.f;
    #pragma unroll
    for (int i = 0; i < 8; i++) var += red[i];
    var *= (1.f / DM);

    float o = d * rsqrtf(var + 1e-5f) * g[t] + bta[t];
    out[idx] = o;
    if (o16) {
        float tq = pos ? o + pos[idx] : o;
        o16[idx] = __float2half(tq);
    }
}

// ---------------- attention-weight softmax ---------------------------------
__global__ void awsm_kernel(float* __restrict__ offaw) {
    int i = blockIdx.x * blockDim.x + threadIdx.x;
    if (i >= NQ * NH) return;
    float* p = offaw + (size_t)(i / NH) * 384 + 256 + (i % NH) * 16;
    float mx = -1e30f;
    #pragma unroll
    for (int j = 0; j < 16; j++) mx = fmaxf(mx, p[j]);
    float sm = 0.f, e[16];
    #pragma unroll
    for (int j = 0; j < 16; j++) { e[j] = __expf(p[j] - mx); sm += e[j]; }
    float inv = 1.f / sm;
    #pragma unroll
    for (int j = 0; j < 16; j++) p[j] = e[j] * inv;
}

// ---------------- MS-deformable sampling (fp16 single out) -----------------
__global__ __launch_bounds__(256)
void deform_kernel(const float* __restrict__ value, const float* __restrict__ offaw,
                   const float* __restrict__ ref, __half* __restrict__ o16) {
    const int qidx = blockIdx.x;
    const int b = qidx / LQ;
    const int h = threadIdx.y, d = threadIdx.x;

    const int starts[4] = {0, 16384, 20480, 21504};
    const int Wi[4]     = {128, 64, 32, 16};

    const float* vb = value + (size_t)b * LEN_IN * DM + h * DH + d;
    const size_t oq = (size_t)qidx;
    const float* offp = offaw + oq * 384;
    float acc = 0.f;

    #pragma unroll
    for (int lvl = 0; lvl < NLV; lvl++) {
        const float W = (float)Wi[lvl];
        const int   Wl = Wi[lvl];
        const int   st = starts[lvl];
        const float rx = ref[(oq * NLV + lvl) * 2 + 0];
        const float ry = ref[(oq * NLV + lvl) * 2 + 1];
        #pragma unroll
        for (int p = 0; p < NPT; p++) {
            const int oidx = ((h * NLV + lvl) * NPT + p) * 2;
            const float ox = offp[oidx + 0];
            const float oy = offp[oidx + 1];
            const float a  = offp[256 + h * 16 + lvl * 4 + p];
            const float x = (rx + ox / W) * W - 0.5f;
            const float y = (ry + oy / W) * W - 0.5f;
            const float x0f = floorf(x), y0f = floorf(y);
            const float lx = x - x0f, ly = y - y0f;
            const int x0 = (int)x0f, y0 = (int)y0f;

            const float w00 = (1.f - ly) * (1.f - lx);
            const float w01 = (1.f - ly) * lx;
            const float w10 = ly * (1.f - lx);
            const float w11 = ly * lx;

            const bool xv0 = (x0 >= 0) & (x0 < Wl);
            const bool xv1 = (x0 + 1 >= 0) & (x0 + 1 < Wl);
            const bool yv0 = (y0 >= 0) & (y0 < Wl);
            const bool yv1 = (y0 + 1 >= 0) & (y0 + 1 < Wl);

            if (yv0 & xv0) acc = fmaf(a * w00, vb[(size_t)(st + y0 * Wl + x0) * DM], acc);
            if (yv0 & xv1) acc = fmaf(a * w01, vb[(size_t)(st + y0 * Wl + x0 + 1) * DM], acc);
            if (yv1 & xv0) acc = fmaf(a * w10, vb[(size_t)(st + (y0 + 1) * Wl + x0) * DM], acc);
            if (yv1 & xv1) acc = fmaf(a * w11, vb[(size_t)(st + (y0 + 1) * Wl + x0 + 1) * DM], acc);
        }
    }
    o16[oq * DM + h * DH + d] = __float2half(acc);
}

// ---------------- host-side orchestration ----------------------------------
static inline void gemm_f32(const __half* A, const __half* Bh, const __half* Bl,
                            const float* bias, float* Cf, int M, int N, int K) {
    dim3 grid(N / 128, (M + 127) / 128);
    tc_gemm<false, 0><<<grid, 256, H2_SMEM>>>(A, Bh, Bl, bias, Cf, 0, 0, M, N, K);
}
static inline void gemm_f16(const __half* A, const __half* Bh, const __half* Bl,
                            const float* bias, __half* C16, int M, int N, int K, bool relu) {
    dim3 grid(N / 128, (M + 127) / 128);
    if (relu) tc_gemm<true, 1><<<grid, 256, H2_SMEM>>>(A, Bh, Bl, bias, 0, C16, 0, M, N, K);
    else      tc_gemm<false, 1><<<grid, 256, H2_SMEM>>>(A, Bh, Bl, bias, 0, C16, 0, M, N, K);
}
static inline void gemm_split(const __half* A, const __half* Bh, const __half* Bl,
                              const float* bias, __half* Ch, __half* Cl, int M, int N, int K) {
    dim3 grid(N / 128, (M + 127) / 128);
    tc_gemm<false, 2><<<grid, 256, H2_SMEM>>>(A, Bh, Bl, bias, 0, Ch, Cl, M, N, K);
}

extern "C" void kernel_launch(void* const* d_in, const int* in_sizes, int n_in,
                              void* d_out, int out_size) {
    (void)in_sizes; (void)n_in; (void)out_size;
    const float* tgt       = (const float*)d_in[0];
    const float* query_pos = (const float*)d_in[1];
    const float* refpts    = (const float*)d_in[2];
    const float* src       = (const float*)d_in[3];
    const float* sa_in_b   = (const float*)d_in[7];
    const float* sa_out_b  = (const float*)d_in[9];
    const float* norm2_g   = (const float*)d_in[10];
    const float* norm2_b   = (const float*)d_in[11];
    const float* off_b     = (const float*)d_in[13];
    const float* aw_b      = (const float*)d_in[15];
    const float* val_b     = (const float*)d_in[17];
    const float* outp_b    = (const float*)d_in[19];
    const float* norm1_g   = (const float*)d_in[20];
    const float* norm1_b   = (const float*)d_in[21];
    const float* ffn_b1    = (const float*)d_in[23];
    const float* ffn_b2    = (const float*)d_in[25];
    const float* norm3_g   = (const float*)d_in[26];
    const float* norm3_b   = (const float*)d_in[27];
    float* out = (float*)d_out;

    cudaFuncSetAttribute(tc_gemm<false,0>, cudaFuncAttributeMaxDynamicSharedMemorySize, H2_SMEM);
    cudaFuncSetAttribute(tc_gemm<false,1>, cudaFuncAttributeMaxDynamicSharedMemorySize, H2_SMEM);
    cudaFuncSetAttribute(tc_gemm<true,1>,  cudaFuncAttributeMaxDynamicSharedMemorySize, H2_SMEM);
    cudaFuncSetAttribute(tc_gemm<false,2>, cudaFuncAttributeMaxDynamicSharedMemorySize, H2_SMEM);
    cudaFuncSetAttribute(attn_mma, cudaFuncAttributeMaxDynamicSharedMemorySize, ATT_SMEM);

    void* p;
    #define SYMF(name) cudaGetSymbolAddress(&p, name); float* name##_p = (float*)p;
    #define SYMH(name) cudaGetSymbolAddress(&p, name); __half* name##_p = (__half*)p;
    SYMF(g_proj) SYMF(g_tgt2) SYMF(g_tgt3) SYMF(g_offaw) SYMF(g_value) SYMF(g_cbias)
    SYMH(g_qk16) SYMH(g_tgt16) SYMH(g_qk2_h) SYMH(g_qk2_l) SYMH(g_v2_h) SYMH(g_v2_l)
    SYMH(g_att16) SYMH(g_query16) SYMH(g_tgt3_16) SYMH(g_ca16) SYMH(g_ffn16)
    SYMH(g_src16) SYMH(g_w16h) SYMH(g_w16l)
    #undef SYMF
    #undef SYMH

    // 0) weight + input conversions
    split_weights<<<(WTOT + 255)/256, 256>>>(
        (const float*)d_in[6], (const float*)d_in[8], (const float*)d_in[12],
        (const float*)d_in[14], (const float*)d_in[16], (const float*)d_in[18],
        (const float*)d_in[22], (const float*)d_in[24],
        off_b, aw_b, g_w16h_p, g_w16l_p, g_cbias_p);
    const int n4 = NQ * DM / 4;
    add_cvt_kernel<<<(n4 + 255)/256, 256>>>(tgt, query_pos, g_qk16_p, g_tgt16_p, n4);
    const int ns4 = (int)((size_t)NSRC * DM / 4);
    cvt_f16_kernel<<<(ns4 + 255)/256, 256>>>(src, g_src16_p, ns4);

    // 1) self-attn
    gemm_split(g_qk16_p, g_w16h_p + OFF_SAIN, g_w16l_p + OFF_SAIN, sa_in_b,
               g_qk2_h_p, g_qk2_l_p, NQ, 512, DM);
    gemm_split(g_tgt16_p, g_w16h_p + OFF_SAIN + 131072, g_w16l_p + OFF_SAIN + 131072,
               sa_in_b + 2*DM, g_v2_h_p, g_v2_l_p, NQ, DM, DM);
    attn_mma<<<dim3(8, NB * NH), 256, ATT_SMEM>>>(g_qk2_h_p, g_qk2_l_p,
                                                  g_v2_h_p, g_v2_l_p, g_att16_p);
    gemm_f32(g_att16_p, g_w16h_p + OFF_SAOUT, g_w16l_p + OFF_SAOUT, sa_out_b,
             g_proj_p, NQ, DM, DM);
    ln_kernel<<<NQ, DM>>>(tgt, g_proj_p, norm2_g, norm2_b, g_tgt2_p, query_pos, g_query16_p);

    // 2) cross-attn
    gemm_f32(g_src16_p, g_w16h_p + OFF_VALW, g_w16l_p + OFF_VALW, val_b,
             g_value_p, NSRC, DM, DM);
    gemm_f32(g_query16_p, g_w16h_p + OFF_OFFW, g_w16l_p + OFF_OFFW, g_cbias_p,
             g_offaw_p, NQ, 384, DM);
    awsm_kernel<<<(NQ * NH + 255)/256, 256>>>(g_offaw_p);
    deform_kernel<<<NQ, dim3(32, 8)>>>(g_value_p, g_offaw_p, refpts, g_ca16_p);
    gemm_f32(g_ca16_p, g_w16h_p + OFF_OUTPW, g_w16l_p + OFF_OUTPW, outp_b,
             g_proj_p, NQ, DM, DM);
    ln_kernel<<<NQ, DM>>>(g_tgt2_p, g_proj_p, norm1_g, norm1_b, g_tgt3_p, nullptr, g_tgt3_16_p);

    // 3) FFN
    gemm_f16(g_tgt3_16_p, g_w16h_p + OFF_FFN1, g_w16l_p + OFF_FFN1, ffn_b1,
             g_ffn16_p, NQ, DFFN, DM, true);
    gemm_f32(g_ffn16_p, g_w16h_p + OFF_FFN2, g_w16l_p + OFF_FFN2, ffn_b2,
             g_proj_p, NQ, DM, DFFN);
    ln_kernel<<<NQ, DM>>>(g_tgt3_p, g_proj_p, norm3_g, norm3_b, out, nullptr, nullptr);
}

// round 13
// speedup vs baseline: 1.9079x; 1.2562x over previous
#include <cuda_runtime.h>
#include <cuda_fp16.h>
#include <math.h>
#include <stdint.h>

#define NB    8
#define LQ    1000
#define DM    256
#define NH    8
#define DH    32
#define NLV   4
#define NPT   4
#define LEN_IN 21760
#define DFFN  1024
#define NQ    (NB*LQ)    /* 8000 */
#define NSRC  (NB*LEN_IN) /* 174080 */

// ---------------- fp32 scratch ---------------------------------------------
__device__ float g_proj[NQ*DM];
__device__ float g_tgt2[NQ*DM];
__device__ float g_tgt3[NQ*DM];
__device__ float g_offaw[NQ*384];
__device__ float g_cbias[384];

// ---------------- fp16 scratch ----------------------------------------------
__device__ __half g_qk16[NQ*DM];
__device__ __half g_tgt16[NQ*DM];
__device__ __half g_qk2[NQ*512];
__device__ __half g_v2[NQ*DM];
__device__ __half g_att16[NQ*DM];
__device__ __half g_query16[NQ*DM];
__device__ __half g_tgt3_16[NQ*DM];
__device__ __half g_ca16[NQ*DM];
__device__ __half g_ffn16[NQ*DFFN];
__device__ __half g_src16[(size_t)NSRC*DM];
__device__ __half g_value16[(size_t)NSRC*DM];

#define WTOT 1015808
#define OFF_SAIN  0
#define OFF_SAOUT 196608
#define OFF_OFFW  262144
#define OFF_VALW  360448
#define OFF_OUTPW 425984
#define OFF_FFN1  491520
#define OFF_FFN2  753664
__device__ __half g_w16[WTOT];

// =================== helpers ===============================================
__device__ __forceinline__ uint32_t smem_u32(const void* p) {
    uint32_t a;
    asm("{ .reg .u64 t; cvta.to.shared.u64 t, %1; cvt.u32.u64 %0, t; }" : "=r"(a) : "l"(p));
    return a;
}
__device__ __forceinline__ void ldmx4(uint32_t addr, uint32_t* r) {
    asm volatile("ldmatrix.sync.aligned.m8n8.x4.shared.b16 {%0,%1,%2,%3}, [%4];"
                 : "=r"(r[0]), "=r"(r[1]), "=r"(r[2]), "=r"(r[3]) : "r"(addr));
}
__device__ __forceinline__ void ldmx4t(uint32_t addr, uint32_t* r) {
    asm volatile("ldmatrix.sync.aligned.m8n8.x4.trans.shared.b16 {%0,%1,%2,%3}, [%4];"
                 : "=r"(r[0]), "=r"(r[1]), "=r"(r[2]), "=r"(r[3]) : "r"(addr));
}
__device__ __forceinline__ void mmah(float* d, const uint32_t* a, uint32_t b0, uint32_t b1) {
    asm volatile("mma.sync.aligned.m16n8k16.row.col.f32.f16.f16.f32 "
                 "{%0,%1,%2,%3}, {%4,%5,%6,%7}, {%8,%9}, {%0,%1,%2,%3};"
                 : "+f"(d[0]), "+f"(d[1]), "+f"(d[2]), "+f"(d[3])
                 : "r"(a[0]), "r"(a[1]), "r"(a[2]), "r"(a[3]), "r"(b0), "r"(b1));
}
__device__ __forceinline__ void cp16z(uint32_t dst, const void* src, bool v) {
    asm volatile("cp.async.cg.shared.global [%0], [%1], 16, %2;"
                 :: "r"(dst), "l"(src), "r"(v ? 16 : 0));
}
__device__ __forceinline__ float ex2f(float x) {
    float r; asm("ex2.approx.ftz.f32 %0, %1;" : "=f"(r) : "f"(x)); return r;
}

#define TCSTR 40

// =================== fp16 1-term GEMM ======================================
// C[M,N] = A@B^T + bias. 128x128, 8 warps (32x64 warp tile), 2-stage.
// OUT: 0 = fp32, 1 = fp16 (opt RELU).
#define H1_A 0
#define H1_B 10240
#define H1_STAGE 20480
#define H1_SMEM (2*H1_STAGE)

__device__ __forceinline__ void stage_load_h1(
    uint32_t sb, const __half* A, const __half* B,
    int M, int N, int K, int rowBase, int colBase, int k0, int ldR, int ldC) {
    int gr = rowBase + ldR; bool av = gr < M; if (!av) gr = 0;
    const char* pa = (const char*)(A + (size_t)gr * K + k0) + ldC;
    uint32_t da = sb + H1_A + ldR * 80 + ldC;
    cp16z(da, pa, av);        cp16z(da + 16, pa + 16, av);
    int gc = colBase + ldR; bool bv = gc < N; if (!bv) gc = 0;
    const char* pb = (const char*)(B + (size_t)gc * K + k0) + ldC;
    uint32_t db = sb + H1_B + ldR * 80 + ldC;
    cp16z(db, pb, bv);        cp16z(db + 16, pb + 16, bv);
    asm volatile("cp.async.commit_group;" ::: "memory");
}

template<bool RELU, int OUT>
__global__ __launch_bounds__(256)
void tc_gemm(const __half* __restrict__ A, const __half* __restrict__ B,
             const float* __restrict__ bias, float* __restrict__ Cf,
             __half* __restrict__ C16, int M, int N, int K) {
    extern __shared__ char smem[];
    const uint32_t sbase = smem_u32(smem);
    const int tid  = threadIdx.x;
    const int lane = tid & 31;
    const int wid  = tid >> 5;
    const int warpM = wid & 3;
    const int warpN = wid >> 2;
    const int rowBase = blockIdx.y * 128;
    const int colBase = blockIdx.x * 128;
    const int ldR = tid >> 1;
    const int ldC = (tid & 1) * 32;

    const int aRow = (lane & 15);
    const int aColOff = (lane >> 4) * 8;
    const int bRow = (lane & 7) + ((lane >> 4) & 1) * 8;
    const int bColOff = ((lane >> 3) & 1) * 8;

    float acc[2][8][4];
    #pragma unroll
    for (int mt = 0; mt < 2; mt++)
        #pragma unroll
        for (int nt = 0; nt < 8; nt++)
            #pragma unroll
            for (int i = 0; i < 4; i++) acc[mt][nt][i] = 0.f;

    const int KC = K >> 5;
    stage_load_h1(sbase, A, B, M, N, K, rowBase, colBase, 0, ldR, ldC);

    for (int c = 0; c < KC; c++) {
        asm volatile("cp.async.wait_group 0;" ::: "memory");
        __syncthreads();
        if (c + 1 < KC)
            stage_load_h1(sbase + ((c + 1) & 1) * H1_STAGE, A, B,
                          M, N, K, rowBase, colBase, (c + 1) << 5, ldR, ldC);

        const uint32_t sb = sbase + (c & 1) * H1_STAGE;
        #pragma unroll
        for (int ks = 0; ks < 32; ks += 16) {
            uint32_t ah[2][4];
            #pragma unroll
            for (int mt = 0; mt < 2; mt++) {
                const int r0 = warpM * 32 + mt * 16;
                uint32_t off = (uint32_t)((r0 + aRow) * TCSTR + ks + aColOff) * 2;
                ldmx4(sb + H1_A + off, ah[mt]);
            }
            uint32_t bh[4][4];
            #pragma unroll
            for (int nb = 0; nb < 4; nb++) {
                const int n0 = warpN * 64 + nb * 16;
                uint32_t off = (uint32_t)((n0 + bRow) * TCSTR + ks + bColOff) * 2;
                ldmx4(sb + H1_B + off, bh[nb]);
            }
            #pragma unroll
            for (int mt = 0; mt < 2; mt++) {
                #pragma unroll
                for (int nt = 0; nt < 8; nt++) {
                    const int nb = nt >> 1, hi = (nt & 1) * 2;
                    mmah(acc[mt][nt], ah[mt], bh[nb][hi], bh[nb][hi+1]);
                }
            }
        }
    }

    #pragma unroll
    for (int mt = 0; mt < 2; mt++) {
        #pragma unroll
        for (int half = 0; half < 2; half++) {
            const int row = rowBase + warpM * 32 + mt * 16 + (lane >> 2) + half * 8;
            if (row < M) {
                #pragma unroll
                for (int nt = 0; nt < 8; nt++) {
                    const int col = colBase + warpN * 64 + nt * 8 + (lane & 3) * 2;
                    float ox = acc[mt][nt][half*2+0] + bias[col];
                    float oy = acc[mt][nt][half*2+1] + bias[col+1];
                    if (RELU) { ox = fmaxf(ox, 0.f); oy = fmaxf(oy, 0.f); }
                    if (OUT == 0) {
                        *(float2*)(Cf + (size_t)row * N + col) = make_float2(ox, oy);
                    } else {
                        *(__half2*)(C16 + (size_t)row * N + col) =
                            __half2(__float2half(ox), __float2half(oy));
                    }
                }
            }
        }
    }
}

// =================== fp16 tensor-core flash self-attention =================
// K/V tile: 64 rows x 64B each. Loader: r = tid>>2 (0..63), j = tid&3 (16B).
#define ATT_Q 0
#define ATT_KV(st) (10240 + (st)*10240)
#define ATT_K_O 0
#define ATT_V_O 5120
#define ATT_SMEM (10240 + 2*10240)
#define KSCALE 0.25503486f   /* log2(e)/sqrt(32) */

__global__ __launch_bounds__(256)
void attn_mma(const __half* __restrict__ qk2, const __half* __restrict__ v2,
              __half* __restrict__ oh) {
    extern __shared__ char smem[];
    const uint32_t sb = smem_u32(smem);
    const int tid = threadIdx.x;
    const int lane = tid & 31;
    const int w = tid >> 5;
    const int g = lane >> 2, t4 = lane & 3;
    const int qbase = blockIdx.x * 128;
    const int b = blockIdx.y >> 3, h = blockIdx.y & 7;

    {   // Q: 128 rows x 64B
        const int r = tid >> 1, cb = (tid & 1) * 32;
        const int gr = qbase + r;
        const bool v = gr < LQ;
        const size_t rowo = ((size_t)(b * LQ + (v ? gr : 0)) * 512 + h * 32) * 2;
        cp16z(sb + ATT_Q + r * 80 + cb,      (const char*)qk2 + rowo + cb, v);
        cp16z(sb + ATT_Q + r * 80 + cb + 16, (const char*)qk2 + rowo + cb + 16, v);
    }
    {   // K/V tile 0: 64 rows x 64B each
        const int r = tid >> 2, j = tid & 3;
        const bool v = r < LQ;
        const size_t ko = ((size_t)(b * LQ + (v ? r : 0)) * 512 + 256 + h * 32) * 2 + j * 16;
        const size_t vo = ((size_t)(b * LQ + (v ? r : 0)) * 256 + h * 32) * 2 + j * 16;
        cp16z(sb + ATT_KV(0) + ATT_K_O + r * 80 + j * 16, (const char*)qk2 + ko, v);
        cp16z(sb + ATT_KV(0) + ATT_V_O + r * 80 + j * 16, (const char*)v2 + vo, v);
    }
    asm volatile("cp.async.commit_group;" ::: "memory");

    float m0 = -1e30f, m1 = -1e30f, l0 = 0.f, l1 = 0.f;
    float o[4][4];
    #pragma unroll
    for (int vt = 0; vt < 4; vt++)
        #pragma unroll
        for (int i = 0; i < 4; i++) o[vt][i] = 0.f;

    uint32_t qh[2][4];
    const int bRow = (lane & 7) + ((lane >> 4) & 1) * 8;
    const int bColOff = ((lane >> 3) & 1) * 8;
    const int NT = (LQ + 63) / 64;

    for (int ti = 0; ti < NT; ti++) {
        asm volatile("cp.async.wait_group 0;" ::: "memory");
        __syncthreads();
        if (ti == 0) {
            #pragma unroll
            for (int kf = 0; kf < 2; kf++) {
                uint32_t off = (uint32_t)((w * 16 + (lane & 15)) * TCSTR + kf * 16 + (lane >> 4) * 8) * 2;
                ldmx4(sb + ATT_Q + off, qh[kf]);
            }
        }
        if (ti + 1 < NT) {
            const int kt = (ti + 1) * 64;
            const int r = tid >> 2, j = tid & 3;
            const int kr = kt + r;
            const bool v = kr < LQ;
            const size_t ko = ((size_t)(b * LQ + (v ? kr : 0)) * 512 + 256 + h * 32) * 2 + j * 16;
            const size_t vo = ((size_t)(b * LQ + (v ? kr : 0)) * 256 + h * 32) * 2 + j * 16;
            const uint32_t st = sb + ATT_KV((ti + 1) & 1);
            cp16z(st + ATT_K_O + r * 80 + j * 16, (const char*)qk2 + ko, v);
            cp16z(st + ATT_V_O + r * 80 + j * 16, (const char*)v2 + vo, v);
            asm volatile("cp.async.commit_group;" ::: "memory");
        }

        const uint32_t stg = sb + ATT_KV(ti & 1);
        const int kt = ti * 64;

        float s[8][4];
        #pragma unroll
        for (int nt = 0; nt < 8; nt++)
            #pragma unroll
            for (int i = 0; i < 4; i++) s[nt][i] = 0.f;
        #pragma unroll
        for (int kf = 0; kf < 2; kf++) {
            #pragma unroll
            for (int nb = 0; nb < 4; nb++) {
                uint32_t off = (uint32_t)((nb * 16 + bRow) * TCSTR + kf * 16 + bColOff) * 2;
                uint32_t kh[4];
                ldmx4(stg + ATT_K_O + off, kh);
                #pragma unroll
                for (int hf = 0; hf < 2; hf++) {
                    mmah(s[nb * 2 + hf], qh[kf], kh[hf*2], kh[hf*2+1]);
                }
            }
        }

        const int validTiles = min(8, (LQ - kt) >> 3);
        float tmax0 = -1e30f, tmax1 = -1e30f;
        #pragma unroll
        for (int nt = 0; nt < 8; nt++) {
            if (nt < validTiles) {
                s[nt][0] *= KSCALE; s[nt][1] *= KSCALE;
                s[nt][2] *= KSCALE; s[nt][3] *= KSCALE;
            } else {
                s[nt][0] = s[nt][1] = s[nt][2] = s[nt][3] = -1e30f;
            }
            tmax0 = fmaxf(tmax0, fmaxf(s[nt][0], s[nt][1]));
            tmax1 = fmaxf(tmax1, fmaxf(s[nt][2], s[nt][3]));
        }
        tmax0 = fmaxf(tmax0, __shfl_xor_sync(0xffffffffu, tmax0, 1));
        tmax0 = fmaxf(tmax0, __shfl_xor_sync(0xffffffffu, tmax0, 2));
        tmax1 = fmaxf(tmax1, __shfl_xor_sync(0xffffffffu, tmax1, 1));
        tmax1 = fmaxf(tmax1, __shfl_xor_sync(0xffffffffu, tmax1, 2));
        const float mn0 = fmaxf(m0, tmax0), mn1 = fmaxf(m1, tmax1);
        const float c0 = ex2f(m0 - mn0), c1 = ex2f(m1 - mn1);
        m0 = mn0; m1 = mn1;
        l0 *= c0; l1 *= c1;
        #pragma unroll
        for (int vt = 0; vt < 4; vt++) {
            o[vt][0] *= c0; o[vt][1] *= c0; o[vt][2] *= c1; o[vt][3] *= c1;
        }

        uint32_t ph[4][4];
        #pragma unroll
        for (int nt = 0; nt < 8; nt++) {
            float p0 = ex2f(s[nt][0] - mn0), p1 = ex2f(s[nt][1] - mn0);
            float p2 = ex2f(s[nt][2] - mn1), p3 = ex2f(s[nt][3] - mn1);
            l0 += p0 + p1; l1 += p2 + p3;
            const int ks = nt >> 1, base = (nt & 1) * 2;
            __half2 p01(__float2half(p0), __float2half(p1));
            __half2 p23(__float2half(p2), __float2half(p3));
            ph[ks][base+0] = *(uint32_t*)&p01;
            ph[ks][base+1] = *(uint32_t*)&p23;
        }

        #pragma unroll
        for (int ks = 0; ks < 4; ks++) {
            const int krow = ks * 16 + (lane & 7) + ((lane >> 3) & 1) * 8;
            #pragma unroll
            for (int nh = 0; nh < 2; nh++) {
                uint32_t off = (uint32_t)(krow * TCSTR + nh * 16 + (lane >> 4) * 8) * 2;
                uint32_t vh[4];
                ldmx4t(stg + ATT_V_O + off, vh);
                #pragma unroll
                for (int sub = 0; sub < 2; sub++) {
                    mmah(o[nh * 2 + sub], ph[ks], vh[sub*2], vh[sub*2+1]);
                }
            }
        }
    }

    l0 += __shfl_xor_sync(0xffffffffu, l0, 1);
    l0 += __shfl_xor_sync(0xffffffffu, l0, 2);
    l1 += __shfl_xor_sync(0xffffffffu, l1, 1);
    l1 += __shfl_xor_sync(0xffffffffu, l1, 2);
    const float inv0 = 1.f / l0, inv1 = 1.f / l1;
    const int r0 = qbase + w * 16 + g;
    const int r1 = r0 + 8;
    #pragma unroll
    for (int half = 0; half < 2; half++) {
        const int row = half ? r1 : r0;
        const float inv = half ? inv1 : inv0;
        if (row < LQ) {
            const size_t base = ((size_t)(b * LQ + row)) * DM + h * DH;
            #pragma unroll
            for (int vt = 0; vt < 4; vt++) {
                float vx = o[vt][half*2+0] * inv;
                float vy = o[vt][half*2+1] * inv;
                *(__half2*)(oh + base + vt * 8 + t4 * 2) =
                    __half2(__float2half(vx), __float2half(vy));
            }
        }
    }
}

// ---------------- weight converter (fp16 single) + combined bias -----------
__global__ void cvt_weights(const float* __restrict__ w0, const float* __restrict__ w1,
                            const float* __restrict__ w2, const float* __restrict__ w3,
                            const float* __restrict__ w4, const float* __restrict__ w5,
                            const float* __restrict__ w6, const float* __restrict__ w7,
                            const float* __restrict__ off_b, const float* __restrict__ aw_b,
                            __half* __restrict__ w16, float* __restrict__ cbias) {
    int i = blockIdx.x * blockDim.x + threadIdx.x;
    if (i < 384) cbias[i] = (i < 256) ? off_b[i] : aw_b[i - 256];
    if (i >= WTOT) return;
    const float* src; int local;
    if      (i < OFF_SAOUT) { src = w0; local = i; }
    else if (i < OFF_OFFW)  { src = w1; local = i - OFF_SAOUT; }
    else if (i < OFF_VALW)  { src = (i < 327680) ? w2 : w3; local = (i < 327680) ? i - OFF_OFFW : i - 327680; }
    else if (i < OFF_OUTPW) { src = w4; local = i - OFF_VALW; }
    else if (i < OFF_FFN1)  { src = w5; local = i - OFF_OUTPW; }
    else if (i < OFF_FFN2)  { src = w6; local = i - OFF_FFN1; }
    else                    { src = w7; local = i - OFF_FFN2; }
    w16[i] = __float2half(src[local]);
}

// ---------------- add + fp16 convert ---------------------------------------
__global__ void add_cvt_kernel(const float* __restrict__ a, const float* __restrict__ b,
                               __half* __restrict__ q16, __half* __restrict__ t16, int n4) {
    int i = blockIdx.x * blockDim.x + threadIdx.x;
    if (i >= n4) return;
    float4 x = ((const float4*)a)[i];
    float4 y = ((const float4*)b)[i];
    *(__half2*)(q16 + i*4)     = __half2(__float2half(x.x + y.x), __float2half(x.y + y.y));
    *(__half2*)(q16 + i*4 + 2) = __half2(__float2half(x.z + y.z), __float2half(x.w + y.w));
    *(__half2*)(t16 + i*4)     = __half2(__float2half(x.x), __float2half(x.y));
    *(__half2*)(t16 + i*4 + 2) = __half2(__float2half(x.z), __float2half(x.w));
}

// ---------------- fp32 -> fp16 converter ------------------------------------
__global__ void cvt_f16_kernel(const float* __restrict__ a, __half* __restrict__ o, int n4) {
    int i = blockIdx.x * blockDim.x + threadIdx.x;
    if (i >= n4) return;
    float4 x = ((const float4*)a)[i];
    *(__half2*)(o + i*4)     = __half2(__float2half(x.x), __float2half(x.y));
    *(__half2*)(o + i*4 + 2) = __half2(__float2half(x.z), __float2half(x.w));
}

// ---------------- LayerNorm(x+res) -> fp32 (+ optional fp16 of out+pos) ----
__global__ __launch_bounds__(256)
void ln_kernel(const float* __restrict__ x, const float* __restrict__ res,
               const float* __restrict__ g, const float* __restrict__ bta,
               float* __restrict__ out,
               const float* __restrict__ pos, __half* __restrict__ o16) {
    __shared__ float red[8];
    const int row = blockIdx.x, t = threadIdx.x;
    const size_t idx = (size_t)row * DM + t;
    float v = x[idx] + res[idx];

    float s = v;
    #pragma unroll
    for (int o = 16; o; o >>= 1) s += __shfl_xor_sync(0xffffffffu, s, o);
    if ((t & 31) == 0) red[t >> 5] = s;
    __syncthreads();
    float mean = 0.f;
    #pragma unroll
    for (int i = 0; i < 8; i++) mean += red[i];
    mean *= (1.f / DM);
    __syncthreads();

    float d = v - mean;
    float s2 = d * d;
    #pragma unroll
    for (int o = 16; o; o >>= 1) s2 += __shfl_xor_sync(0xffffffffu, s2, o);
    if ((t & 31) == 0) red[t >> 5] = s2;
    __syncthreads();
    float var = 0.f;
    #pragma unroll
    for (int i = 0; i < 8; i++) var += red[i];
    var *= (1.f / DM);

    float o = d * rsqrtf(var + 1e-5f) * g[t] + bta[t];
    out[idx] = o;
    if (o16) {
        float tq = pos ? o + pos[idx] : o;
        o16[idx] = __float2half(tq);
    }
}

// ---------------- attention-weight softmax ---------------------------------
__global__ void awsm_kernel(float* __restrict__ offaw) {
    int i = blockIdx.x * blockDim.x + threadIdx.x;
    if (i >= NQ * NH) return;
    float* p = offaw + (size_t)(i / NH) * 384 + 256 + (i % NH) * 16;
    float mx = -1e30f;
    #pragma unroll
    for (int j = 0; j < 16; j++) mx = fmaxf(mx, p[j]);
    float sm = 0.f, e[16];
    #pragma unroll
    for (int j = 0; j < 16; j++) { e[j] = __expf(p[j] - mx); sm += e[j]; }
    float inv = 1.f / sm;
    #pragma unroll
    for (int j = 0; j < 16; j++) p[j] = e[j] * inv;
}

// ---------------- MS-deformable sampling (fp16 value, fp16 out) ------------
__global__ __launch_bounds__(256)
void deform_kernel(const __half* __restrict__ value, const float* __restrict__ offaw,
                   const float* __restrict__ ref, __half* __restrict__ o16) {
    const int qidx = blockIdx.x;
    const int b = qidx / LQ;
    const int h = threadIdx.y, d = threadIdx.x;

    const int starts[4] = {0, 16384, 20480, 21504};
    const int Wi[4]     = {128, 64, 32, 16};

    const __half* vb = value + (size_t)b * LEN_IN * DM + h * DH + d;
    const size_t oq = (size_t)qidx;
    const float* offp = offaw + oq * 384;
    float acc = 0.f;

    #pragma unroll
    for (int lvl = 0; lvl < NLV; lvl++) {
        const float W = (float)Wi[lvl];
        const int   Wl = Wi[lvl];
        const int   st = starts[lvl];
        const float rx = ref[(oq * NLV + lvl) * 2 + 0];
        const float ry = ref[(oq * NLV + lvl) * 2 + 1];
        #pragma unroll
        for (int p = 0; p < NPT; p++) {
            const int oidx = ((h * NLV + lvl) * NPT + p) * 2;
            const float ox = offp[oidx + 0];
            const float oy = offp[oidx + 1];
            const float a  = offp[256 + h * 16 + lvl * 4 + p];
            const float x = (rx + ox / W) * W - 0.5f;
            const float y = (ry + oy / W) * W - 0.5f;
            const float x0f = floorf(x), y0f = floorf(y);
            const float lx = x - x0f, ly = y - y0f;
            const int x0 = (int)x0f, y0 = (int)y0f;

            const float w00 = (1.f - ly) * (1.f - lx);
            const float w01 = (1.f - ly) * lx;
            const float w10 = ly * (1.f - lx);
            const float w11 = ly * lx;

            const bool xv0 = (x0 >= 0) & (x0 < Wl);
            const bool xv1 = (x0 + 1 >= 0) & (x0 + 1 < Wl);
            const bool yv0 = (y0 >= 0) & (y0 < Wl);
            const bool yv1 = (y0 + 1 >= 0) & (y0 + 1 < Wl);

            if (yv0 & xv0) acc = fmaf(a * w00, __half2float(vb[(size_t)(st + y0 * Wl + x0) * DM]), acc);
            if (yv0 & xv1) acc = fmaf(a * w01, __half2float(vb[(size_t)(st + y0 * Wl + x0 + 1) * DM]), acc);
            if (yv1 & xv0) acc = fmaf(a * w10, __half2float(vb[(size_t)(st + (y0 + 1) * Wl + x0) * DM]), acc);
            if (yv1 & xv1) acc = fmaf(a * w11, __half2float(vb[(size_t)(st + (y0 + 1) * Wl + x0 + 1) * DM]), acc);
        }
    }
    o16[oq * DM + h * DH + d] = __float2half(acc);
}

// ---------------- host-side orchestration ----------------------------------
static inline void gemm_f32(const __half* A, const __half* B, const float* bias,
                            float* Cf, int M, int N, int K) {
    dim3 grid(N / 128, (M + 127) / 128);
    tc_gemm<false, 0><<<grid, 256, H1_SMEM>>>(A, B, bias, Cf, 0, M, N, K);
}
static inline void gemm_f16(const __half* A, const __half* B, const float* bias,
                            __half* C16, int M, int N, int K, bool relu) {
    dim3 grid(N / 128, (M + 127) / 128);
    if (relu) tc_gemm<true, 1><<<grid, 256, H1_SMEM>>>(A, B, bias, 0, C16, M, N, K);
    else      tc_gemm<false, 1><<<grid, 256, H1_SMEM>>>(A, B, bias, 0, C16, M, N, K);
}

extern "C" void kernel_launch(void* const* d_in, const int* in_sizes, int n_in,
                              void* d_out, int out_size) {
    (void)in_sizes; (void)n_in; (void)out_size;
    const float* tgt       = (const float*)d_in[0];
    const float* query_pos = (const float*)d_in[1];
    const float* refpts    = (const float*)d_in[2];
    const float* src       = (const float*)d_in[3];
    const float* sa_in_b   = (const float*)d_in[7];
    const float* sa_out_b  = (const float*)d_in[9];
    const float* norm2_g   = (const float*)d_in[10];
    const float* norm2_b   = (const float*)d_in[11];
    const float* off_b     = (const float*)d_in[13];
    const float* aw_b      = (const float*)d_in[15];
    const float* val_b     = (const float*)d_in[17];
    const float* outp_b    = (const float*)d_in[19];
    const float* norm1_g   = (const float*)d_in[20];
    const float* norm1_b   = (const float*)d_in[21];
    const float* ffn_b1    = (const float*)d_in[23];
    const float* ffn_b2    = (const float*)d_in[25];
    const float* norm3_g   = (const float*)d_in[26];
    const float* norm3_b   = (const float*)d_in[27];
    float* out = (float*)d_out;

    cudaFuncSetAttribute(tc_gemm<false,0>, cudaFuncAttributeMaxDynamicSharedMemorySize, H1_SMEM);
    cudaFuncSetAttribute(tc_gemm<false,1>, cudaFuncAttributeMaxDynamicSharedMemorySize, H1_SMEM);
    cudaFuncSetAttribute(tc_gemm<true,1>,  cudaFuncAttributeMaxDynamicSharedMemorySize, H1_SMEM);
    cudaFuncSetAttribute(attn_mma, cudaFuncAttributeMaxDynamicSharedMemorySize, ATT_SMEM);

    void* p;
    #define SYMF(name) cudaGetSymbolAddress(&p, name); float* name##_p = (float*)p;
    #define SYMH(name) cudaGetSymbolAddress(&p, name); __half* name##_p = (__half*)p;
    SYMF(g_proj) SYMF(g_tgt2) SYMF(g_tgt3) SYMF(g_offaw) SYMF(g_cbias)
    SYMH(g_qk16) SYMH(g_tgt16) SYMH(g_qk2) SYMH(g_v2)
    SYMH(g_att16) SYMH(g_query16) SYMH(g_tgt3_16) SYMH(g_ca16) SYMH(g_ffn16)
    SYMH(g_src16) SYMH(g_value16) SYMH(g_w16)
    #undef SYMF
    #undef SYMH

    // 0) weight + input conversions
    cvt_weights<<<(WTOT + 255)/256, 256>>>(
        (const float*)d_in[6], (const float*)d_in[8], (const float*)d_in[12],
        (const float*)d_in[14], (const float*)d_in[16], (const float*)d_in[18],
        (const float*)d_in[22], (const float*)d_in[24],
        off_b, aw_b, g_w16_p, g_cbias_p);
    const int n4 = NQ * DM / 4;
    add_cvt_kernel<<<(n4 + 255)/256, 256>>>(tgt, query_pos, g_qk16_p, g_tgt16_p, n4);
    const int ns4 = (int)((size_t)NSRC * DM / 4);
    cvt_f16_kernel<<<(ns4 + 255)/256, 256>>>(src, g_src16_p, ns4);

    // 1) self-attn
    gemm_f16(g_qk16_p, g_w16_p + OFF_SAIN, sa_in_b, g_qk2_p, NQ, 512, DM, false);
    gemm_f16(g_tgt16_p, g_w16_p + OFF_SAIN + 131072, sa_in_b + 2*DM, g_v2_p, NQ, DM, DM, false);
    attn_mma<<<dim3(8, NB * NH), 256, ATT_SMEM>>>(g_qk2_p, g_v2_p, g_att16_p);
    gemm_f32(g_att16_p, g_w16_p + OFF_SAOUT, sa_out_b, g_proj_p, NQ, DM, DM);
    ln_kernel<<<NQ, DM>>>(tgt, g_proj_p, norm2_g, norm2_b, g_tgt2_p, query_pos, g_query16_p);

    // 2) cross-attn
    gemm_f16(g_src16_p, g_w16_p + OFF_VALW, val_b, g_value16_p, NSRC, DM, DM, false);
    gemm_f32(g_query16_p, g_w16_p + OFF_OFFW, g_cbias_p, g_offaw_p, NQ, 384, DM);
    awsm_kernel<<<(NQ * NH + 255)/256, 256>>>(g_offaw_p);
    deform_kernel<<<NQ, dim3(32, 8)>>>(g_value16_p, g_offaw_p, refpts, g_ca16_p);
    gemm_f32(g_ca16_p, g_w16_p + OFF_OUTPW, outp_b, g_proj_p, NQ, DM, DM);
    ln_kernel<<<NQ, DM>>>(g_tgt2_p, g_proj_p, norm1_g, norm1_b, g_tgt3_p, nullptr, g_tgt3_16_p);

    // 3) FFN
    gemm_f16(g_tgt3_16_p, g_w16_p + OFF_FFN1, ffn_b1, g_ffn16_p, NQ, DFFN, DM, true);
    gemm_f32(g_ffn16_p, g_w16_p + OFF_FFN2, ffn_b2, g_proj_p, NQ, DM, DFFN);
    ln_kernel<<<NQ, DM>>>(g_tgt3_p, g_proj_p, norm3_g, norm3_b, out, nullptr, nullptr);
}

// round 14
// speedup vs baseline: 2.0797x; 1.0901x over previous
#include <cuda_runtime.h>
#include <cuda_fp16.h>
#include <math.h>
#include <stdint.h>

#define NB    8
#define LQ    1000
#define DM    256
#define NH    8
#define DH    32
#define NLV   4
#define NPT   4
#define LEN_IN 21760
#define DFFN  1024
#define NQ    (NB*LQ)    /* 8000 */
#define NSRC  (NB*LEN_IN) /* 174080 */

// ---------------- fp32 scratch ---------------------------------------------
__device__ float g_proj[NQ*DM];
__device__ float g_tgt2[NQ*DM];
__device__ float g_tgt3[NQ*DM];
__device__ float g_offaw[NQ*384];
__device__ float g_cbias[384];

// ---------------- fp16 scratch ----------------------------------------------
__device__ __half g_qk16[NQ*DM];
__device__ __half g_tgt16[NQ*DM];
__device__ __half g_qk2[NQ*512];
__device__ __half g_v2[NQ*DM];
__device__ __half g_att16[NQ*DM];
__device__ __half g_query16[NQ*DM];
__device__ __half g_tgt3_16[NQ*DM];
__device__ __half g_ca16[NQ*DM];
__device__ __half g_ffn16[NQ*DFFN];
__device__ __half g_src16[(size_t)NSRC*DM];
__device__ __half g_value16[(size_t)NSRC*DM];

#define WTOT 1015808
#define OFF_SAIN  0
#define OFF_SAOUT 196608
#define OFF_OFFW  262144
#define OFF_VALW  360448
#define OFF_OUTPW 425984
#define OFF_FFN1  491520
#define OFF_FFN2  753664
__device__ __half g_w16[WTOT];

// =================== helpers ===============================================
__device__ __forceinline__ uint32_t smem_u32(const void* p) {
    uint32_t a;
    asm("{ .reg .u64 t; cvta.to.shared.u64 t, %1; cvt.u32.u64 %0, t; }" : "=r"(a) : "l"(p));
    return a;
}
__device__ __forceinline__ void ldmx4(uint32_t addr, uint32_t* r) {
    asm volatile("ldmatrix.sync.aligned.m8n8.x4.shared.b16 {%0,%1,%2,%3}, [%4];"
                 : "=r"(r[0]), "=r"(r[1]), "=r"(r[2]), "=r"(r[3]) : "r"(addr));
}
__device__ __forceinline__ void ldmx4t(uint32_t addr, uint32_t* r) {
    asm volatile("ldmatrix.sync.aligned.m8n8.x4.trans.shared.b16 {%0,%1,%2,%3}, [%4];"
                 : "=r"(r[0]), "=r"(r[1]), "=r"(r[2]), "=r"(r[3]) : "r"(addr));
}
__device__ __forceinline__ void mmah(float* d, const uint32_t* a, uint32_t b0, uint32_t b1) {
    asm volatile("mma.sync.aligned.m16n8k16.row.col.f32.f16.f16.f32 "
                 "{%0,%1,%2,%3}, {%4,%5,%6,%7}, {%8,%9}, {%0,%1,%2,%3};"
                 : "+f"(d[0]), "+f"(d[1]), "+f"(d[2]), "+f"(d[3])
                 : "r"(a[0]), "r"(a[1]), "r"(a[2]), "r"(a[3]), "r"(b0), "r"(b1));
}
__device__ __forceinline__ void cp16z(uint32_t dst, const void* src, bool v) {
    asm volatile("cp.async.cg.shared.global [%0], [%1], 16, %2;"
                 :: "r"(dst), "l"(src), "r"(v ? 16 : 0));
}
__device__ __forceinline__ float ex2f(float x) {
    float r; asm("ex2.approx.ftz.f32 %0, %1;" : "=f"(r) : "f"(x)); return r;
}

#define TCSTR 40

// =================== fp16 1-term GEMM, 3-stage ring ========================
// C[M,N] = A@B^T + bias. 128x128, 8 warps (32x64 warp tile).
// OUT: 0 = fp32, 1 = fp16 (opt RELU).
#define H1_A 0
#define H1_B 10240
#define H1_STAGE 20480
#define H1_NSTG 3
#define H1_SMEM (H1_NSTG*H1_STAGE)

__device__ __forceinline__ void stage_load_h1(
    uint32_t sb, const __half* A, const __half* B,
    int M, int N, int K, int rowBase, int colBase, int k0, int ldR, int ldC) {
    int gr = rowBase + ldR; bool av = gr < M; if (!av) gr = 0;
    const char* pa = (const char*)(A + (size_t)gr * K + k0) + ldC;
    uint32_t da = sb + H1_A + ldR * 80 + ldC;
    cp16z(da, pa, av);        cp16z(da + 16, pa + 16, av);
    int gc = colBase + ldR; bool bv = gc < N; if (!bv) gc = 0;
    const char* pb = (const char*)(B + (size_t)gc * K + k0) + ldC;
    uint32_t db = sb + H1_B + ldR * 80 + ldC;
    cp16z(db, pb, bv);        cp16z(db + 16, pb + 16, bv);
    asm volatile("cp.async.commit_group;" ::: "memory");
}

template<bool RELU, int OUT>
__global__ __launch_bounds__(256)
void tc_gemm(const __half* __restrict__ A, const __half* __restrict__ B,
             const float* __restrict__ bias, float* __restrict__ Cf,
             __half* __restrict__ C16, int M, int N, int K) {
    extern __shared__ char smem[];
    const uint32_t sbase = smem_u32(smem);
    const int tid  = threadIdx.x;
    const int lane = tid & 31;
    const int wid  = tid >> 5;
    const int warpM = wid & 3;
    const int warpN = wid >> 2;
    const int rowBase = blockIdx.y * 128;
    const int colBase = blockIdx.x * 128;
    const int ldR = tid >> 1;
    const int ldC = (tid & 1) * 32;

    const int aRow = (lane & 15);
    const int aColOff = (lane >> 4) * 8;
    const int bRow = (lane & 7) + ((lane >> 4) & 1) * 8;
    const int bColOff = ((lane >> 3) & 1) * 8;

    float acc[2][8][4];
    #pragma unroll
    for (int mt = 0; mt < 2; mt++)
        #pragma unroll
        for (int nt = 0; nt < 8; nt++)
            #pragma unroll
            for (int i = 0; i < 4; i++) acc[mt][nt][i] = 0.f;

    const int KC = K >> 5;
    #pragma unroll
    for (int s = 0; s < H1_NSTG - 1; s++)
        if (s < KC)
            stage_load_h1(sbase + s * H1_STAGE, A, B, M, N, K,
                          rowBase, colBase, s << 5, ldR, ldC);

    int slot = 0;
    for (int c = 0; c < KC; c++) {
        asm volatile("cp.async.wait_group %0;" :: "n"(H1_NSTG - 2) : "memory");
        __syncthreads();
        // prefetch into the slot consumed at iter c-1
        if (c + H1_NSTG - 1 < KC) {
            int ps = slot + (H1_NSTG - 1); if (ps >= H1_NSTG) ps -= H1_NSTG;
            stage_load_h1(sbase + ps * H1_STAGE, A, B, M, N, K,
                          rowBase, colBase, (c + H1_NSTG - 1) << 5, ldR, ldC);
        }

        const uint32_t sb = sbase + slot * H1_STAGE;
        if (++slot == H1_NSTG) slot = 0;
        #pragma unroll
        for (int ks = 0; ks < 32; ks += 16) {
            uint32_t ah[2][4];
            #pragma unroll
            for (int mt = 0; mt < 2; mt++) {
                const int r0 = warpM * 32 + mt * 16;
                uint32_t off = (uint32_t)((r0 + aRow) * TCSTR + ks + aColOff) * 2;
                ldmx4(sb + H1_A + off, ah[mt]);
            }
            uint32_t bh[4][4];
            #pragma unroll
            for (int nb = 0; nb < 4; nb++) {
                const int n0 = warpN * 64 + nb * 16;
                uint32_t off = (uint32_t)((n0 + bRow) * TCSTR + ks + bColOff) * 2;
                ldmx4(sb + H1_B + off, bh[nb]);
            }
            #pragma unroll
            for (int mt = 0; mt < 2; mt++) {
                #pragma unroll
                for (int nt = 0; nt < 8; nt++) {
                    const int nb = nt >> 1, hi = (nt & 1) * 2;
                    mmah(acc[mt][nt], ah[mt], bh[nb][hi], bh[nb][hi+1]);
                }
            }
        }
    }

    #pragma unroll
    for (int mt = 0; mt < 2; mt++) {
        #pragma unroll
        for (int half = 0; half < 2; half++) {
            const int row = rowBase + warpM * 32 + mt * 16 + (lane >> 2) + half * 8;
            if (row < M) {
                #pragma unroll
                for (int nt = 0; nt < 8; nt++) {
                    const int col = colBase + warpN * 64 + nt * 8 + (lane & 3) * 2;
                    float ox = acc[mt][nt][half*2+0] + bias[col];
                    float oy = acc[mt][nt][half*2+1] + bias[col+1];
                    if (RELU) { ox = fmaxf(ox, 0.f); oy = fmaxf(oy, 0.f); }
                    if (OUT == 0) {
                        *(float2*)(Cf + (size_t)row * N + col) = make_float2(ox, oy);
                    } else {
                        *(__half2*)(C16 + (size_t)row * N + col) =
                            __half2(__float2half(ox), __float2half(oy));
                    }
                }
            }
        }
    }
}

// =================== fp16 tensor-core flash self-attention (R13) ===========
#define ATT_Q 0
#define ATT_KV(st) (10240 + (st)*10240)
#define ATT_K_O 0
#define ATT_V_O 5120
#define ATT_SMEM (10240 + 2*10240)
#define KSCALE 0.25503486f   /* log2(e)/sqrt(32) */

__global__ __launch_bounds__(256)
void attn_mma(const __half* __restrict__ qk2, const __half* __restrict__ v2,
              __half* __restrict__ oh) {
    extern __shared__ char smem[];
    const uint32_t sb = smem_u32(smem);
    const int tid = threadIdx.x;
    const int lane = tid & 31;
    const int w = tid >> 5;
    const int g = lane >> 2, t4 = lane & 3;
    const int qbase = blockIdx.x * 128;
    const int b = blockIdx.y >> 3, h = blockIdx.y & 7;

    {
        const int r = tid >> 1, cb = (tid & 1) * 32;
        const int gr = qbase + r;
        const bool v = gr < LQ;
        const size_t rowo = ((size_t)(b * LQ + (v ? gr : 0)) * 512 + h * 32) * 2;
        cp16z(sb + ATT_Q + r * 80 + cb,      (const char*)qk2 + rowo + cb, v);
        cp16z(sb + ATT_Q + r * 80 + cb + 16, (const char*)qk2 + rowo + cb + 16, v);
    }
    {
        const int r = tid >> 2, j = tid & 3;
        const bool v = r < LQ;
        const size_t ko = ((size_t)(b * LQ + (v ? r : 0)) * 512 + 256 + h * 32) * 2 + j * 16;
        const size_t vo = ((size_t)(b * LQ + (v ? r : 0)) * 256 + h * 32) * 2 + j * 16;
        cp16z(sb + ATT_KV(0) + ATT_K_O + r * 80 + j * 16, (const char*)qk2 + ko, v);
        cp16z(sb + ATT_KV(0) + ATT_V_O + r * 80 + j * 16, (const char*)v2 + vo, v);
    }
    asm volatile("cp.async.commit_group;" ::: "memory");

    float m0 = -1e30f, m1 = -1e30f, l0 = 0.f, l1 = 0.f;
    float o[4][4];
    #pragma unroll
    for (int vt = 0; vt < 4; vt++)
        #pragma unroll
        for (int i = 0; i < 4; i++) o[vt][i] = 0.f;

    uint32_t qh[2][4];
    const int bRow = (lane & 7) + ((lane >> 4) & 1) * 8;
    const int bColOff = ((lane >> 3) & 1) * 8;
    const int NT = (LQ + 63) / 64;

    for (int ti = 0; ti < NT; ti++) {
        asm volatile("cp.async.wait_group 0;" ::: "memory");
        __syncthreads();
        if (ti == 0) {
            #pragma unroll
            for (int kf = 0; kf < 2; kf++) {
                uint32_t off = (uint32_t)((w * 16 + (lane & 15)) * TCSTR + kf * 16 + (lane >> 4) * 8) * 2;
                ldmx4(sb + ATT_Q + off, qh[kf]);
            }
        }
        if (ti + 1 < NT) {
            const int kt = (ti + 1) * 64;
            const int r = tid >> 2, j = tid & 3;
            const int kr = kt + r;
            const bool v = kr < LQ;
            const size_t ko = ((size_t)(b * LQ + (v ? kr : 0)) * 512 + 256 + h * 32) * 2 + j * 16;
            const size_t vo = ((size_t)(b * LQ + (v ? kr : 0)) * 256 + h * 32) * 2 + j * 16;
            const uint32_t st = sb + ATT_KV((ti + 1) & 1);
            cp16z(st + ATT_K_O + r * 80 + j * 16, (const char*)qk2 + ko, v);
            cp16z(st + ATT_V_O + r * 80 + j * 16, (const char*)v2 + vo, v);
            asm volatile("cp.async.commit_group;" ::: "memory");
        }

        const uint32_t stg = sb + ATT_KV(ti & 1);
        const int kt = ti * 64;

        float s[8][4];
        #pragma unroll
        for (int nt = 0; nt < 8; nt++)
            #pragma unroll
            for (int i = 0; i < 4; i++) s[nt][i] = 0.f;
        #pragma unroll
        for (int kf = 0; kf < 2; kf++) {
            #pragma unroll
            for (int nb = 0; nb < 4; nb++) {
                uint32_t off = (uint32_t)((nb * 16 + bRow) * TCSTR + kf * 16 + bColOff) * 2;
                uint32_t kh[4];
                ldmx4(stg + ATT_K_O + off, kh);
                #pragma unroll
                for (int hf = 0; hf < 2; hf++) {
                    mmah(s[nb * 2 + hf], qh[kf], kh[hf*2], kh[hf*2+1]);
                }
            }
        }

        const int validTiles = min(8, (LQ - kt) >> 3);
        float tmax0 = -1e30f, tmax1 = -1e30f;
        #pragma unroll
        for (int nt = 0; nt < 8; nt++) {
            if (nt < validTiles) {
                s[nt][0] *= KSCALE; s[nt][1] *= KSCALE;
                s[nt][2] *= KSCALE; s[nt][3] *= KSCALE;
            } else {
                s[nt][0] = s[nt][1] = s[nt][2] = s[nt][3] = -1e30f;
            }
            tmax0 = fmaxf(tmax0, fmaxf(s[nt][0], s[nt][1]));
            tmax1 = fmaxf(tmax1, fmaxf(s[nt][2], s[nt][3]));
        }
        tmax0 = fmaxf(tmax0, __shfl_xor_sync(0xffffffffu, tmax0, 1));
        tmax0 = fmaxf(tmax0, __shfl_xor_sync(0xffffffffu, tmax0, 2));
        tmax1 = fmaxf(tmax1, __shfl_xor_sync(0xffffffffu, tmax1, 1));
        tmax1 = fmaxf(tmax1, __shfl_xor_sync(0xffffffffu, tmax1, 2));
        const float mn0 = fmaxf(m0, tmax0), mn1 = fmaxf(m1, tmax1);
        const float c0 = ex2f(m0 - mn0), c1 = ex2f(m1 - mn1);
        m0 = mn0; m1 = mn1;
        l0 *= c0; l1 *= c1;
        #pragma unroll
        for (int vt = 0; vt < 4; vt++) {
            o[vt][0] *= c0; o[vt][1] *= c0; o[vt][2] *= c1; o[vt][3] *= c1;
        }

        uint32_t ph[4][4];
        #pragma unroll
        for (int nt = 0; nt < 8; nt++) {
            float p0 = ex2f(s[nt][0] - mn0), p1 = ex2f(s[nt][1] - mn0);
            float p2 = ex2f(s[nt][2] - mn1), p3 = ex2f(s[nt][3] - mn1);
            l0 += p0 + p1; l1 += p2 + p3;
            const int ks = nt >> 1, base = (nt & 1) * 2;
            __half2 p01(__float2half(p0), __float2half(p1));
            __half2 p23(__float2half(p2), __float2half(p3));
            ph[ks][base+0] = *(uint32_t*)&p01;
            ph[ks][base+1] = *(uint32_t*)&p23;
        }

        #pragma unroll
        for (int ks = 0; ks < 4; ks++) {
            const int krow = ks * 16 + (lane & 7) + ((lane >> 3) & 1) * 8;
            #pragma unroll
            for (int nh = 0; nh < 2; nh++) {
                uint32_t off = (uint32_t)(krow * TCSTR + nh * 16 + (lane >> 4) * 8) * 2;
                uint32_t vh[4];
                ldmx4t(stg + ATT_V_O + off, vh);
                #pragma unroll
                for (int sub = 0; sub < 2; sub++) {
                    mmah(o[nh * 2 + sub], ph[ks], vh[sub*2], vh[sub*2+1]);
                }
            }
        }
    }

    l0 += __shfl_xor_sync(0xffffffffu, l0, 1);
    l0 += __shfl_xor_sync(0xffffffffu, l0, 2);
    l1 += __shfl_xor_sync(0xffffffffu, l1, 1);
    l1 += __shfl_xor_sync(0xffffffffu, l1, 2);
    const float inv0 = 1.f / l0, inv1 = 1.f / l1;
    const int r0 = qbase + w * 16 + g;
    const int r1 = r0 + 8;
    #pragma unroll
    for (int half = 0; half < 2; half++) {
        const int row = half ? r1 : r0;
        const float inv = half ? inv1 : inv0;
        if (row < LQ) {
            const size_t base = ((size_t)(b * LQ + row)) * DM + h * DH;
            #pragma unroll
            for (int vt = 0; vt < 4; vt++) {
                float vx = o[vt][half*2+0] * inv;
                float vy = o[vt][half*2+1] * inv;
                *(__half2*)(oh + base + vt * 8 + t4 * 2) =
                    __half2(__float2half(vx), __float2half(vy));
            }
        }
    }
}

// ---------------- weight converter (fp16 single) + combined bias -----------
__global__ void cvt_weights(const float* __restrict__ w0, const float* __restrict__ w1,
                            const float* __restrict__ w2, const float* __restrict__ w3,
                            const float* __restrict__ w4, const float* __restrict__ w5,
                            const float* __restrict__ w6, const float* __restrict__ w7,
                            const float* __restrict__ off_b, const float* __restrict__ aw_b,
                            __half* __restrict__ w16, float* __restrict__ cbias) {
    int i = blockIdx.x * blockDim.x + threadIdx.x;
    if (i < 384) cbias[i] = (i < 256) ? off_b[i] : aw_b[i - 256];
    if (i >= WTOT) return;
    const float* src; int local;
    if      (i < OFF_SAOUT) { src = w0; local = i; }
    else if (i < OFF_OFFW)  { src = w1; local = i - OFF_SAOUT; }
    else if (i < OFF_VALW)  { src = (i < 327680) ? w2 : w3; local = (i < 327680) ? i - OFF_OFFW : i - 327680; }
    else if (i < OFF_OUTPW) { src = w4; local = i - OFF_VALW; }
    else if (i < OFF_FFN1)  { src = w5; local = i - OFF_OUTPW; }
    else if (i < OFF_FFN2)  { src = w6; local = i - OFF_FFN1; }
    else                    { src = w7; local = i - OFF_FFN2; }
    w16[i] = __float2half(src[local]);
}

// ---------------- add + fp16 convert ---------------------------------------
__global__ void add_cvt_kernel(const float* __restrict__ a, const float* __restrict__ b,
                               __half* __restrict__ q16, __half* __restrict__ t16, int n4) {
    int i = blockIdx.x * blockDim.x + threadIdx.x;
    if (i >= n4) return;
    float4 x = ((const float4*)a)[i];
    float4 y = ((const float4*)b)[i];
    *(__half2*)(q16 + i*4)     = __half2(__float2half(x.x + y.x), __float2half(x.y + y.y));
    *(__half2*)(q16 + i*4 + 2) = __half2(__float2half(x.z + y.z), __float2half(x.w + y.w));
    *(__half2*)(t16 + i*4)     = __half2(__float2half(x.x), __float2half(x.y));
    *(__half2*)(t16 + i*4 + 2) = __half2(__float2half(x.z), __float2half(x.w));
}

// ---------------- fp32 -> fp16 converter ------------------------------------
__global__ void cvt_f16_kernel(const float* __restrict__ a, __half* __restrict__ o, int n4) {
    int i = blockIdx.x * blockDim.x + threadIdx.x;
    if (i >= n4) return;
    float4 x = ((const float4*)a)[i];
    *(__half2*)(o + i*4)     = __half2(__float2half(x.x), __float2half(x.y));
    *(__half2*)(o + i*4 + 2) = __half2(__float2half(x.z), __float2half(x.w));
}

// ---------------- LayerNorm(x+res) -> fp32 (+ optional fp16 of out+pos) ----
__global__ __launch_bounds__(256)
void ln_kernel(const float* __restrict__ x, const float* __restrict__ res,
               const float* __restrict__ g, const float* __restrict__ bta,
               float* __restrict__ out,
               const float* __restrict__ pos, __half* __restrict__ o16) {
    __shared__ float red[8];
    const int row = blockIdx.x, t = threadIdx.x;
    const size_t idx = (size_t)row * DM + t;
    float v = x[idx] + res[idx];

    float s = v;
    #pragma unroll
    for (int o = 16; o; o >>= 1) s += __shfl_xor_sync(0xffffffffu, s, o);
    if ((t & 31) == 0) red[t >> 5] = s;
    __syncthreads();
    float mean = 0.f;
    #pragma unroll
    for (int i = 0; i < 8; i++) mean += red[i];
    mean *= (1.f / DM);
    __syncthreads();

    float d = v - mean;
    float s2 = d * d;
    #pragma unroll
    for (int o = 16; o; o >>= 1) s2 += __shfl_xor_sync(0xffffffffu, s2, o);
    if ((t & 31) == 0) red[t >> 5] = s2;
    __syncthreads();
    float var = 0.f;
    #pragma unroll
    for (int i = 0; i < 8; i++) var += red[i];
    var *= (1.f / DM);

    float o = d * rsqrtf(var + 1e-5f) * g[t] + bta[t];
    out[idx] = o;
    if (o16) {
        float tq = pos ? o + pos[idx] : o;
        o16[idx] = __float2half(tq);
    }
}

// ---------------- attention-weight softmax ---------------------------------
__global__ void awsm_kernel(float* __restrict__ offaw) {
    int i = blockIdx.x * blockDim.x + threadIdx.x;
    if (i >= NQ * NH) return;
    float* p = offaw + (size_t)(i / NH) * 384 + 256 + (i % NH) * 16;
    float mx = -1e30f;
    #pragma unroll
    for (int j = 0; j < 16; j++) mx = fmaxf(mx, p[j]);
    float sm = 0.f, e[16];
    #pragma unroll
    for (int j = 0; j < 16; j++) { e[j] = __expf(p[j] - mx); sm += e[j]; }
    float inv = 1.f / sm;
    #pragma unroll
    for (int j = 0; j < 16; j++) p[j] = e[j] * inv;
}

// ---------------- MS-deformable sampling (half2, 2 ch/thread) --------------
__global__ __launch_bounds__(128)
void deform_kernel(const __half* __restrict__ value, const float* __restrict__ offaw,
                   const float* __restrict__ ref, __half* __restrict__ o16) {
    const int qidx = blockIdx.x;
    const int b = qidx / LQ;
    const int h = threadIdx.y;          // 0..7
    const int d2 = threadIdx.x;         // 0..15 -> channels 2*d2, 2*d2+1

    const int starts[4] = {0, 16384, 20480, 21504};
    const int Wi[4]     = {128, 64, 32, 16};

    const __half2* vb = (const __half2*)(value + (size_t)b * LEN_IN * DM + h * DH) + d2;
    const size_t oq = (size_t)qidx;
    const float* offp = offaw + oq * 384;
    float accx = 0.f, accy = 0.f;

    #pragma unroll
    for (int lvl = 0; lvl < NLV; lvl++) {
        const float W = (float)Wi[lvl];
        const int   Wl = Wi[lvl];
        const int   st = starts[lvl];
        const float rx = ref[(oq * NLV + lvl) * 2 + 0];
        const float ry = ref[(oq * NLV + lvl) * 2 + 1];
        #pragma unroll
        for (int p = 0; p < NPT; p++) {
            const int oidx = ((h * NLV + lvl) * NPT + p) * 2;
            const float ox = offp[oidx + 0];
            const float oy = offp[oidx + 1];
            const float a  = offp[256 + h * 16 + lvl * 4 + p];
            const float x = (rx + ox / W) * W - 0.5f;
            const float y = (ry + oy / W) * W - 0.5f;
            const float x0f = floorf(x), y0f = floorf(y);
            const float lx = x - x0f, ly = y - y0f;
            const int x0 = (int)x0f, y0 = (int)y0f;

            const float w00 = a * (1.f - ly) * (1.f - lx);
            const float w01 = a * (1.f - ly) * lx;
            const float w10 = a * ly * (1.f - lx);
            const float w11 = a * ly * lx;

            const bool xv0 = (x0 >= 0) & (x0 < Wl);
            const bool xv1 = (x0 + 1 >= 0) & (x0 + 1 < Wl);
            const bool yv0 = (y0 >= 0) & (y0 < Wl);
            const bool yv1 = (y0 + 1 >= 0) & (y0 + 1 < Wl);

            if (yv0 & xv0) { float2 v = __half22float2(vb[(size_t)(st + y0 * Wl + x0) * 128]); accx = fmaf(w00, v.x, accx); accy = fmaf(w00, v.y, accy); }
            if (yv0 & xv1) { float2 v = __half22float2(vb[(size_t)(st + y0 * Wl + x0 + 1) * 128]); accx = fmaf(w01, v.x, accx); accy = fmaf(w01, v.y, accy); }
            if (yv1 & xv0) { float2 v = __half22float2(vb[(size_t)(st + (y0 + 1) * Wl + x0) * 128]); accx = fmaf(w10, v.x, accx); accy = fmaf(w10, v.y, accy); }
            if (yv1 & xv1) { float2 v = __half22float2(vb[(size_t)(st + (y0 + 1) * Wl + x0 + 1) * 128]); accx = fmaf(w11, v.x, accx); accy = fmaf(w11, v.y, accy); }
        }
    }
    *(__half2*)(o16 + oq * DM + h * DH + d2 * 2) =
        __half2(__float2half(accx), __float2half(accy));
}

// ---------------- host-side orchestration ----------------------------------
static inline void gemm_f32(const __half* A, const __half* B, const float* bias,
                            float* Cf, int M, int N, int K) {
    dim3 grid(N / 128, (M + 127) / 128);
    tc_gemm<false, 0><<<grid, 256, H1_SMEM>>>(A, B, bias, Cf, 0, M, N, K);
}
static inline void gemm_f16(const __half* A, const __half* B, const float* bias,
                            __half* C16, int M, int N, int K, bool relu) {
    dim3 grid(N / 128, (M + 127) / 128);
    if (relu) tc_gemm<true, 1><<<grid, 256, H1_SMEM>>>(A, B, bias, 0, C16, M, N, K);
    else      tc_gemm<false, 1><<<grid, 256, H1_SMEM>>>(A, B, bias, 0, C16, M, N, K);
}

extern "C" void kernel_launch(void* const* d_in, const int* in_sizes, int n_in,
                              void* d_out, int out_size) {
    (void)in_sizes; (void)n_in; (void)out_size;
    const float* tgt       = (const float*)d_in[0];
    const float* query_pos = (const float*)d_in[1];
    const float* refpts    = (const float*)d_in[2];
    const float* src       = (const float*)d_in[3];
    const float* sa_in_b   = (const float*)d_in[7];
    const float* sa_out_b  = (const float*)d_in[9];
    const float* norm2_g   = (const float*)d_in[10];
    const float* norm2_b   = (const float*)d_in[11];
    const float* off_b     = (const float*)d_in[13];
    const float* aw_b      = (const float*)d_in[15];
    const float* val_b     = (const float*)d_in[17];
    const float* outp_b    = (const float*)d_in[19];
    const float* norm1_g   = (const float*)d_in[20];
    const float* norm1_b   = (const float*)d_in[21];
    const float* ffn_b1    = (const float*)d_in[23];
    const float* ffn_b2    = (const float*)d_in[25];
    const float* norm3_g   = (const float*)d_in[26];
    const float* norm3_b   = (const float*)d_in[27];
    float* out = (float*)d_out;

    cudaFuncSetAttribute(tc_gemm<false,0>, cudaFuncAttributeMaxDynamicSharedMemorySize, H1_SMEM);
    cudaFuncSetAttribute(tc_gemm<false,1>, cudaFuncAttributeMaxDynamicSharedMemorySize, H1_SMEM);
    cudaFuncSetAttribute(tc_gemm<true,1>,  cudaFuncAttributeMaxDynamicSharedMemorySize, H1_SMEM);
    cudaFuncSetAttribute(attn_mma, cudaFuncAttributeMaxDynamicSharedMemorySize, ATT_SMEM);

    void* p;
    #define SYMF(name) cudaGetSymbolAddress(&p, name); float* name##_p = (float*)p;
    #define SYMH(name) cudaGetSymbolAddress(&p, name); __half* name##_p = (__half*)p;
    SYMF(g_proj) SYMF(g_tgt2) SYMF(g_tgt3) SYMF(g_offaw) SYMF(g_cbias)
    SYMH(g_qk16) SYMH(g_tgt16) SYMH(g_qk2) SYMH(g_v2)
    SYMH(g_att16) SYMH(g_query16) SYMH(g_tgt3_16) SYMH(g_ca16) SYMH(g_ffn16)
    SYMH(g_src16) SYMH(g_value16) SYMH(g_w16)
    #undef SYMF
    #undef SYMH

    // 0) weight + input conversions
    cvt_weights<<<(WTOT + 255)/256, 256>>>(
        (const float*)d_in[6], (const float*)d_in[8], (const float*)d_in[12],
        (const float*)d_in[14], (const float*)d_in[16], (const float*)d_in[18],
        (const float*)d_in[22], (const float*)d_in[24],
        off_b, aw_b, g_w16_p, g_cbias_p);
    const int n4 = NQ * DM / 4;
    add_cvt_kernel<<<(n4 + 255)/256, 256>>>(tgt, query_pos, g_qk16_p, g_tgt16_p, n4);
    const int ns4 = (int)((size_t)NSRC * DM / 4);
    cvt_f16_kernel<<<(ns4 + 255)/256, 256>>>(src, g_src16_p, ns4);

    // 1) self-attn
    gemm_f16(g_qk16_p, g_w16_p + OFF_SAIN, sa_in_b, g_qk2_p, NQ, 512, DM, false);
    gemm_f16(g_tgt16_p, g_w16_p + OFF_SAIN + 131072, sa_in_b + 2*DM, g_v2_p, NQ, DM, DM, false);
    attn_mma<<<dim3(8, NB * NH), 256, ATT_SMEM>>>(g_qk2_p, g_v2_p, g_att16_p);
    gemm_f32(g_att16_p, g_w16_p + OFF_SAOUT, sa_out_b, g_proj_p, NQ, DM, DM);
    ln_kernel<<<NQ, DM>>>(tgt, g_proj_p, norm2_g, norm2_b, g_tgt2_p, query_pos, g_query16_p);

    // 2) cross-attn
    gemm_f16(g_src16_p, g_w16_p + OFF_VALW, val_b, g_value16_p, NSRC, DM, DM, false);
    gemm_f32(g_query16_p, g_w16_p + OFF_OFFW, g_cbias_p, g_offaw_p, NQ, 384, DM);
    awsm_kernel<<<(NQ * NH + 255)/256, 256>>>(g_offaw_p);
    deform_kernel<<<NQ, dim3(16, 8)>>>(g_value16_p, g_offaw_p, refpts, g_ca16_p);
    gemm_f32(g_ca16_p, g_w16_p + OFF_OUTPW, outp_b, g_proj_p, NQ, DM, DM);
    ln_kernel<<<NQ, DM>>>(g_tgt2_p, g_proj_p, norm1_g, norm1_b, g_tgt3_p, nullptr, g_tgt3_16_p);

    // 3) FFN
    gemm_f16(g_tgt3_16_p, g_w16_p + OFF_FFN1, ffn_b1, g_ffn16_p, NQ, DFFN, DM, true);
    gemm_f32(g_ffn16_p, g_w16_p + OFF_FFN2, ffn_b2, g_proj_p, NQ, DM, DFFN);
    ln_kernel<<<NQ, DM>>>(g_tgt3_p, g_proj_p, norm3_g, norm3_b, out, nullptr, nullptr);
}